// round 4
// baseline (speedup 1.0000x reference)
#include <cuda_runtime.h>
#include <cuda_bf16.h>

#define NN 50000
#define EE 1000000
#define BB 512
#define HH 128
#define MID 64
#define IN1 54
#define IN2 18

typedef unsigned long long u64;

#define FMA2(d, a, b, c) asm("fma.rn.f32x2 %0, %1, %2, %3;" : "=l"(d) : "l"(a), "l"(b), "l"(c))

__device__ __forceinline__ u64 pack2(float lo, float hi) {
    u64 r; asm("mov.b64 %0, {%1, %2};" : "=l"(r) : "f"(lo), "f"(hi)); return r;
}
__device__ __forceinline__ void unpack2(u64 v, float& lo, float& hi) {
    asm("mov.b64 {%0, %1}, %2;" : "=f"(lo), "=f"(hi) : "l"(v));
}
__device__ __forceinline__ void red_add_v4(float* addr, float4 v) {
    asm volatile("red.global.add.v4.f32 [%0], {%1, %2, %3, %4};"
                 :: "l"(addr), "f"(v.x), "f"(v.y), "f"(v.z), "f"(v.w) : "memory");
}

// ---------------- scratch (no allocation allowed) ----------------
__device__ float g_xact[NN * HH];
__device__ float g_agg1[NN * HH];
__device__ float g_agg2[NN * HH];
__device__ float g_A[NN * HH];
__device__ float g_B[NN * HH];
__device__ float g_C[NN * HH];
__device__ float g_mean[BB * HH];
__device__ float g_var[BB * HH];
__device__ float g_cnt[BB];

// ---------------- zero scratch ----------------
__global__ void zero_kernel() {
    int idx = blockIdx.x * blockDim.x + threadIdx.x;
    if (idx < NN * HH) { g_agg1[idx] = 0.f; g_agg2[idx] = 0.f; }
    if (idx < BB * HH) { g_mean[idx] = 0.f; g_var[idx] = 0.f; }
    if (idx < BB) g_cnt[idx] = 0.f;
}

// ---------------- node GEMM with packed f32x2 ----------------
constexpr int RB = 64;
constexpr int WPAD = 130;
constexpr int GEMM_SMEM = (128 * WPAD + RB * 128) * 4;

template <bool DUAL, bool SWISH, bool RESID>
__global__ __launch_bounds__(256) void gemm_node(
    const float* __restrict__ A1, const float* __restrict__ W1, int ldw1,
    const float* __restrict__ A2, const float* __restrict__ W2, int ldw2,
    const float* __restrict__ bias, const float* __restrict__ resid,
    float* __restrict__ out, int nrows)
{
    extern __shared__ float sm[];
    float* Ws = sm;                 // [128][WPAD], Ws[k][c] = W[c][k]
    float* Xs = sm + 128 * WPAD;    // [RB][128]

    const int tid  = threadIdx.x;
    const int lane = tid & 31;
    const int warp = tid >> 5;
    const int r0   = blockIdx.x * RB;

    u64 acc[8][2];
#pragma unroll
    for (int i = 0; i < 8; i++) { acc[i][0] = 0ull; acc[i][1] = 0ull; }

    const int npass = DUAL ? 2 : 1;
    for (int pass = 0; pass < npass; pass++) {
        const float* A = (pass == 0) ? A1 : A2;
        const float* W = (pass == 0) ? W1 : W2;
        const int ldw  = (pass == 0) ? ldw1 : ldw2;
        if (pass == 1) __syncthreads();
        for (int i = tid; i < RB * 128; i += 256) {
            int r = r0 + (i >> 7);
            Xs[i] = (r < nrows) ? A[(size_t)r * 128 + (i & 127)] : 0.f;
        }
        for (int i = tid; i < 128 * 128; i += 256) {
            int c = i >> 7, k = i & 127;
            Ws[k * WPAD + c] = W[(size_t)c * ldw + k];
        }
        __syncthreads();
#pragma unroll 2
        for (int k = 0; k < 128; k++) {
            float2 w0 = *(const float2*)(Ws + k * WPAD + 2 * lane);
            float2 w1 = *(const float2*)(Ws + k * WPAD + 64 + 2 * lane);
            u64 w0p = pack2(w0.x, w0.y);
            u64 w1p = pack2(w1.x, w1.y);
            const float* xr = Xs + (warp << 3) * 128 + k;
#pragma unroll
            for (int i = 0; i < 8; i++) {
                float xv = xr[i * 128];
                u64 x2 = pack2(xv, xv);
                FMA2(acc[i][0], x2, w0p, acc[i][0]);
                FMA2(acc[i][1], x2, w1p, acc[i][1]);
            }
        }
    }
    float2 b0 = *(const float2*)(bias + 2 * lane);
    float2 b1 = *(const float2*)(bias + 64 + 2 * lane);
#pragma unroll
    for (int i = 0; i < 8; i++) {
        int r = r0 + (warp << 3) + i;
        if (r < nrows) {
            float v0, v1, v2, v3;
            unpack2(acc[i][0], v0, v1);
            unpack2(acc[i][1], v2, v3);
            v0 += b0.x; v1 += b0.y; v2 += b1.x; v3 += b1.y;
            if (SWISH) {
                v0 = v0 / (1.f + __expf(-v0));
                v1 = v1 / (1.f + __expf(-v1));
                v2 = v2 / (1.f + __expf(-v2));
                v3 = v3 / (1.f + __expf(-v3));
            }
            float* orow = out + (size_t)r * 128;
            if (RESID) {
                const float* rr = resid + (size_t)r * 128;
                float2 r0v = *(const float2*)(rr + 2 * lane);
                float2 r1v = *(const float2*)(rr + 64 + 2 * lane);
                v0 += r0v.x; v1 += r0v.y; v2 += r1v.x; v3 += r1v.y;
            }
            *(float2*)(orow + 2 * lane)      = make_float2(v0, v1);
            *(float2*)(orow + 64 + 2 * lane) = make_float2(v2, v3);
        }
    }
}

// ---------------- fused edge kernel (f32x2 + v4 reds) ----------------
constexpr int EB = 16;

__global__ __launch_bounds__(256, 2) void edge_kernel(
    const float* __restrict__ feat1, const float* __restrict__ feat2,
    const int* __restrict__ ei,
    const float* __restrict__ W1a, const float* __restrict__ W2a,
    const float* __restrict__ W1b, const float* __restrict__ W2b,
    const float* __restrict__ xact,
    float* __restrict__ agg1, float* __restrict__ agg2, int nE)
{
    __shared__ __align__(16) float f1s[EB * IN1];
    __shared__ __align__(16) float f2s[EB * IN2];
    __shared__ __align__(16) float m1s[EB * MID];
    __shared__ __align__(16) float m2s[EB * MID];
    __shared__ __align__(16) float xs[EB * HH];
    __shared__ __align__(16) float fs[EB * 256];   // staged outputs: [e][path*128+h]
    __shared__ int sidx[2 * EB];
    __shared__ __align__(16) float Ws1a[MID * IN1];  // [k][j]
    __shared__ __align__(16) float Ws1b[MID * IN2];

    const int tid = threadIdx.x;

    for (int i = tid; i < MID * IN1; i += 256) Ws1a[i] = W1a[i];
    for (int i = tid; i < MID * IN2; i += 256) Ws1b[i] = W1b[i];

    // second-layer weight row packed: thread h holds W2[h][0..63] as 32 u64 pairs
    u64 w2p[MID / 2];
    {
        const u64* w2g = (const u64*)(((tid < 128) ? W2a : W2b) + (size_t)(tid & 127) * MID);
#pragma unroll
        for (int kk = 0; kk < MID / 2; kk++) w2p[kk] = w2g[kk];
    }
    __syncthreads();

    const int ntiles = nE / EB;
    for (int t = blockIdx.x; t < ntiles; t += gridDim.x) {
        const int e0 = t * EB;
        for (int i = tid; i < EB * IN1; i += 256) f1s[i] = feat1[(size_t)e0 * IN1 + i];
        for (int i = tid; i < EB * IN2; i += 256) f2s[i] = feat2[(size_t)e0 * IN2 + i];
        if (tid < EB) { sidx[tid] = ei[e0 + tid]; sidx[EB + tid] = ei[nE + e0 + tid]; }
        __syncthreads();

        for (int i = tid; i < EB * HH; i += 256) {
            int e = i >> 7;
            xs[i] = xact[(size_t)sidx[e] * HH + (i & 127)];
        }

        // phase A: m = feat @ W1^T
        {
            const int k = tid & 63, g = tid >> 6;
            {
                const u64* wrow = (const u64*)(Ws1a + k * IN1);
                const u64* fr0 = (const u64*)(f1s + (g + 0)  * IN1);
                const u64* fr1 = (const u64*)(f1s + (g + 4)  * IN1);
                const u64* fr2 = (const u64*)(f1s + (g + 8)  * IN1);
                const u64* fr3 = (const u64*)(f1s + (g + 12) * IN1);
                u64 a0 = 0ull, a1 = 0ull, a2 = 0ull, a3 = 0ull;
#pragma unroll
                for (int jp = 0; jp < IN1 / 2; jp++) {
                    u64 w = wrow[jp];
                    FMA2(a0, fr0[jp], w, a0);
                    FMA2(a1, fr1[jp], w, a1);
                    FMA2(a2, fr2[jp], w, a2);
                    FMA2(a3, fr3[jp], w, a3);
                }
                float lo, hi;
                unpack2(a0, lo, hi); m1s[(g + 0)  * MID + k] = lo + hi;
                unpack2(a1, lo, hi); m1s[(g + 4)  * MID + k] = lo + hi;
                unpack2(a2, lo, hi); m1s[(g + 8)  * MID + k] = lo + hi;
                unpack2(a3, lo, hi); m1s[(g + 12) * MID + k] = lo + hi;
            }
            {
                const u64* wrow = (const u64*)(Ws1b + k * IN2);
                const u64* fr0 = (const u64*)(f2s + (g + 0)  * IN2);
                const u64* fr1 = (const u64*)(f2s + (g + 4)  * IN2);
                const u64* fr2 = (const u64*)(f2s + (g + 8)  * IN2);
                const u64* fr3 = (const u64*)(f2s + (g + 12) * IN2);
                u64 a0 = 0ull, a1 = 0ull, a2 = 0ull, a3 = 0ull;
#pragma unroll
                for (int jp = 0; jp < IN2 / 2; jp++) {
                    u64 w = wrow[jp];
                    FMA2(a0, fr0[jp], w, a0);
                    FMA2(a1, fr1[jp], w, a1);
                    FMA2(a2, fr2[jp], w, a2);
                    FMA2(a3, fr3[jp], w, a3);
                }
                float lo, hi;
                unpack2(a0, lo, hi); m2s[(g + 0)  * MID + k] = lo + hi;
                unpack2(a1, lo, hi); m2s[(g + 4)  * MID + k] = lo + hi;
                unpack2(a2, lo, hi); m2s[(g + 8)  * MID + k] = lo + hi;
                unpack2(a3, lo, hi); m2s[(g + 12) * MID + k] = lo + hi;
            }
        }
        __syncthreads();

        // phase B: f_h = m . w2[h]; stage v = f_h * x[src][h] into fs
        {
            const int h = tid & 127;
            const int pofs = (tid < 128) ? 0 : 128;
            const float* msrcf = (tid < 128) ? m1s : m2s;
#pragma unroll 2
            for (int e = 0; e < EB; e++) {
                const ulonglong2* mp = (const ulonglong2*)(msrcf + e * MID);
                u64 acc0 = 0ull, acc1 = 0ull;
#pragma unroll
                for (int kk = 0; kk < MID / 4; kk++) {
                    ulonglong2 mv = mp[kk];
                    FMA2(acc0, mv.x, w2p[2 * kk + 0], acc0);
                    FMA2(acc1, mv.y, w2p[2 * kk + 1], acc1);
                }
                float l0, h0, l1, h1;
                unpack2(acc0, l0, h0);
                unpack2(acc1, l1, h1);
                fs[e * 256 + pofs + h] = ((l0 + l1) + (h0 + h1)) * xs[e * HH + h];
            }
        }
        __syncthreads();

        // phase C: vectorized scatter — one red.v4 per 4 channels
#pragma unroll
        for (int i = 0; i < 4; i++) {
            int g = tid + 256 * i;          // 0..1023
            int e = g >> 6;
            int rem = g & 63;
            int path = rem >> 5;
            int c4 = (rem & 31) << 2;
            float4 v = *(const float4*)(fs + e * 256 + path * 128 + c4);
            float* agg = path ? agg2 : agg1;
            red_add_v4(agg + (size_t)sidx[EB + e] * HH + c4, v);
        }
        __syncthreads();
    }
}

// ---------------- GraphNorm (v4 reds) ----------------
__global__ void norm_sum(const float* __restrict__ hin, const int* __restrict__ batch) {
    int idx = blockIdx.x * blockDim.x + threadIdx.x;   // over NN*32
    if (idx >= NN * 32) return;
    int n = idx >> 5, c4 = (idx & 31) << 2;
    int b = batch[n];
    float4 v = *(const float4*)(hin + (size_t)n * HH + c4);
    red_add_v4(&g_mean[b * HH + c4], v);
    if (c4 == 0) atomicAdd(&g_cnt[b], 1.f);
}

__global__ void norm_center(const float* __restrict__ hin, const int* __restrict__ batch,
                            const float* __restrict__ ms, float* __restrict__ hc_out) {
    int idx = blockIdx.x * blockDim.x + threadIdx.x;   // over NN*32
    if (idx >= NN * 32) return;
    int n = idx >> 5, c4 = (idx & 31) << 2;
    int b = batch[n];
    float rcnt = 1.f / fmaxf(g_cnt[b], 1.f);
    float4 hv = *(const float4*)(hin + (size_t)n * HH + c4);
    float4 mv = *(const float4*)(&g_mean[b * HH + c4]);
    float4 msv = *(const float4*)(ms + c4);
    float4 hc;
    hc.x = hv.x - mv.x * rcnt * msv.x;
    hc.y = hv.y - mv.y * rcnt * msv.y;
    hc.z = hv.z - mv.z * rcnt * msv.z;
    hc.w = hv.w - mv.w * rcnt * msv.w;
    *(float4*)(hc_out + (size_t)n * HH + c4) = hc;
    float4 sq = make_float4(hc.x * hc.x, hc.y * hc.y, hc.z * hc.z, hc.w * hc.w);
    red_add_v4(&g_var[b * HH + c4], sq);
}

__global__ void norm_apply(const float* __restrict__ hc, const int* __restrict__ batch,
                           const float* __restrict__ w, const float* __restrict__ b_,
                           float* __restrict__ out) {
    int idx = blockIdx.x * blockDim.x + threadIdx.x;   // over NN*32
    if (idx >= NN * 32) return;
    int n = idx >> 5, c4 = (idx & 31) << 2;
    int b = batch[n];
    float rcnt = 1.f / fmaxf(g_cnt[b], 1.f);
    float4 hv = *(const float4*)(hc + (size_t)n * HH + c4);
    float4 vv = *(const float4*)(&g_var[b * HH + c4]);
    float4 wv = *(const float4*)(w + c4);
    float4 bv = *(const float4*)(b_ + c4);
    float4 o;
    o.x = wv.x * hv.x * rsqrtf(vv.x * rcnt + 1e-5f) + bv.x;
    o.y = wv.y * hv.y * rsqrtf(vv.y * rcnt + 1e-5f) + bv.y;
    o.z = wv.z * hv.z * rsqrtf(vv.z * rcnt + 1e-5f) + bv.z;
    o.w = wv.w * hv.w * rsqrtf(vv.w * rcnt + 1e-5f) + bv.w;
    *(float4*)(out + (size_t)n * HH + c4) = o;
}

// ---------------- launch ----------------
extern "C" void kernel_launch(void* const* d_in, const int* in_sizes, int n_in,
                              void* d_out, int out_size)
{
    const float* x        = (const float*)d_in[0];
    const float* feature1 = (const float*)d_in[1];
    const float* feature2 = (const float*)d_in[2];
    const int*   ei       = (const int*)d_in[3];
    const int*   batch    = (const int*)d_in[4];
    const float* lin_W    = (const float*)d_in[5];
    const float* lin_b    = (const float*)d_in[6];
    const float* f1_W1    = (const float*)d_in[7];
    const float* f1_W2    = (const float*)d_in[8];
    const float* f2_W1    = (const float*)d_in[9];
    const float* f2_W2    = (const float*)d_in[10];
    const float* c1_rel_W = (const float*)d_in[11];
    const float* c1_rel_b = (const float*)d_in[12];
    const float* c1_rt_W  = (const float*)d_in[13];
    const float* c2_rel_W = (const float*)d_in[14];
    const float* c2_rel_b = (const float*)d_in[15];
    const float* c2_rt_W  = (const float*)d_in[16];
    const float* lin1_W   = (const float*)d_in[17];
    const float* lin1_b   = (const float*)d_in[18];
    const float* lin2_W   = (const float*)d_in[19];
    const float* lin2_b   = (const float*)d_in[20];
    const float* cat_W    = (const float*)d_in[21];
    const float* cat_b    = (const float*)d_in[22];
    const float* norm_w   = (const float*)d_in[23];
    const float* norm_b   = (const float*)d_in[24];
    const float* norm_ms  = (const float*)d_in[25];
    const float* lins_W   = (const float*)d_in[26];
    const float* lins_b   = (const float*)d_in[27];
    const float* final_W  = (const float*)d_in[28];
    const float* final_b  = (const float*)d_in[29];

    const int nN = in_sizes[0] / HH;
    const int nE = in_sizes[3] / 2;

    float *pxact, *pagg1, *pagg2, *pA, *pB, *pC;
    cudaGetSymbolAddress((void**)&pxact, g_xact);
    cudaGetSymbolAddress((void**)&pagg1, g_agg1);
    cudaGetSymbolAddress((void**)&pagg2, g_agg2);
    cudaGetSymbolAddress((void**)&pA, g_A);
    cudaGetSymbolAddress((void**)&pB, g_B);
    cudaGetSymbolAddress((void**)&pC, g_C);

    cudaFuncSetAttribute(gemm_node<false, true,  false>, cudaFuncAttributeMaxDynamicSharedMemorySize, GEMM_SMEM);
    cudaFuncSetAttribute(gemm_node<true,  false, false>, cudaFuncAttributeMaxDynamicSharedMemorySize, GEMM_SMEM);
    cudaFuncSetAttribute(gemm_node<true,  false, true >, cudaFuncAttributeMaxDynamicSharedMemorySize, GEMM_SMEM);
    cudaFuncSetAttribute(gemm_node<false, true,  true >, cudaFuncAttributeMaxDynamicSharedMemorySize, GEMM_SMEM);
    cudaFuncSetAttribute(gemm_node<false, false, false>, cudaFuncAttributeMaxDynamicSharedMemorySize, GEMM_SMEM);

    const int gblocks = (nN + RB - 1) / RB;

    zero_kernel<<<(NN * HH + 255) / 256, 256>>>();

    gemm_node<false, true, false><<<gblocks, 256, GEMM_SMEM>>>(
        x, lin_W, HH, nullptr, nullptr, 0, lin_b, nullptr, pxact, nN);

    edge_kernel<<<296, 256>>>(feature1, feature2, ei,
                              f1_W1, f1_W2, f2_W1, f2_W2,
                              pxact, pagg1, pagg2, nE);

    gemm_node<true, false, false><<<gblocks, 256, GEMM_SMEM>>>(
        pagg1, c1_rel_W, HH, pxact, c1_rt_W, HH, c1_rel_b, nullptr, pA, nN);
    gemm_node<false, true, false><<<gblocks, 256, GEMM_SMEM>>>(
        pA, lin1_W, HH, nullptr, nullptr, 0, lin1_b, nullptr, pB, nN);
    gemm_node<true, false, false><<<gblocks, 256, GEMM_SMEM>>>(
        pagg2, c2_rel_W, HH, pxact, c2_rt_W, HH, c2_rel_b, nullptr, pA, nN);
    gemm_node<false, true, false><<<gblocks, 256, GEMM_SMEM>>>(
        pA, lin2_W, HH, nullptr, nullptr, 0, lin2_b, nullptr, pC, nN);
    gemm_node<true, false, true><<<gblocks, 256, GEMM_SMEM>>>(
        pB, cat_W, 2 * HH, pC, cat_W + HH, 2 * HH, cat_b, pxact, pA, nN);
    gemm_node<false, true, true><<<gblocks, 256, GEMM_SMEM>>>(
        pA, lins_W + 0 * HH * HH, HH, nullptr, nullptr, 0, lins_b + 0 * HH, pA, pB, nN);
    gemm_node<false, true, true><<<gblocks, 256, GEMM_SMEM>>>(
        pB, lins_W + 1 * HH * HH, HH, nullptr, nullptr, 0, lins_b + 1 * HH, pB, pA, nN);
    gemm_node<false, true, true><<<gblocks, 256, GEMM_SMEM>>>(
        pA, lins_W + 2 * HH * HH, HH, nullptr, nullptr, 0, lins_b + 2 * HH, pA, pB, nN);

    const int n32b = (NN * 32 + 255) / 256;
    norm_sum<<<n32b, 256>>>(pB, batch);
    norm_center<<<n32b, 256>>>(pB, batch, norm_ms, pC);
    norm_apply<<<n32b, 256>>>(pC, batch, norm_w, norm_b, pA);

    gemm_node<false, false, false><<<gblocks, 256, GEMM_SMEM>>>(
        pA, final_W, HH, nullptr, nullptr, 0, final_b, nullptr, (float*)d_out, nN);
}

// round 5
// speedup vs baseline: 1.1924x; 1.1924x over previous
#include <cuda_runtime.h>
#include <cuda_bf16.h>

#define NN 50000
#define EE 1000000
#define BB 512
#define HH 128
#define MID 64
#define IN1 54
#define IN2 18

typedef unsigned long long u64;
typedef unsigned int u32;

#define FMA2(d, a, b, c) asm("fma.rn.f32x2 %0, %1, %2, %3;" : "=l"(d) : "l"(a), "l"(b), "l"(c))

__device__ __forceinline__ u64 pack2(float lo, float hi) {
    u64 r; asm("mov.b64 %0, {%1, %2};" : "=l"(r) : "f"(lo), "f"(hi)); return r;
}
__device__ __forceinline__ void unpack2(u64 v, float& lo, float& hi) {
    asm("mov.b64 {%0, %1}, %2;" : "=f"(lo), "=f"(hi) : "l"(v));
}
__device__ __forceinline__ void red_add_v4(float* addr, float4 v) {
    asm volatile("red.global.add.v4.f32 [%0], {%1, %2, %3, %4};"
                 :: "l"(addr), "f"(v.x), "f"(v.y), "f"(v.z), "f"(v.w) : "memory");
}
__device__ __forceinline__ void red_add_v2(float* addr, float a, float b) {
    asm volatile("red.global.add.v2.f32 [%0], {%1, %2};"
                 :: "l"(addr), "f"(a), "f"(b) : "memory");
}
// mma.sync m16n8k16 bf16 -> f32, accumulate in place
#define MMA16816(c0, c1, c2, c3, a0, a1, a2, a3, b0, b1) \
    asm volatile("mma.sync.aligned.m16n8k16.row.col.f32.bf16.bf16.f32 " \
                 "{%0,%1,%2,%3}, {%4,%5,%6,%7}, {%8,%9}, {%0,%1,%2,%3};" \
                 : "+f"(c0), "+f"(c1), "+f"(c2), "+f"(c3) \
                 : "r"(a0), "r"(a1), "r"(a2), "r"(a3), "r"(b0), "r"(b1))

__device__ __forceinline__ u32 pack_bf2(float e0, float e1) {
    __nv_bfloat162 h = __floats2bfloat162_rn(e0, e1);   // e0 -> low half
    return *(u32*)&h;
}

// ---------------- scratch (no allocation allowed) ----------------
__device__ float g_xact[NN * HH];
__device__ float g_agg1[NN * HH];
__device__ float g_agg2[NN * HH];
__device__ float g_A[NN * HH];
__device__ float g_B[NN * HH];
__device__ float g_C[NN * HH];
__device__ float g_mean[BB * HH];
__device__ float g_var[BB * HH];
__device__ float g_cnt[BB];

// ---------------- zero scratch ----------------
__global__ void zero_kernel() {
    int idx = blockIdx.x * blockDim.x + threadIdx.x;
    if (idx < NN * HH) { g_agg1[idx] = 0.f; g_agg2[idx] = 0.f; }
    if (idx < BB * HH) { g_mean[idx] = 0.f; g_var[idx] = 0.f; }
    if (idx < BB) g_cnt[idx] = 0.f;
}

// ---------------- node GEMM with packed f32x2 (unchanged from R3) ----------------
constexpr int RB = 64;
constexpr int WPAD = 130;
constexpr int GEMM_SMEM = (128 * WPAD + RB * 128) * 4;

template <bool DUAL, bool SWISH, bool RESID>
__global__ __launch_bounds__(256) void gemm_node(
    const float* __restrict__ A1, const float* __restrict__ W1, int ldw1,
    const float* __restrict__ A2, const float* __restrict__ W2, int ldw2,
    const float* __restrict__ bias, const float* __restrict__ resid,
    float* __restrict__ out, int nrows)
{
    extern __shared__ float sm[];
    float* Ws = sm;
    float* Xs = sm + 128 * WPAD;

    const int tid  = threadIdx.x;
    const int lane = tid & 31;
    const int warp = tid >> 5;
    const int r0   = blockIdx.x * RB;

    u64 acc[8][2];
#pragma unroll
    for (int i = 0; i < 8; i++) { acc[i][0] = 0ull; acc[i][1] = 0ull; }

    const int npass = DUAL ? 2 : 1;
    for (int pass = 0; pass < npass; pass++) {
        const float* A = (pass == 0) ? A1 : A2;
        const float* W = (pass == 0) ? W1 : W2;
        const int ldw  = (pass == 0) ? ldw1 : ldw2;
        if (pass == 1) __syncthreads();
        for (int i = tid; i < RB * 128; i += 256) {
            int r = r0 + (i >> 7);
            Xs[i] = (r < nrows) ? A[(size_t)r * 128 + (i & 127)] : 0.f;
        }
        for (int i = tid; i < 128 * 128; i += 256) {
            int c = i >> 7, k = i & 127;
            Ws[k * WPAD + c] = W[(size_t)c * ldw + k];
        }
        __syncthreads();
#pragma unroll 2
        for (int k = 0; k < 128; k++) {
            float2 w0 = *(const float2*)(Ws + k * WPAD + 2 * lane);
            float2 w1 = *(const float2*)(Ws + k * WPAD + 64 + 2 * lane);
            u64 w0p = pack2(w0.x, w0.y);
            u64 w1p = pack2(w1.x, w1.y);
            const float* xr = Xs + (warp << 3) * 128 + k;
#pragma unroll
            for (int i = 0; i < 8; i++) {
                float xv = xr[i * 128];
                u64 x2 = pack2(xv, xv);
                FMA2(acc[i][0], x2, w0p, acc[i][0]);
                FMA2(acc[i][1], x2, w1p, acc[i][1]);
            }
        }
    }
    float2 b0 = *(const float2*)(bias + 2 * lane);
    float2 b1 = *(const float2*)(bias + 64 + 2 * lane);
#pragma unroll
    for (int i = 0; i < 8; i++) {
        int r = r0 + (warp << 3) + i;
        if (r < nrows) {
            float v0, v1, v2, v3;
            unpack2(acc[i][0], v0, v1);
            unpack2(acc[i][1], v2, v3);
            v0 += b0.x; v1 += b0.y; v2 += b1.x; v3 += b1.y;
            if (SWISH) {
                v0 = v0 / (1.f + __expf(-v0));
                v1 = v1 / (1.f + __expf(-v1));
                v2 = v2 / (1.f + __expf(-v2));
                v3 = v3 / (1.f + __expf(-v3));
            }
            float* orow = out + (size_t)r * 128;
            if (RESID) {
                const float* rr = resid + (size_t)r * 128;
                float2 r0v = *(const float2*)(rr + 2 * lane);
                float2 r1v = *(const float2*)(rr + 64 + 2 * lane);
                v0 += r0v.x; v1 += r0v.y; v2 += r1v.x; v3 += r1v.y;
            }
            *(float2*)(orow + 2 * lane)      = make_float2(v0, v1);
            *(float2*)(orow + 64 + 2 * lane) = make_float2(v2, v3);
        }
    }
}

// ---------------- fused edge kernel: fp32 phase A + split-bf16 HMMA phase B ----------------
constexpr int EB = 16;
constexpr int MP = 72;    // bf16 pitch for m tiles (conflict-free ldmatrix-less A-frag loads)
constexpr int XP = 132;   // fp32 pitch for xs

__global__ __launch_bounds__(256) void edge_kernel(
    const float* __restrict__ feat1, const float* __restrict__ feat2,
    const int* __restrict__ ei,
    const float* __restrict__ W1a, const float* __restrict__ W2a,
    const float* __restrict__ W1b, const float* __restrict__ W2b,
    const float* __restrict__ xact,
    float* __restrict__ agg1, float* __restrict__ agg2, int nE)
{
    __shared__ __align__(16) float f1s[EB * IN1];
    __shared__ __align__(16) float f2s[EB * IN2];
    __shared__ __align__(16) __nv_bfloat16 mh1s[EB * MP];
    __shared__ __align__(16) __nv_bfloat16 ml1s[EB * MP];
    __shared__ __align__(16) __nv_bfloat16 mh2s[EB * MP];
    __shared__ __align__(16) __nv_bfloat16 ml2s[EB * MP];
    __shared__ __align__(16) float xs[EB * XP];
    __shared__ int sidx[2 * EB];
    __shared__ __align__(16) float Ws1a[MID * IN1];  // [k][j]
    __shared__ __align__(16) float Ws1b[MID * IN2];

    const int tid  = threadIdx.x;
    const int warp = tid >> 5;
    const int lane = tid & 31;
    const int fg   = lane >> 2;   // fragment group 0..7
    const int ft   = lane & 3;    // fragment thread 0..3

    for (int i = tid; i < MID * IN1; i += 256) Ws1a[i] = W1a[i];
    for (int i = tid; i < MID * IN2; i += 256) Ws1b[i] = W1b[i];

    // ---- preload W2 B-fragments (hi/lo split) into registers ----
    // warp 0-3: path1 channels 32w..32w+31; warp 4-7: path2.
    u32 bhi[4][4][2], blo[4][4][2];
    {
        const float* W2 = (warp < 4) ? W2a : W2b;
        const int nbase = (warp & 3) * 32;
#pragma unroll
        for (int nt = 0; nt < 4; nt++) {
            const float* wrow = W2 + (size_t)(nbase + nt * 8 + fg) * MID;
#pragma unroll
            for (int kt = 0; kt < 4; kt++) {
#pragma unroll
                for (int half = 0; half < 2; half++) {
                    int k0 = kt * 16 + half * 8 + 2 * ft;
                    float w0 = wrow[k0], w1 = wrow[k0 + 1];
                    __nv_bfloat16 h0 = __float2bfloat16_rn(w0);
                    __nv_bfloat16 h1 = __float2bfloat16_rn(w1);
                    float r0 = w0 - __bfloat162float(h0);
                    float r1 = w1 - __bfloat162float(h1);
                    bhi[nt][kt][half] = pack_bf2(__bfloat162float(h0), __bfloat162float(h1));
                    blo[nt][kt][half] = pack_bf2(r0, r1);
                }
            }
        }
    }
    __syncthreads();

    const int ntiles = nE / EB;
    for (int t = blockIdx.x; t < ntiles; t += gridDim.x) {
        const int e0 = t * EB;
        for (int i = tid; i < EB * IN1; i += 256) f1s[i] = feat1[(size_t)e0 * IN1 + i];
        for (int i = tid; i < EB * IN2; i += 256) f2s[i] = feat2[(size_t)e0 * IN2 + i];
        if (tid < EB) { sidx[tid] = ei[e0 + tid]; sidx[EB + tid] = ei[nE + e0 + tid]; }
        __syncthreads();

        // gather x rows into padded xs
        for (int i = tid; i < EB * HH; i += 256) {
            int e = i >> 7, h = i & 127;
            xs[e * XP + h] = xact[(size_t)sidx[e] * HH + h];
        }

        // ---- phase A: m = feat @ W1^T (fp32), store bf16 hi/lo ----
        {
            const int k = tid & 63, g = tid >> 6;
            {
                const u64* wrow = (const u64*)(Ws1a + k * IN1);
                const u64* fr0 = (const u64*)(f1s + (g + 0)  * IN1);
                const u64* fr1 = (const u64*)(f1s + (g + 4)  * IN1);
                const u64* fr2 = (const u64*)(f1s + (g + 8)  * IN1);
                const u64* fr3 = (const u64*)(f1s + (g + 12) * IN1);
                u64 a0 = 0ull, a1 = 0ull, a2 = 0ull, a3 = 0ull;
#pragma unroll
                for (int jp = 0; jp < IN1 / 2; jp++) {
                    u64 w = wrow[jp];
                    FMA2(a0, fr0[jp], w, a0);
                    FMA2(a1, fr1[jp], w, a1);
                    FMA2(a2, fr2[jp], w, a2);
                    FMA2(a3, fr3[jp], w, a3);
                }
                float lo, hi;
#pragma unroll
                for (int q = 0; q < 4; q++) {
                    u64 a = (q == 0) ? a0 : (q == 1) ? a1 : (q == 2) ? a2 : a3;
                    unpack2(a, lo, hi);
                    float v = lo + hi;
                    int e = g + 4 * q;
                    __nv_bfloat16 bh = __float2bfloat16_rn(v);
                    mh1s[e * MP + k] = bh;
                    ml1s[e * MP + k] = __float2bfloat16_rn(v - __bfloat162float(bh));
                }
            }
            {
                const u64* wrow = (const u64*)(Ws1b + k * IN2);
                const u64* fr0 = (const u64*)(f2s + (g + 0)  * IN2);
                const u64* fr1 = (const u64*)(f2s + (g + 4)  * IN2);
                const u64* fr2 = (const u64*)(f2s + (g + 8)  * IN2);
                const u64* fr3 = (const u64*)(f2s + (g + 12) * IN2);
                u64 a0 = 0ull, a1 = 0ull, a2 = 0ull, a3 = 0ull;
#pragma unroll
                for (int jp = 0; jp < IN2 / 2; jp++) {
                    u64 w = wrow[jp];
                    FMA2(a0, fr0[jp], w, a0);
                    FMA2(a1, fr1[jp], w, a1);
                    FMA2(a2, fr2[jp], w, a2);
                    FMA2(a3, fr3[jp], w, a3);
                }
                float lo, hi;
#pragma unroll
                for (int q = 0; q < 4; q++) {
                    u64 a = (q == 0) ? a0 : (q == 1) ? a1 : (q == 2) ? a2 : a3;
                    unpack2(a, lo, hi);
                    float v = lo + hi;
                    int e = g + 4 * q;
                    __nv_bfloat16 bh = __float2bfloat16_rn(v);
                    mh2s[e * MP + k] = bh;
                    ml2s[e * MP + k] = __float2bfloat16_rn(v - __bfloat162float(bh));
                }
            }
        }
        __syncthreads();

        // ---- phase B: D[16 x 32ch] per warp via 48 HMMA (split-bf16) ----
        {
            const __nv_bfloat16* mh = (warp < 4) ? mh1s : mh2s;
            const __nv_bfloat16* ml = (warp < 4) ? ml1s : ml2s;
            float* agg = (warp < 4) ? agg1 : agg2;
            const int nbase = (warp & 3) * 32;

            float acc[4][4];
#pragma unroll
            for (int nt = 0; nt < 4; nt++)
#pragma unroll
                for (int q = 0; q < 4; q++) acc[nt][q] = 0.f;

#pragma unroll
            for (int kt = 0; kt < 4; kt++) {
                const int base0 = fg * MP + kt * 16 + 2 * ft;
                u32 ah0 = *(const u32*)(mh + base0);
                u32 ah1 = *(const u32*)(mh + base0 + 8 * MP);
                u32 ah2 = *(const u32*)(mh + base0 + 8);
                u32 ah3 = *(const u32*)(mh + base0 + 8 * MP + 8);
                u32 al0 = *(const u32*)(ml + base0);
                u32 al1 = *(const u32*)(ml + base0 + 8 * MP);
                u32 al2 = *(const u32*)(ml + base0 + 8);
                u32 al3 = *(const u32*)(ml + base0 + 8 * MP + 8);
#pragma unroll
                for (int nt = 0; nt < 4; nt++) {
                    MMA16816(acc[nt][0], acc[nt][1], acc[nt][2], acc[nt][3],
                             ah0, ah1, ah2, ah3, bhi[nt][kt][0], bhi[nt][kt][1]);
                    MMA16816(acc[nt][0], acc[nt][1], acc[nt][2], acc[nt][3],
                             al0, al1, al2, al3, bhi[nt][kt][0], bhi[nt][kt][1]);
                    MMA16816(acc[nt][0], acc[nt][1], acc[nt][2], acc[nt][3],
                             ah0, ah1, ah2, ah3, blo[nt][kt][0], blo[nt][kt][1]);
                }
            }

            // epilogue: v = D * x[src], paired-channel RED to agg[dst]
            const int dA = sidx[EB + fg];
            const int dB = sidx[EB + fg + 8];
#pragma unroll
            for (int nt = 0; nt < 4; nt++) {
                int ch = nbase + nt * 8 + 2 * ft;
                float2 xga = *(const float2*)(xs + fg * XP + ch);
                float2 xgb = *(const float2*)(xs + (fg + 8) * XP + ch);
                red_add_v2(agg + (size_t)dA * HH + ch, acc[nt][0] * xga.x, acc[nt][1] * xga.y);
                red_add_v2(agg + (size_t)dB * HH + ch, acc[nt][2] * xgb.x, acc[nt][3] * xgb.y);
            }
        }
        __syncthreads();
    }
}

// ---------------- GraphNorm (v4 reds) ----------------
__global__ void norm_sum(const float* __restrict__ hin, const int* __restrict__ batch) {
    int idx = blockIdx.x * blockDim.x + threadIdx.x;
    if (idx >= NN * 32) return;
    int n = idx >> 5, c4 = (idx & 31) << 2;
    int b = batch[n];
    float4 v = *(const float4*)(hin + (size_t)n * HH + c4);
    red_add_v4(&g_mean[b * HH + c4], v);
    if (c4 == 0) atomicAdd(&g_cnt[b], 1.f);
}

__global__ void norm_center(const float* __restrict__ hin, const int* __restrict__ batch,
                            const float* __restrict__ ms, float* __restrict__ hc_out) {
    int idx = blockIdx.x * blockDim.x + threadIdx.x;
    if (idx >= NN * 32) return;
    int n = idx >> 5, c4 = (idx & 31) << 2;
    int b = batch[n];
    float rcnt = 1.f / fmaxf(g_cnt[b], 1.f);
    float4 hv = *(const float4*)(hin + (size_t)n * HH + c4);
    float4 mv = *(const float4*)(&g_mean[b * HH + c4]);
    float4 msv = *(const float4*)(ms + c4);
    float4 hc;
    hc.x = hv.x - mv.x * rcnt * msv.x;
    hc.y = hv.y - mv.y * rcnt * msv.y;
    hc.z = hv.z - mv.z * rcnt * msv.z;
    hc.w = hv.w - mv.w * rcnt * msv.w;
    *(float4*)(hc_out + (size_t)n * HH + c4) = hc;
    float4 sq = make_float4(hc.x * hc.x, hc.y * hc.y, hc.z * hc.z, hc.w * hc.w);
    red_add_v4(&g_var[b * HH + c4], sq);
}

__global__ void norm_apply(const float* __restrict__ hc, const int* __restrict__ batch,
                           const float* __restrict__ w, const float* __restrict__ b_,
                           float* __restrict__ out) {
    int idx = blockIdx.x * blockDim.x + threadIdx.x;
    if (idx >= NN * 32) return;
    int n = idx >> 5, c4 = (idx & 31) << 2;
    int b = batch[n];
    float rcnt = 1.f / fmaxf(g_cnt[b], 1.f);
    float4 hv = *(const float4*)(hc + (size_t)n * HH + c4);
    float4 vv = *(const float4*)(&g_var[b * HH + c4]);
    float4 wv = *(const float4*)(w + c4);
    float4 bv = *(const float4*)(b_ + c4);
    float4 o;
    o.x = wv.x * hv.x * rsqrtf(vv.x * rcnt + 1e-5f) + bv.x;
    o.y = wv.y * hv.y * rsqrtf(vv.y * rcnt + 1e-5f) + bv.y;
    o.z = wv.z * hv.z * rsqrtf(vv.z * rcnt + 1e-5f) + bv.z;
    o.w = wv.w * hv.w * rsqrtf(vv.w * rcnt + 1e-5f) + bv.w;
    *(float4*)(out + (size_t)n * HH + c4) = o;
}

// ---------------- launch ----------------
extern "C" void kernel_launch(void* const* d_in, const int* in_sizes, int n_in,
                              void* d_out, int out_size)
{
    const float* x        = (const float*)d_in[0];
    const float* feature1 = (const float*)d_in[1];
    const float* feature2 = (const float*)d_in[2];
    const int*   ei       = (const int*)d_in[3];
    const int*   batch    = (const int*)d_in[4];
    const float* lin_W    = (const float*)d_in[5];
    const float* lin_b    = (const float*)d_in[6];
    const float* f1_W1    = (const float*)d_in[7];
    const float* f1_W2    = (const float*)d_in[8];
    const float* f2_W1    = (const float*)d_in[9];
    const float* f2_W2    = (const float*)d_in[10];
    const float* c1_rel_W = (const float*)d_in[11];
    const float* c1_rel_b = (const float*)d_in[12];
    const float* c1_rt_W  = (const float*)d_in[13];
    const float* c2_rel_W = (const float*)d_in[14];
    const float* c2_rel_b = (const float*)d_in[15];
    const float* c2_rt_W  = (const float*)d_in[16];
    const float* lin1_W   = (const float*)d_in[17];
    const float* lin1_b   = (const float*)d_in[18];
    const float* lin2_W   = (const float*)d_in[19];
    const float* lin2_b   = (const float*)d_in[20];
    const float* cat_W    = (const float*)d_in[21];
    const float* cat_b    = (const float*)d_in[22];
    const float* norm_w   = (const float*)d_in[23];
    const float* norm_b   = (const float*)d_in[24];
    const float* norm_ms  = (const float*)d_in[25];
    const float* lins_W   = (const float*)d_in[26];
    const float* lins_b   = (const float*)d_in[27];
    const float* final_W  = (const float*)d_in[28];
    const float* final_b  = (const float*)d_in[29];

    const int nN = in_sizes[0] / HH;
    const int nE = in_sizes[3] / 2;

    float *pxact, *pagg1, *pagg2, *pA, *pB, *pC;
    cudaGetSymbolAddress((void**)&pxact, g_xact);
    cudaGetSymbolAddress((void**)&pagg1, g_agg1);
    cudaGetSymbolAddress((void**)&pagg2, g_agg2);
    cudaGetSymbolAddress((void**)&pA, g_A);
    cudaGetSymbolAddress((void**)&pB, g_B);
    cudaGetSymbolAddress((void**)&pC, g_C);

    cudaFuncSetAttribute(gemm_node<false, true,  false>, cudaFuncAttributeMaxDynamicSharedMemorySize, GEMM_SMEM);
    cudaFuncSetAttribute(gemm_node<true,  false, false>, cudaFuncAttributeMaxDynamicSharedMemorySize, GEMM_SMEM);
    cudaFuncSetAttribute(gemm_node<true,  false, true >, cudaFuncAttributeMaxDynamicSharedMemorySize, GEMM_SMEM);
    cudaFuncSetAttribute(gemm_node<false, true,  true >, cudaFuncAttributeMaxDynamicSharedMemorySize, GEMM_SMEM);
    cudaFuncSetAttribute(gemm_node<false, false, false>, cudaFuncAttributeMaxDynamicSharedMemorySize, GEMM_SMEM);

    const int gblocks = (nN + RB - 1) / RB;

    zero_kernel<<<(NN * HH + 255) / 256, 256>>>();

    gemm_node<false, true, false><<<gblocks, 256, GEMM_SMEM>>>(
        x, lin_W, HH, nullptr, nullptr, 0, lin_b, nullptr, pxact, nN);

    edge_kernel<<<296, 256>>>(feature1, feature2, ei,
                              f1_W1, f1_W2, f2_W1, f2_W2,
                              pxact, pagg1, pagg2, nE);

    gemm_node<true, false, false><<<gblocks, 256, GEMM_SMEM>>>(
        pagg1, c1_rel_W, HH, pxact, c1_rt_W, HH, c1_rel_b, nullptr, pA, nN);
    gemm_node<false, true, false><<<gblocks, 256, GEMM_SMEM>>>(
        pA, lin1_W, HH, nullptr, nullptr, 0, lin1_b, nullptr, pB, nN);
    gemm_node<true, false, false><<<gblocks, 256, GEMM_SMEM>>>(
        pagg2, c2_rel_W, HH, pxact, c2_rt_W, HH, c2_rel_b, nullptr, pA, nN);
    gemm_node<false, true, false><<<gblocks, 256, GEMM_SMEM>>>(
        pA, lin2_W, HH, nullptr, nullptr, 0, lin2_b, nullptr, pC, nN);
    gemm_node<true, false, true><<<gblocks, 256, GEMM_SMEM>>>(
        pB, cat_W, 2 * HH, pC, cat_W + HH, 2 * HH, cat_b, pxact, pA, nN);
    gemm_node<false, true, true><<<gblocks, 256, GEMM_SMEM>>>(
        pA, lins_W + 0 * HH * HH, HH, nullptr, nullptr, 0, lins_b + 0 * HH, pA, pB, nN);
    gemm_node<false, true, true><<<gblocks, 256, GEMM_SMEM>>>(
        pB, lins_W + 1 * HH * HH, HH, nullptr, nullptr, 0, lins_b + 1 * HH, pB, pA, nN);
    gemm_node<false, true, true><<<gblocks, 256, GEMM_SMEM>>>(
        pA, lins_W + 2 * HH * HH, HH, nullptr, nullptr, 0, lins_b + 2 * HH, pA, pB, nN);

    const int n32b = (NN * 32 + 255) / 256;
    norm_sum<<<n32b, 256>>>(pB, batch);
    norm_center<<<n32b, 256>>>(pB, batch, norm_ms, pC);
    norm_apply<<<n32b, 256>>>(pC, batch, norm_w, norm_b, pA);

    gemm_node<false, false, false><<<gblocks, 256, GEMM_SMEM>>>(
        pA, final_W, HH, nullptr, nullptr, 0, final_b, nullptr, (float*)d_out, nN);
}

// round 6
// speedup vs baseline: 1.3196x; 1.1066x over previous
#include <cuda_runtime.h>
#include <cuda_bf16.h>

#define NN 50000
#define EE 1000000
#define BB 512
#define HH 128
#define MID 64
#define IN1 54
#define IN2 18

typedef unsigned long long u64;
typedef unsigned int u32;

#define FMA2(d, a, b, c) asm("fma.rn.f32x2 %0, %1, %2, %3;" : "=l"(d) : "l"(a), "l"(b), "l"(c))

__device__ __forceinline__ u64 pack2(float lo, float hi) {
    u64 r; asm("mov.b64 %0, {%1, %2};" : "=l"(r) : "f"(lo), "f"(hi)); return r;
}
__device__ __forceinline__ void unpack2(u64 v, float& lo, float& hi) {
    asm("mov.b64 {%0, %1}, %2;" : "=f"(lo), "=f"(hi) : "l"(v));
}
__device__ __forceinline__ void red_add_v4(float* addr, float4 v) {
    asm volatile("red.global.add.v4.f32 [%0], {%1, %2, %3, %4};"
                 :: "l"(addr), "f"(v.x), "f"(v.y), "f"(v.z), "f"(v.w) : "memory");
}
__device__ __forceinline__ void red_add_v2(float* addr, float a, float b) {
    asm volatile("red.global.add.v2.f32 [%0], {%1, %2};"
                 :: "l"(addr), "f"(a), "f"(b) : "memory");
}
#define MMA16816(c0, c1, c2, c3, a0, a1, a2, a3, b0, b1) \
    asm volatile("mma.sync.aligned.m16n8k16.row.col.f32.bf16.bf16.f32 " \
                 "{%0,%1,%2,%3}, {%4,%5,%6,%7}, {%8,%9}, {%0,%1,%2,%3};" \
                 : "+f"(c0), "+f"(c1), "+f"(c2), "+f"(c3) \
                 : "r"(a0), "r"(a1), "r"(a2), "r"(a3), "r"(b0), "r"(b1))

__device__ __forceinline__ u32 pack_bf2(float e0, float e1) {
    __nv_bfloat162 h = __floats2bfloat162_rn(e0, e1);
    return *(u32*)&h;
}

// ---------------- scratch ----------------
__device__ float g_xact[NN * HH];
__device__ float g_agg1[NN * HH];
__device__ float g_agg2[NN * HH];
__device__ float g_A[NN * HH];
__device__ float g_B[NN * HH];
__device__ float g_C[NN * HH];
__device__ float g_mean[BB * HH];
__device__ float g_var[BB * HH];
__device__ float g_cnt[BB];

__global__ void zero_kernel() {
    int idx = blockIdx.x * blockDim.x + threadIdx.x;
    if (idx < NN * HH) { g_agg1[idx] = 0.f; g_agg2[idx] = 0.f; }
    if (idx < BB * HH) { g_mean[idx] = 0.f; g_var[idx] = 0.f; }
    if (idx < BB) g_cnt[idx] = 0.f;
}

// ---------------- node GEMM via split-bf16 HMMA ----------------
// out = op(A1@W1^T [+ A2@W2^T] + bias [+ resid]); K=128, 128 cols.
// 512 threads, 128-row tile. Warp w: rows (w&7)*16.., cols (w>>3)*64..
constexpr int RB = 128;
constexpr int GP = 136;   // bf16 pitch (lane bank = 4*fg+ft, conflict-free)
constexpr int GEMM_SMEM = 4 * RB * GP * 2;   // Ahi,Alo,Whi,Wlo

template <bool DUAL, bool SWISH, bool RESID>
__global__ __launch_bounds__(512) void gemm_node(
    const float* __restrict__ A1, const float* __restrict__ W1, int ldw1,
    const float* __restrict__ A2, const float* __restrict__ W2, int ldw2,
    const float* __restrict__ bias, const float* __restrict__ resid,
    float* __restrict__ out, int nrows)
{
    extern __shared__ __nv_bfloat16 smb[];
    __nv_bfloat16* Ahi = smb;
    __nv_bfloat16* Alo = smb + RB * GP;
    __nv_bfloat16* Whi = smb + 2 * RB * GP;
    __nv_bfloat16* Wlo = smb + 3 * RB * GP;

    const int tid  = threadIdx.x;
    const int warp = tid >> 5;
    const int lane = tid & 31;
    const int fg   = lane >> 2;
    const int ft   = lane & 3;
    const int rg   = warp & 7;      // row group: rows rg*16 .. rg*16+15
    const int chf  = warp >> 3;     // col half: cols chf*64 .. chf*64+63
    const int r0   = blockIdx.x * RB;

    float acc[8][4];
#pragma unroll
    for (int nt = 0; nt < 8; nt++)
#pragma unroll
        for (int q = 0; q < 4; q++) acc[nt][q] = 0.f;

    const int npass = DUAL ? 2 : 1;
    for (int pass = 0; pass < npass; pass++) {
        const float* A = (pass == 0) ? A1 : A2;
        const float* W = (pass == 0) ? W1 : W2;
        const int ldw  = (pass == 0) ? ldw1 : ldw2;
        if (pass == 1) __syncthreads();

        // load+convert A tile (hi/lo)
        for (int i = tid; i < RB * 128; i += 512) {
            int r = i >> 7, k = i & 127;
            int gr = r0 + r;
            float v = (gr < nrows) ? A[(size_t)gr * 128 + k] : 0.f;
            __nv_bfloat16 h = __float2bfloat16_rn(v);
            Ahi[r * GP + k] = h;
            Alo[r * GP + k] = __float2bfloat16_rn(v - __bfloat162float(h));
        }
        // load+convert W (hi/lo), row-major [c][k]
        for (int i = tid; i < 128 * 128; i += 512) {
            int c = i >> 7, k = i & 127;
            float v = W[(size_t)c * ldw + k];
            __nv_bfloat16 h = __float2bfloat16_rn(v);
            Whi[c * GP + k] = h;
            Wlo[c * GP + k] = __float2bfloat16_rn(v - __bfloat162float(h));
        }
        __syncthreads();

        const int m0 = rg * 16 + fg;
#pragma unroll
        for (int kstep = 0; kstep < 8; kstep++) {
            const int k0 = kstep * 16 + 2 * ft;
            u32 ah0 = *(const u32*)(Ahi + m0 * GP + k0);
            u32 ah1 = *(const u32*)(Ahi + (m0 + 8) * GP + k0);
            u32 ah2 = *(const u32*)(Ahi + m0 * GP + k0 + 8);
            u32 ah3 = *(const u32*)(Ahi + (m0 + 8) * GP + k0 + 8);
            u32 al0 = *(const u32*)(Alo + m0 * GP + k0);
            u32 al1 = *(const u32*)(Alo + (m0 + 8) * GP + k0);
            u32 al2 = *(const u32*)(Alo + m0 * GP + k0 + 8);
            u32 al3 = *(const u32*)(Alo + (m0 + 8) * GP + k0 + 8);
#pragma unroll
            for (int nt = 0; nt < 8; nt++) {
                const int c = chf * 64 + nt * 8 + fg;
                u32 bh0 = *(const u32*)(Whi + c * GP + k0);
                u32 bh1 = *(const u32*)(Whi + c * GP + k0 + 8);
                u32 bl0 = *(const u32*)(Wlo + c * GP + k0);
                u32 bl1 = *(const u32*)(Wlo + c * GP + k0 + 8);
                MMA16816(acc[nt][0], acc[nt][1], acc[nt][2], acc[nt][3],
                         ah0, ah1, ah2, ah3, bh0, bh1);
                MMA16816(acc[nt][0], acc[nt][1], acc[nt][2], acc[nt][3],
                         al0, al1, al2, al3, bh0, bh1);
                MMA16816(acc[nt][0], acc[nt][1], acc[nt][2], acc[nt][3],
                         ah0, ah1, ah2, ah3, bl0, bl1);
            }
        }
    }

    // epilogue: rows m0, m0+8; col pair c_out = chf*64 + nt*8 + 2*ft
    const int m0 = rg * 16 + fg;
    const int rA = r0 + m0, rBr = r0 + m0 + 8;
#pragma unroll
    for (int nt = 0; nt < 8; nt++) {
        const int c = chf * 64 + nt * 8 + 2 * ft;
        float2 bv = *(const float2*)(bias + c);
        float v0 = acc[nt][0] + bv.x, v1 = acc[nt][1] + bv.y;
        float v2 = acc[nt][2] + bv.x, v3 = acc[nt][3] + bv.y;
        if (SWISH) {
            v0 = v0 / (1.f + __expf(-v0));
            v1 = v1 / (1.f + __expf(-v1));
            v2 = v2 / (1.f + __expf(-v2));
            v3 = v3 / (1.f + __expf(-v3));
        }
        if (rA < nrows) {
            if (RESID) {
                float2 rv = *(const float2*)(resid + (size_t)rA * 128 + c);
                v0 += rv.x; v1 += rv.y;
            }
            *(float2*)(out + (size_t)rA * 128 + c) = make_float2(v0, v1);
        }
        if (rBr < nrows) {
            if (RESID) {
                float2 rv = *(const float2*)(resid + (size_t)rBr * 128 + c);
                v2 += rv.x; v3 += rv.y;
            }
            *(float2*)(out + (size_t)rBr * 128 + c) = make_float2(v2, v3);
        }
    }
}

// ---------------- fused edge kernel (unchanged from R5) ----------------
constexpr int EB = 16;
constexpr int MP = 72;
constexpr int XP = 132;

__global__ __launch_bounds__(256) void edge_kernel(
    const float* __restrict__ feat1, const float* __restrict__ feat2,
    const int* __restrict__ ei,
    const float* __restrict__ W1a, const float* __restrict__ W2a,
    const float* __restrict__ W1b, const float* __restrict__ W2b,
    const float* __restrict__ xact,
    float* __restrict__ agg1, float* __restrict__ agg2, int nE)
{
    __shared__ __align__(16) float f1s[EB * IN1];
    __shared__ __align__(16) float f2s[EB * IN2];
    __shared__ __align__(16) __nv_bfloat16 mh1s[EB * MP];
    __shared__ __align__(16) __nv_bfloat16 ml1s[EB * MP];
    __shared__ __align__(16) __nv_bfloat16 mh2s[EB * MP];
    __shared__ __align__(16) __nv_bfloat16 ml2s[EB * MP];
    __shared__ __align__(16) float xs[EB * XP];
    __shared__ int sidx[2 * EB];
    __shared__ __align__(16) float Ws1a[MID * IN1];
    __shared__ __align__(16) float Ws1b[MID * IN2];

    const int tid  = threadIdx.x;
    const int warp = tid >> 5;
    const int lane = tid & 31;
    const int fg   = lane >> 2;
    const int ft   = lane & 3;

    for (int i = tid; i < MID * IN1; i += 256) Ws1a[i] = W1a[i];
    for (int i = tid; i < MID * IN2; i += 256) Ws1b[i] = W1b[i];

    u32 bhi[4][4][2], blo[4][4][2];
    {
        const float* W2 = (warp < 4) ? W2a : W2b;
        const int nbase = (warp & 3) * 32;
#pragma unroll
        for (int nt = 0; nt < 4; nt++) {
            const float* wrow = W2 + (size_t)(nbase + nt * 8 + fg) * MID;
#pragma unroll
            for (int kt = 0; kt < 4; kt++) {
#pragma unroll
                for (int half = 0; half < 2; half++) {
                    int k0 = kt * 16 + half * 8 + 2 * ft;
                    float w0 = wrow[k0], w1 = wrow[k0 + 1];
                    __nv_bfloat16 h0 = __float2bfloat16_rn(w0);
                    __nv_bfloat16 h1 = __float2bfloat16_rn(w1);
                    float r0 = w0 - __bfloat162float(h0);
                    float r1 = w1 - __bfloat162float(h1);
                    bhi[nt][kt][half] = pack_bf2(__bfloat162float(h0), __bfloat162float(h1));
                    blo[nt][kt][half] = pack_bf2(r0, r1);
                }
            }
        }
    }
    __syncthreads();

    const int ntiles = nE / EB;
    for (int t = blockIdx.x; t < ntiles; t += gridDim.x) {
        const int e0 = t * EB;
        for (int i = tid; i < EB * IN1; i += 256) f1s[i] = feat1[(size_t)e0 * IN1 + i];
        for (int i = tid; i < EB * IN2; i += 256) f2s[i] = feat2[(size_t)e0 * IN2 + i];
        if (tid < EB) { sidx[tid] = ei[e0 + tid]; sidx[EB + tid] = ei[nE + e0 + tid]; }
        __syncthreads();

        for (int i = tid; i < EB * HH; i += 256) {
            int e = i >> 7, h = i & 127;
            xs[e * XP + h] = xact[(size_t)sidx[e] * HH + h];
        }

        {
            const int k = tid & 63, g = tid >> 6;
            {
                const u64* wrow = (const u64*)(Ws1a + k * IN1);
                const u64* fr0 = (const u64*)(f1s + (g + 0)  * IN1);
                const u64* fr1 = (const u64*)(f1s + (g + 4)  * IN1);
                const u64* fr2 = (const u64*)(f1s + (g + 8)  * IN1);
                const u64* fr3 = (const u64*)(f1s + (g + 12) * IN1);
                u64 a0 = 0ull, a1 = 0ull, a2 = 0ull, a3 = 0ull;
#pragma unroll
                for (int jp = 0; jp < IN1 / 2; jp++) {
                    u64 w = wrow[jp];
                    FMA2(a0, fr0[jp], w, a0);
                    FMA2(a1, fr1[jp], w, a1);
                    FMA2(a2, fr2[jp], w, a2);
                    FMA2(a3, fr3[jp], w, a3);
                }
                float lo, hi;
#pragma unroll
                for (int q = 0; q < 4; q++) {
                    u64 a = (q == 0) ? a0 : (q == 1) ? a1 : (q == 2) ? a2 : a3;
                    unpack2(a, lo, hi);
                    float v = lo + hi;
                    int e = g + 4 * q;
                    __nv_bfloat16 bh = __float2bfloat16_rn(v);
                    mh1s[e * MP + k] = bh;
                    ml1s[e * MP + k] = __float2bfloat16_rn(v - __bfloat162float(bh));
                }
            }
            {
                const u64* wrow = (const u64*)(Ws1b + k * IN2);
                const u64* fr0 = (const u64*)(f2s + (g + 0)  * IN2);
                const u64* fr1 = (const u64*)(f2s + (g + 4)  * IN2);
                const u64* fr2 = (const u64*)(f2s + (g + 8)  * IN2);
                const u64* fr3 = (const u64*)(f2s + (g + 12) * IN2);
                u64 a0 = 0ull, a1 = 0ull, a2 = 0ull, a3 = 0ull;
#pragma unroll
                for (int jp = 0; jp < IN2 / 2; jp++) {
                    u64 w = wrow[jp];
                    FMA2(a0, fr0[jp], w, a0);
                    FMA2(a1, fr1[jp], w, a1);
                    FMA2(a2, fr2[jp], w, a2);
                    FMA2(a3, fr3[jp], w, a3);
                }
                float lo, hi;
#pragma unroll
                for (int q = 0; q < 4; q++) {
                    u64 a = (q == 0) ? a0 : (q == 1) ? a1 : (q == 2) ? a2 : a3;
                    unpack2(a, lo, hi);
                    float v = lo + hi;
                    int e = g + 4 * q;
                    __nv_bfloat16 bh = __float2bfloat16_rn(v);
                    mh2s[e * MP + k] = bh;
                    ml2s[e * MP + k] = __float2bfloat16_rn(v - __bfloat162float(bh));
                }
            }
        }
        __syncthreads();

        {
            const __nv_bfloat16* mh = (warp < 4) ? mh1s : mh2s;
            const __nv_bfloat16* ml = (warp < 4) ? ml1s : ml2s;
            float* agg = (warp < 4) ? agg1 : agg2;
            const int nbase = (warp & 3) * 32;

            float acc[4][4];
#pragma unroll
            for (int nt = 0; nt < 4; nt++)
#pragma unroll
                for (int q = 0; q < 4; q++) acc[nt][q] = 0.f;

#pragma unroll
            for (int kt = 0; kt < 4; kt++) {
                const int base0 = fg * MP + kt * 16 + 2 * ft;
                u32 ah0 = *(const u32*)(mh + base0);
                u32 ah1 = *(const u32*)(mh + base0 + 8 * MP);
                u32 ah2 = *(const u32*)(mh + base0 + 8);
                u32 ah3 = *(const u32*)(mh + base0 + 8 * MP + 8);
                u32 al0 = *(const u32*)(ml + base0);
                u32 al1 = *(const u32*)(ml + base0 + 8 * MP);
                u32 al2 = *(const u32*)(ml + base0 + 8);
                u32 al3 = *(const u32*)(ml + base0 + 8 * MP + 8);
#pragma unroll
                for (int nt = 0; nt < 4; nt++) {
                    MMA16816(acc[nt][0], acc[nt][1], acc[nt][2], acc[nt][3],
                             ah0, ah1, ah2, ah3, bhi[nt][kt][0], bhi[nt][kt][1]);
                    MMA16816(acc[nt][0], acc[nt][1], acc[nt][2], acc[nt][3],
                             al0, al1, al2, al3, bhi[nt][kt][0], bhi[nt][kt][1]);
                    MMA16816(acc[nt][0], acc[nt][1], acc[nt][2], acc[nt][3],
                             ah0, ah1, ah2, ah3, blo[nt][kt][0], blo[nt][kt][1]);
                }
            }

            const int dA = sidx[EB + fg];
            const int dB = sidx[EB + fg + 8];
#pragma unroll
            for (int nt = 0; nt < 4; nt++) {
                int ch = nbase + nt * 8 + 2 * ft;
                float2 xga = *(const float2*)(xs + fg * XP + ch);
                float2 xgb = *(const float2*)(xs + (fg + 8) * XP + ch);
                red_add_v2(agg + (size_t)dA * HH + ch, acc[nt][0] * xga.x, acc[nt][1] * xga.y);
                red_add_v2(agg + (size_t)dB * HH + ch, acc[nt][2] * xgb.x, acc[nt][3] * xgb.y);
            }
        }
        __syncthreads();
    }
}

// ---------------- GraphNorm ----------------
__global__ void norm_sum(const float* __restrict__ hin, const int* __restrict__ batch) {
    int idx = blockIdx.x * blockDim.x + threadIdx.x;
    if (idx >= NN * 32) return;
    int n = idx >> 5, c4 = (idx & 31) << 2;
    int b = batch[n];
    float4 v = *(const float4*)(hin + (size_t)n * HH + c4);
    red_add_v4(&g_mean[b * HH + c4], v);
    if (c4 == 0) atomicAdd(&g_cnt[b], 1.f);
}

__global__ void norm_center(const float* __restrict__ hin, const int* __restrict__ batch,
                            const float* __restrict__ ms, float* __restrict__ hc_out) {
    int idx = blockIdx.x * blockDim.x + threadIdx.x;
    if (idx >= NN * 32) return;
    int n = idx >> 5, c4 = (idx & 31) << 2;
    int b = batch[n];
    float rcnt = 1.f / fmaxf(g_cnt[b], 1.f);
    float4 hv = *(const float4*)(hin + (size_t)n * HH + c4);
    float4 mv = *(const float4*)(&g_mean[b * HH + c4]);
    float4 msv = *(const float4*)(ms + c4);
    float4 hc;
    hc.x = hv.x - mv.x * rcnt * msv.x;
    hc.y = hv.y - mv.y * rcnt * msv.y;
    hc.z = hv.z - mv.z * rcnt * msv.z;
    hc.w = hv.w - mv.w * rcnt * msv.w;
    *(float4*)(hc_out + (size_t)n * HH + c4) = hc;
    float4 sq = make_float4(hc.x * hc.x, hc.y * hc.y, hc.z * hc.z, hc.w * hc.w);
    red_add_v4(&g_var[b * HH + c4], sq);
}

__global__ void norm_apply(const float* __restrict__ hc, const int* __restrict__ batch,
                           const float* __restrict__ w, const float* __restrict__ b_,
                           float* __restrict__ out) {
    int idx = blockIdx.x * blockDim.x + threadIdx.x;
    if (idx >= NN * 32) return;
    int n = idx >> 5, c4 = (idx & 31) << 2;
    int b = batch[n];
    float rcnt = 1.f / fmaxf(g_cnt[b], 1.f);
    float4 hv = *(const float4*)(hc + (size_t)n * HH + c4);
    float4 vv = *(const float4*)(&g_var[b * HH + c4]);
    float4 wv = *(const float4*)(w + c4);
    float4 bv = *(const float4*)(b_ + c4);
    float4 o;
    o.x = wv.x * hv.x * rsqrtf(vv.x * rcnt + 1e-5f) + bv.x;
    o.y = wv.y * hv.y * rsqrtf(vv.y * rcnt + 1e-5f) + bv.y;
    o.z = wv.z * hv.z * rsqrtf(vv.z * rcnt + 1e-5f) + bv.z;
    o.w = wv.w * hv.w * rsqrtf(vv.w * rcnt + 1e-5f) + bv.w;
    *(float4*)(out + (size_t)n * HH + c4) = o;
}

// ---------------- launch ----------------
extern "C" void kernel_launch(void* const* d_in, const int* in_sizes, int n_in,
                              void* d_out, int out_size)
{
    const float* x        = (const float*)d_in[0];
    const float* feature1 = (const float*)d_in[1];
    const float* feature2 = (const float*)d_in[2];
    const int*   ei       = (const int*)d_in[3];
    const int*   batch    = (const int*)d_in[4];
    const float* lin_W    = (const float*)d_in[5];
    const float* lin_b    = (const float*)d_in[6];
    const float* f1_W1    = (const float*)d_in[7];
    const float* f1_W2    = (const float*)d_in[8];
    const float* f2_W1    = (const float*)d_in[9];
    const float* f2_W2    = (const float*)d_in[10];
    const float* c1_rel_W = (const float*)d_in[11];
    const float* c1_rel_b = (const float*)d_in[12];
    const float* c1_rt_W  = (const float*)d_in[13];
    const float* c2_rel_W = (const float*)d_in[14];
    const float* c2_rel_b = (const float*)d_in[15];
    const float* c2_rt_W  = (const float*)d_in[16];
    const float* lin1_W   = (const float*)d_in[17];
    const float* lin1_b   = (const float*)d_in[18];
    const float* lin2_W   = (const float*)d_in[19];
    const float* lin2_b   = (const float*)d_in[20];
    const float* cat_W    = (const float*)d_in[21];
    const float* cat_b    = (const float*)d_in[22];
    const float* norm_w   = (const float*)d_in[23];
    const float* norm_b   = (const float*)d_in[24];
    const float* norm_ms  = (const float*)d_in[25];
    const float* lins_W   = (const float*)d_in[26];
    const float* lins_b   = (const float*)d_in[27];
    const float* final_W  = (const float*)d_in[28];
    const float* final_b  = (const float*)d_in[29];

    const int nN = in_sizes[0] / HH;
    const int nE = in_sizes[3] / 2;

    float *pxact, *pagg1, *pagg2, *pA, *pB, *pC;
    cudaGetSymbolAddress((void**)&pxact, g_xact);
    cudaGetSymbolAddress((void**)&pagg1, g_agg1);
    cudaGetSymbolAddress((void**)&pagg2, g_agg2);
    cudaGetSymbolAddress((void**)&pA, g_A);
    cudaGetSymbolAddress((void**)&pB, g_B);
    cudaGetSymbolAddress((void**)&pC, g_C);

    cudaFuncSetAttribute(gemm_node<false, true,  false>, cudaFuncAttributeMaxDynamicSharedMemorySize, GEMM_SMEM);
    cudaFuncSetAttribute(gemm_node<true,  false, false>, cudaFuncAttributeMaxDynamicSharedMemorySize, GEMM_SMEM);
    cudaFuncSetAttribute(gemm_node<true,  false, true >, cudaFuncAttributeMaxDynamicSharedMemorySize, GEMM_SMEM);
    cudaFuncSetAttribute(gemm_node<false, true,  true >, cudaFuncAttributeMaxDynamicSharedMemorySize, GEMM_SMEM);
    cudaFuncSetAttribute(gemm_node<false, false, false>, cudaFuncAttributeMaxDynamicSharedMemorySize, GEMM_SMEM);

    const int gblocks = (nN + RB - 1) / RB;

    zero_kernel<<<(NN * HH + 255) / 256, 256>>>();

    gemm_node<false, true, false><<<gblocks, 512, GEMM_SMEM>>>(
        x, lin_W, HH, nullptr, nullptr, 0, lin_b, nullptr, pxact, nN);

    edge_kernel<<<296, 256>>>(feature1, feature2, ei,
                              f1_W1, f1_W2, f2_W1, f2_W2,
                              pxact, pagg1, pagg2, nE);

    gemm_node<true, false, false><<<gblocks, 512, GEMM_SMEM>>>(
        pagg1, c1_rel_W, HH, pxact, c1_rt_W, HH, c1_rel_b, nullptr, pA, nN);
    gemm_node<false, true, false><<<gblocks, 512, GEMM_SMEM>>>(
        pA, lin1_W, HH, nullptr, nullptr, 0, lin1_b, nullptr, pB, nN);
    gemm_node<true, false, false><<<gblocks, 512, GEMM_SMEM>>>(
        pagg2, c2_rel_W, HH, pxact, c2_rt_W, HH, c2_rel_b, nullptr, pA, nN);
    gemm_node<false, true, false><<<gblocks, 512, GEMM_SMEM>>>(
        pA, lin2_W, HH, nullptr, nullptr, 0, lin2_b, nullptr, pC, nN);
    gemm_node<true, false, true><<<gblocks, 512, GEMM_SMEM>>>(
        pB, cat_W, 2 * HH, pC, cat_W + HH, 2 * HH, cat_b, pxact, pA, nN);
    gemm_node<false, true, true><<<gblocks, 512, GEMM_SMEM>>>(
        pA, lins_W + 0 * HH * HH, HH, nullptr, nullptr, 0, lins_b + 0 * HH, pA, pB, nN);
    gemm_node<false, true, true><<<gblocks, 512, GEMM_SMEM>>>(
        pB, lins_W + 1 * HH * HH, HH, nullptr, nullptr, 0, lins_b + 1 * HH, pB, pA, nN);
    gemm_node<false, true, true><<<gblocks, 512, GEMM_SMEM>>>(
        pA, lins_W + 2 * HH * HH, HH, nullptr, nullptr, 0, lins_b + 2 * HH, pA, pB, nN);

    const int n32b = (NN * 32 + 255) / 256;
    norm_sum<<<n32b, 256>>>(pB, batch);
    norm_center<<<n32b, 256>>>(pB, batch, norm_ms, pC);
    norm_apply<<<n32b, 256>>>(pC, batch, norm_w, norm_b, pA);

    gemm_node<false, false, false><<<gblocks, 512, GEMM_SMEM>>>(
        pA, final_W, HH, nullptr, nullptr, 0, final_b, nullptr, (float*)d_out, nN);
}

// round 7
// speedup vs baseline: 1.6653x; 1.2620x over previous
#include <cuda_runtime.h>
#include <cuda_bf16.h>

#define NN 50000
#define EE 1000000
#define BB 512
#define HH 128
#define MID 64
#define IN1 54
#define IN2 18

typedef unsigned long long u64;
typedef unsigned int u32;

#define FMA2(d, a, b, c) asm("fma.rn.f32x2 %0, %1, %2, %3;" : "=l"(d) : "l"(a), "l"(b), "l"(c))

__device__ __forceinline__ u64 pack2(float lo, float hi) {
    u64 r; asm("mov.b64 %0, {%1, %2};" : "=l"(r) : "f"(lo), "f"(hi)); return r;
}
__device__ __forceinline__ void unpack2(u64 v, float& lo, float& hi) {
    asm("mov.b64 {%0, %1}, %2;" : "=f"(lo), "=f"(hi) : "l"(v));
}
__device__ __forceinline__ void red_add_v4(float* addr, float4 v) {
    asm volatile("red.global.add.v4.f32 [%0], {%1, %2, %3, %4};"
                 :: "l"(addr), "f"(v.x), "f"(v.y), "f"(v.z), "f"(v.w) : "memory");
}
__device__ __forceinline__ void red_add_v2(float* addr, float a, float b) {
    asm volatile("red.global.add.v2.f32 [%0], {%1, %2};"
                 :: "l"(addr), "f"(a), "f"(b) : "memory");
}
__device__ __forceinline__ u32 prmt(u32 a, u32 b, u32 s) {
    u32 d; asm("prmt.b32 %0, %1, %2, %3;" : "=r"(d) : "r"(a), "r"(b), "r"(s)); return d;
}
#define MMA16816(c0, c1, c2, c3, a0, a1, a2, a3, b0, b1) \
    asm volatile("mma.sync.aligned.m16n8k16.row.col.f32.bf16.bf16.f32 " \
                 "{%0,%1,%2,%3}, {%4,%5,%6,%7}, {%8,%9}, {%0,%1,%2,%3};" \
                 : "+f"(c0), "+f"(c1), "+f"(c2), "+f"(c3) \
                 : "r"(a0), "r"(a1), "r"(a2), "r"(a3), "r"(b0), "r"(b1))

__device__ __forceinline__ u32 pack_bf2(float e0, float e1) {
    __nv_bfloat162 h = __floats2bfloat162_rn(e0, e1);
    return *(u32*)&h;
}

// ---------------- scratch ----------------
__device__ float g_xact[NN * HH];
__device__ float g_agg1[NN * HH];
__device__ float g_agg2[NN * HH];
__device__ float g_A[NN * HH];
__device__ float g_B[NN * HH];
__device__ float g_C[NN * HH];
__device__ float g_mean[BB * HH];
__device__ float g_var[BB * HH];
__device__ float g_cnt[BB];
// edge MLP first-stage outputs: per element u32 = bf16 hi | bf16 lo << 16
__device__ u32 g_m1p[EE * MID];
__device__ u32 g_m2p[EE * MID];
// preconverted node-GEMM weights: 13 matrices of 128x128, bf16 hi/lo planes
__device__ __nv_bfloat16 g_Wh[13 * 128 * 128];
__device__ __nv_bfloat16 g_Wl[13 * 128 * 128];

__global__ void zero_kernel() {
    int idx = blockIdx.x * blockDim.x + threadIdx.x;
    if (idx < NN * HH) { g_agg1[idx] = 0.f; g_agg2[idx] = 0.f; }
    if (idx < BB * HH) { g_mean[idx] = 0.f; g_var[idx] = 0.f; }
    if (idx < BB) g_cnt[idx] = 0.f;
}

// ---------------- weight prep: fp32 -> bf16 hi/lo planes ----------------
struct WSrc { const float* p; int ldw; };
struct WPack { WSrc w[13]; };

__global__ void prep_weights(WPack wp) {
    int idx = blockIdx.x * blockDim.x + threadIdx.x;
    if (idx >= 13 * 16384) return;
    int m = idx >> 14, r = idx & 16383, c = r >> 7, k = r & 127;
    float v = wp.w[m].p[(size_t)c * wp.w[m].ldw + k];
    __nv_bfloat16 h = __float2bfloat16_rn(v);
    g_Wh[idx] = h;
    g_Wl[idx] = __float2bfloat16_rn(v - __bfloat162float(h));
}

// ---------------- node GEMM via split-bf16 HMMA (RB=64, preconverted W) ----------------
constexpr int RB = 64;
constexpr int GP = 136;   // bf16 pitch
// smem bytes: Ahi/Alo 64*136*2 each, Whi/Wlo 128*136*2 each
constexpr int GEMM_SMEM = (64 + 64 + 128 + 128) * GP * 2;

template <bool DUAL, bool SWISH, bool RESID>
__global__ __launch_bounds__(256) void gemm_node(
    const float* __restrict__ A1, int w1,
    const float* __restrict__ A2, int w2,
    const float* __restrict__ bias, const float* __restrict__ resid,
    float* __restrict__ out, int nrows)
{
    extern __shared__ char smc[];
    __nv_bfloat16* Ahi = (__nv_bfloat16*)(smc);
    __nv_bfloat16* Alo = (__nv_bfloat16*)(smc + 64 * GP * 2);
    __nv_bfloat16* Whi = (__nv_bfloat16*)(smc + 128 * GP * 2);
    __nv_bfloat16* Wlo = (__nv_bfloat16*)(smc + 256 * GP * 2);

    const int tid  = threadIdx.x;
    const int warp = tid >> 5;
    const int lane = tid & 31;
    const int fg   = lane >> 2;
    const int ft   = lane & 3;
    const int rg   = warp & 3;      // rows rg*16 .. rg*16+15
    const int chf  = warp >> 2;     // cols chf*64 .. chf*64+63
    const int r0   = blockIdx.x * RB;

    float acc[8][4];
#pragma unroll
    for (int nt = 0; nt < 8; nt++)
#pragma unroll
        for (int q = 0; q < 4; q++) acc[nt][q] = 0.f;

    const int npass = DUAL ? 2 : 1;
    for (int pass = 0; pass < npass; pass++) {
        const float* A = (pass == 0) ? A1 : A2;
        const int widx = (pass == 0) ? w1 : w2;
        if (pass == 1) __syncthreads();

        // A tile: load fp32 pairs, split to hi/lo pair u32s
        for (int i = tid; i < RB * 64; i += 256) {
            int r = i >> 6, kp = i & 63;
            int gr = r0 + r;
            float2 v = (gr < nrows) ? *(const float2*)(A + (size_t)gr * 128 + 2 * kp)
                                    : make_float2(0.f, 0.f);
            __nv_bfloat16 h0 = __float2bfloat16_rn(v.x);
            __nv_bfloat16 h1 = __float2bfloat16_rn(v.y);
            float l0 = v.x - __bfloat162float(h0);
            float l1 = v.y - __bfloat162float(h1);
            ((u32*)Ahi)[r * 68 + kp] = pack_bf2(__bfloat162float(h0), __bfloat162float(h1));
            ((u32*)Alo)[r * 68 + kp] = pack_bf2(l0, l1);
        }
        // W planes: straight u32 copy from preconverted global
        {
            const u32* srcH = (const u32*)(g_Wh + (size_t)widx * 16384);
            const u32* srcL = (const u32*)(g_Wl + (size_t)widx * 16384);
            for (int i = tid; i < 128 * 64; i += 256) {
                int c = i >> 6, kp = i & 63;
                ((u32*)Whi)[c * 68 + kp] = srcH[i];
                ((u32*)Wlo)[c * 68 + kp] = srcL[i];
            }
        }
        __syncthreads();

        const int m0 = rg * 16 + fg;
#pragma unroll
        for (int kstep = 0; kstep < 8; kstep++) {
            const int k0 = kstep * 16 + 2 * ft;
            u32 ah0 = *(const u32*)(Ahi + m0 * GP + k0);
            u32 ah1 = *(const u32*)(Ahi + (m0 + 8) * GP + k0);
            u32 ah2 = *(const u32*)(Ahi + m0 * GP + k0 + 8);
            u32 ah3 = *(const u32*)(Ahi + (m0 + 8) * GP + k0 + 8);
            u32 al0 = *(const u32*)(Alo + m0 * GP + k0);
            u32 al1 = *(const u32*)(Alo + (m0 + 8) * GP + k0);
            u32 al2 = *(const u32*)(Alo + m0 * GP + k0 + 8);
            u32 al3 = *(const u32*)(Alo + (m0 + 8) * GP + k0 + 8);
#pragma unroll
            for (int nt = 0; nt < 8; nt++) {
                const int c = chf * 64 + nt * 8 + fg;
                u32 bh0 = *(const u32*)(Whi + c * GP + k0);
                u32 bh1 = *(const u32*)(Whi + c * GP + k0 + 8);
                u32 bl0 = *(const u32*)(Wlo + c * GP + k0);
                u32 bl1 = *(const u32*)(Wlo + c * GP + k0 + 8);
                MMA16816(acc[nt][0], acc[nt][1], acc[nt][2], acc[nt][3],
                         ah0, ah1, ah2, ah3, bh0, bh1);
                MMA16816(acc[nt][0], acc[nt][1], acc[nt][2], acc[nt][3],
                         al0, al1, al2, al3, bh0, bh1);
                MMA16816(acc[nt][0], acc[nt][1], acc[nt][2], acc[nt][3],
                         ah0, ah1, ah2, ah3, bl0, bl1);
            }
        }
        if (DUAL && pass == 0) __syncthreads();
    }

    const int m0 = rg * 16 + fg;
    const int rA = r0 + m0, rBr = r0 + m0 + 8;
#pragma unroll
    for (int nt = 0; nt < 8; nt++) {
        const int c = chf * 64 + nt * 8 + 2 * ft;
        float2 bv = *(const float2*)(bias + c);
        float v0 = acc[nt][0] + bv.x, v1 = acc[nt][1] + bv.y;
        float v2 = acc[nt][2] + bv.x, v3 = acc[nt][3] + bv.y;
        if (SWISH) {
            v0 = v0 / (1.f + __expf(-v0));
            v1 = v1 / (1.f + __expf(-v1));
            v2 = v2 / (1.f + __expf(-v2));
            v3 = v3 / (1.f + __expf(-v3));
        }
        if (rA < nrows) {
            if (RESID) {
                float2 rv = *(const float2*)(resid + (size_t)rA * 128 + c);
                v0 += rv.x; v1 += rv.y;
            }
            *(float2*)(out + (size_t)rA * 128 + c) = make_float2(v0, v1);
        }
        if (rBr < nrows) {
            if (RESID) {
                float2 rv = *(const float2*)(resid + (size_t)rBr * 128 + c);
                v2 += rv.x; v3 += rv.y;
            }
            *(float2*)(out + (size_t)rBr * 128 + c) = make_float2(v2, v3);
        }
    }
}

// ---------------- edge stage 1: m = feat @ W1^T, packed bf16 hi/lo to global ----------------
constexpr int EB = 16;

__global__ __launch_bounds__(256) void edge_mlp1(
    const float* __restrict__ feat1, const float* __restrict__ feat2,
    const float* __restrict__ W1a, const float* __restrict__ W1b, int nE)
{
    __shared__ __align__(16) float f1s[EB * IN1];
    __shared__ __align__(16) float f2s[EB * IN2];
    __shared__ __align__(16) float Ws1a[MID * IN1];  // [k][j]
    __shared__ __align__(16) float Ws1b[MID * IN2];

    const int tid = threadIdx.x;
    for (int i = tid; i < MID * IN1; i += 256) Ws1a[i] = W1a[i];
    for (int i = tid; i < MID * IN2; i += 256) Ws1b[i] = W1b[i];
    __syncthreads();

    const int ntiles = nE / EB;
    const int k = tid & 63, g = tid >> 6;

    for (int t = blockIdx.x; t < ntiles; t += gridDim.x) {
        const int e0 = t * EB;
        for (int i = tid; i < EB * IN1; i += 256) f1s[i] = feat1[(size_t)e0 * IN1 + i];
        for (int i = tid; i < EB * IN2; i += 256) f2s[i] = feat2[(size_t)e0 * IN2 + i];
        __syncthreads();

        {
            const u64* wrow = (const u64*)(Ws1a + k * IN1);
            const u64* fr0 = (const u64*)(f1s + (g + 0)  * IN1);
            const u64* fr1 = (const u64*)(f1s + (g + 4)  * IN1);
            const u64* fr2 = (const u64*)(f1s + (g + 8)  * IN1);
            const u64* fr3 = (const u64*)(f1s + (g + 12) * IN1);
            u64 a0 = 0ull, a1 = 0ull, a2 = 0ull, a3 = 0ull;
#pragma unroll
            for (int jp = 0; jp < IN1 / 2; jp++) {
                u64 w = wrow[jp];
                FMA2(a0, fr0[jp], w, a0);
                FMA2(a1, fr1[jp], w, a1);
                FMA2(a2, fr2[jp], w, a2);
                FMA2(a3, fr3[jp], w, a3);
            }
            float lo, hi;
#pragma unroll
            for (int q = 0; q < 4; q++) {
                u64 a = (q == 0) ? a0 : (q == 1) ? a1 : (q == 2) ? a2 : a3;
                unpack2(a, lo, hi);
                float v = lo + hi;
                __nv_bfloat16 bh = __float2bfloat16_rn(v);
                __nv_bfloat16 bl = __float2bfloat16_rn(v - __bfloat162float(bh));
                u32 pk = (u32)__bfloat16_as_ushort(bh) | ((u32)__bfloat16_as_ushort(bl) << 16);
                g_m1p[(size_t)(e0 + g + 4 * q) * MID + k] = pk;
            }
        }
        {
            const u64* wrow = (const u64*)(Ws1b + k * IN2);
            const u64* fr0 = (const u64*)(f2s + (g + 0)  * IN2);
            const u64* fr1 = (const u64*)(f2s + (g + 4)  * IN2);
            const u64* fr2 = (const u64*)(f2s + (g + 8)  * IN2);
            const u64* fr3 = (const u64*)(f2s + (g + 12) * IN2);
            u64 a0 = 0ull, a1 = 0ull, a2 = 0ull, a3 = 0ull;
#pragma unroll
            for (int jp = 0; jp < IN2 / 2; jp++) {
                u64 w = wrow[jp];
                FMA2(a0, fr0[jp], w, a0);
                FMA2(a1, fr1[jp], w, a1);
                FMA2(a2, fr2[jp], w, a2);
                FMA2(a3, fr3[jp], w, a3);
            }
            float lo, hi;
#pragma unroll
            for (int q = 0; q < 4; q++) {
                u64 a = (q == 0) ? a0 : (q == 1) ? a1 : (q == 2) ? a2 : a3;
                unpack2(a, lo, hi);
                float v = lo + hi;
                __nv_bfloat16 bh = __float2bfloat16_rn(v);
                __nv_bfloat16 bl = __float2bfloat16_rn(v - __bfloat162float(bh));
                u32 pk = (u32)__bfloat16_as_ushort(bh) | ((u32)__bfloat16_as_ushort(bl) << 16);
                g_m2p[(size_t)(e0 + g + 4 * q) * MID + k] = pk;
            }
        }
        __syncthreads();
    }
}

// ---------------- edge stage 2: gather + HMMA + scatter, 1 sync/tile ----------------
constexpr int XP = 132;

__global__ __launch_bounds__(256, 2) void edge_scatter(
    const int* __restrict__ ei,
    const float* __restrict__ W2a, const float* __restrict__ W2b,
    const float* __restrict__ xact,
    float* __restrict__ agg1, float* __restrict__ agg2, int nE)
{
    __shared__ __align__(16) float xs[2][EB * XP];

    const int tid  = threadIdx.x;
    const int warp = tid >> 5;
    const int lane = tid & 31;
    const int fg   = lane >> 2;
    const int ft   = lane & 3;

    // preload W2 B-fragments (hi/lo split) into registers
    u32 bhi[4][4][2], blo[4][4][2];
    {
        const float* W2 = (warp < 4) ? W2a : W2b;
        const int nbase = (warp & 3) * 32;
#pragma unroll
        for (int nt = 0; nt < 4; nt++) {
            const float* wrow = W2 + (size_t)(nbase + nt * 8 + fg) * MID;
#pragma unroll
            for (int kt = 0; kt < 4; kt++) {
#pragma unroll
                for (int half = 0; half < 2; half++) {
                    int k0 = kt * 16 + half * 8 + 2 * ft;
                    float w0 = wrow[k0], w1 = wrow[k0 + 1];
                    __nv_bfloat16 h0 = __float2bfloat16_rn(w0);
                    __nv_bfloat16 h1 = __float2bfloat16_rn(w1);
                    bhi[nt][kt][half] = pack_bf2(__bfloat162float(h0), __bfloat162float(h1));
                    blo[nt][kt][half] = pack_bf2(w0 - __bfloat162float(h0),
                                                 w1 - __bfloat162float(h1));
                }
            }
        }
    }

    const int ntiles = nE / EB;

    auto do_gather = [&](int buf, int tt) {
        const int e0n = tt * EB;
#pragma unroll
        for (int j = 0; j < 2; j++) {
            int idx = tid + 256 * j;
            int e = idx >> 5, h4 = (idx & 31) << 2;
            int src = __ldg(ei + e0n + e);
            float4 v = *(const float4*)(xact + (size_t)src * HH + h4);
            *(float4*)(&xs[buf][e * XP + h4]) = v;
        }
    };

    int t = blockIdx.x;
    if (t < ntiles) do_gather(0, t);

    int it = 0;
    for (; t < ntiles; t += gridDim.x, it ^= 1) {
        const int cur = it, nxt = it ^ 1;
        const int tn = t + gridDim.x;
        __syncthreads();                 // xs[cur] ready; prior compute done with xs[nxt]
        if (tn < ntiles) do_gather(nxt, tn);

        // compute tile t
        const int e0 = t * EB;
        const u32* mpl = (warp < 4) ? g_m1p : g_m2p;
        float* agg = (warp < 4) ? agg1 : agg2;
        const int nbase = (warp & 3) * 32;

        float acc[4][4];
#pragma unroll
        for (int nt = 0; nt < 4; nt++)
#pragma unroll
            for (int q = 0; q < 4; q++) acc[nt][q] = 0.f;

        const u32* rowA = mpl + (size_t)(e0 + fg) * MID;
        const u32* rowB = mpl + (size_t)(e0 + fg + 8) * MID;
#pragma unroll
        for (int kt = 0; kt < 4; kt++) {
            const int k0 = kt * 16 + 2 * ft;
            uint2 vA0 = *(const uint2*)(rowA + k0);
            uint2 vA1 = *(const uint2*)(rowB + k0);
            uint2 vA2 = *(const uint2*)(rowA + k0 + 8);
            uint2 vA3 = *(const uint2*)(rowB + k0 + 8);
            u32 ah0 = prmt(vA0.x, vA0.y, 0x5410), al0 = prmt(vA0.x, vA0.y, 0x7632);
            u32 ah1 = prmt(vA1.x, vA1.y, 0x5410), al1 = prmt(vA1.x, vA1.y, 0x7632);
            u32 ah2 = prmt(vA2.x, vA2.y, 0x5410), al2 = prmt(vA2.x, vA2.y, 0x7632);
            u32 ah3 = prmt(vA3.x, vA3.y, 0x5410), al3 = prmt(vA3.x, vA3.y, 0x7632);
#pragma unroll
            for (int nt = 0; nt < 4; nt++) {
                MMA16816(acc[nt][0], acc[nt][1], acc[nt][2], acc[nt][3],
                         ah0, ah1, ah2, ah3, bhi[nt][kt][0], bhi[nt][kt][1]);
                MMA16816(acc[nt][0], acc[nt][1], acc[nt][2], acc[nt][3],
                         al0, al1, al2, al3, bhi[nt][kt][0], bhi[nt][kt][1]);
                MMA16816(acc[nt][0], acc[nt][1], acc[nt][2], acc[nt][3],
                         ah0, ah1, ah2, ah3, blo[nt][kt][0], blo[nt][kt][1]);
            }
        }

        const int dA = __ldg(ei + nE + e0 + fg);
        const int dB = __ldg(ei + nE + e0 + fg + 8);
#pragma unroll
        for (int nt = 0; nt < 4; nt++) {
            int ch = nbase + nt * 8 + 2 * ft;
            float2 xga = *(const float2*)(&xs[cur][fg * XP + ch]);
            float2 xgb = *(const float2*)(&xs[cur][(fg + 8) * XP + ch]);
            red_add_v2(agg + (size_t)dA * HH + ch, acc[nt][0] * xga.x, acc[nt][1] * xga.y);
            red_add_v2(agg + (size_t)dB * HH + ch, acc[nt][2] * xgb.x, acc[nt][3] * xgb.y);
        }
    }
}

// ---------------- GraphNorm ----------------
__global__ void norm_sum(const float* __restrict__ hin, const int* __restrict__ batch) {
    int idx = blockIdx.x * blockDim.x + threadIdx.x;
    if (idx >= NN * 32) return;
    int n = idx >> 5, c4 = (idx & 31) << 2;
    int b = batch[n];
    float4 v = *(const float4*)(hin + (size_t)n * HH + c4);
    red_add_v4(&g_mean[b * HH + c4], v);
    if (c4 == 0) atomicAdd(&g_cnt[b], 1.f);
}

__global__ void norm_center(const float* __restrict__ hin, const int* __restrict__ batch,
                            const float* __restrict__ ms, float* __restrict__ hc_out) {
    int idx = blockIdx.x * blockDim.x + threadIdx.x;
    if (idx >= NN * 32) return;
    int n = idx >> 5, c4 = (idx & 31) << 2;
    int b = batch[n];
    float rcnt = 1.f / fmaxf(g_cnt[b], 1.f);
    float4 hv = *(const float4*)(hin + (size_t)n * HH + c4);
    float4 mv = *(const float4*)(&g_mean[b * HH + c4]);
    float4 msv = *(const float4*)(ms + c4);
    float4 hc;
    hc.x = hv.x - mv.x * rcnt * msv.x;
    hc.y = hv.y - mv.y * rcnt * msv.y;
    hc.z = hv.z - mv.z * rcnt * msv.z;
    hc.w = hv.w - mv.w * rcnt * msv.w;
    *(float4*)(hc_out + (size_t)n * HH + c4) = hc;
    float4 sq = make_float4(hc.x * hc.x, hc.y * hc.y, hc.z * hc.z, hc.w * hc.w);
    red_add_v4(&g_var[b * HH + c4], sq);
}

__global__ void norm_apply(const float* __restrict__ hc, const int* __restrict__ batch,
                           const float* __restrict__ w, const float* __restrict__ b_,
                           float* __restrict__ out) {
    int idx = blockIdx.x * blockDim.x + threadIdx.x;
    if (idx >= NN * 32) return;
    int n = idx >> 5, c4 = (idx & 31) << 2;
    int b = batch[n];
    float rcnt = 1.f / fmaxf(g_cnt[b], 1.f);
    float4 hv = *(const float4*)(hc + (size_t)n * HH + c4);
    float4 vv = *(const float4*)(&g_var[b * HH + c4]);
    float4 wv = *(const float4*)(w + c4);
    float4 bv = *(const float4*)(b_ + c4);
    float4 o;
    o.x = wv.x * hv.x * rsqrtf(vv.x * rcnt + 1e-5f) + bv.x;
    o.y = wv.y * hv.y * rsqrtf(vv.y * rcnt + 1e-5f) + bv.y;
    o.z = wv.z * hv.z * rsqrtf(vv.z * rcnt + 1e-5f) + bv.z;
    o.w = wv.w * hv.w * rsqrtf(vv.w * rcnt + 1e-5f) + bv.w;
    *(float4*)(out + (size_t)n * HH + c4) = o;
}

// ---------------- launch ----------------
extern "C" void kernel_launch(void* const* d_in, const int* in_sizes, int n_in,
                              void* d_out, int out_size)
{
    const float* x        = (const float*)d_in[0];
    const float* feature1 = (const float*)d_in[1];
    const float* feature2 = (const float*)d_in[2];
    const int*   ei       = (const int*)d_in[3];
    const int*   batch    = (const int*)d_in[4];
    const float* lin_W    = (const float*)d_in[5];
    const float* lin_b    = (const float*)d_in[6];
    const float* f1_W1    = (const float*)d_in[7];
    const float* f1_W2    = (const float*)d_in[8];
    const float* f2_W1    = (const float*)d_in[9];
    const float* f2_W2    = (const float*)d_in[10];
    const float* c1_rel_W = (const float*)d_in[11];
    const float* c1_rel_b = (const float*)d_in[12];
    const float* c1_rt_W  = (const float*)d_in[13];
    const float* c2_rel_W = (const float*)d_in[14];
    const float* c2_rel_b = (const float*)d_in[15];
    const float* c2_rt_W  = (const float*)d_in[16];
    const float* lin1_W   = (const float*)d_in[17];
    const float* lin1_b   = (const float*)d_in[18];
    const float* lin2_W   = (const float*)d_in[19];
    const float* lin2_b   = (const float*)d_in[20];
    const float* cat_W    = (const float*)d_in[21];
    const float* cat_b    = (const float*)d_in[22];
    const float* norm_w   = (const float*)d_in[23];
    const float* norm_b   = (const float*)d_in[24];
    const float* norm_ms  = (const float*)d_in[25];
    const float* lins_W   = (const float*)d_in[26];
    const float* lins_b   = (const float*)d_in[27];
    const float* final_W  = (const float*)d_in[28];
    const float* final_b  = (const float*)d_in[29];

    const int nN = in_sizes[0] / HH;
    const int nE = in_sizes[3] / 2;

    float *pxact, *pagg1, *pagg2, *pA, *pB, *pC;
    cudaGetSymbolAddress((void**)&pxact, g_xact);
    cudaGetSymbolAddress((void**)&pagg1, g_agg1);
    cudaGetSymbolAddress((void**)&pagg2, g_agg2);
    cudaGetSymbolAddress((void**)&pA, g_A);
    cudaGetSymbolAddress((void**)&pB, g_B);
    cudaGetSymbolAddress((void**)&pC, g_C);

    cudaFuncSetAttribute(gemm_node<false, true,  false>, cudaFuncAttributeMaxDynamicSharedMemorySize, GEMM_SMEM);
    cudaFuncSetAttribute(gemm_node<true,  false, false>, cudaFuncAttributeMaxDynamicSharedMemorySize, GEMM_SMEM);
    cudaFuncSetAttribute(gemm_node<true,  false, true >, cudaFuncAttributeMaxDynamicSharedMemorySize, GEMM_SMEM);
    cudaFuncSetAttribute(gemm_node<false, true,  true >, cudaFuncAttributeMaxDynamicSharedMemorySize, GEMM_SMEM);
    cudaFuncSetAttribute(gemm_node<false, false, false>, cudaFuncAttributeMaxDynamicSharedMemorySize, GEMM_SMEM);

    const int gblocks = (nN + RB - 1) / RB;

    // weight prep (one pass; deterministic each call)
    WPack wp;
    wp.w[0]  = { lin_W, HH };
    wp.w[1]  = { c1_rel_W, HH };
    wp.w[2]  = { c1_rt_W, HH };
    wp.w[3]  = { lin1_W, HH };
    wp.w[4]  = { c2_rel_W, HH };
    wp.w[5]  = { c2_rt_W, HH };
    wp.w[6]  = { lin2_W, HH };
    wp.w[7]  = { cat_W, 2 * HH };
    wp.w[8]  = { cat_W + HH, 2 * HH };
    wp.w[9]  = { lins_W + 0 * HH * HH, HH };
    wp.w[10] = { lins_W + 1 * HH * HH, HH };
    wp.w[11] = { lins_W + 2 * HH * HH, HH };
    wp.w[12] = { final_W, HH };

    zero_kernel<<<(NN * HH + 255) / 256, 256>>>();
    prep_weights<<<(13 * 16384 + 255) / 256, 256>>>(wp);

    // edge stage 1 (independent of xact)
    edge_mlp1<<<592, 256>>>(feature1, feature2, f1_W1, f2_W1, nE);

    // x_act = swish(x @ lin_W^T + lin_b)
    gemm_node<false, true, false><<<gblocks, 256, GEMM_SMEM>>>(
        x, 0, nullptr, 0, lin_b, nullptr, pxact, nN);

    // edge stage 2
    edge_scatter<<<296, 256>>>(ei, f1_W2, f2_W2, pxact, pagg1, pagg2, nE);

    gemm_node<true, false, false><<<gblocks, 256, GEMM_SMEM>>>(
        pagg1, 1, pxact, 2, c1_rel_b, nullptr, pA, nN);
    gemm_node<false, true, false><<<gblocks, 256, GEMM_SMEM>>>(
        pA, 3, nullptr, 0, lin1_b, nullptr, pB, nN);
    gemm_node<true, false, false><<<gblocks, 256, GEMM_SMEM>>>(
        pagg2, 4, pxact, 5, c2_rel_b, nullptr, pA, nN);
    gemm_node<false, true, false><<<gblocks, 256, GEMM_SMEM>>>(
        pA, 6, nullptr, 0, lin2_b, nullptr, pC, nN);
    gemm_node<true, false, true><<<gblocks, 256, GEMM_SMEM>>>(
        pB, 7, pC, 8, cat_b, pxact, pA, nN);
    gemm_node<false, true, true><<<gblocks, 256, GEMM_SMEM>>>(
        pA, 9, nullptr, 0, lins_b + 0 * HH, pA, pB, nN);
    gemm_node<false, true, true><<<gblocks, 256, GEMM_SMEM>>>(
        pB, 10, nullptr, 0, lins_b + 1 * HH, pB, pA, nN);
    gemm_node<false, true, true><<<gblocks, 256, GEMM_SMEM>>>(
        pA, 11, nullptr, 0, lins_b + 2 * HH, pA, pB, nN);

    const int n32b = (NN * 32 + 255) / 256;
    norm_sum<<<n32b, 256>>>(pB, batch);
    norm_center<<<n32b, 256>>>(pB, batch, norm_ms, pC);
    norm_apply<<<n32b, 256>>>(pC, batch, norm_w, norm_b, pA);

    gemm_node<false, false, false><<<gblocks, 256, GEMM_SMEM>>>(
        pA, 12, nullptr, 0, final_b, nullptr, (float*)d_out, nN);
}

// round 8
// speedup vs baseline: 1.6659x; 1.0004x over previous
#include <cuda_runtime.h>
#include <cuda_bf16.h>

#define NN 50000
#define EE 1000000
#define BB 512
#define HH 128
#define MID 64
#define IN1 54
#define IN2 18

typedef unsigned long long u64;
typedef unsigned int u32;

#define FMA2(d, a, b, c) asm("fma.rn.f32x2 %0, %1, %2, %3;" : "=l"(d) : "l"(a), "l"(b), "l"(c))

__device__ __forceinline__ u64 pack2(float lo, float hi) {
    u64 r; asm("mov.b64 %0, {%1, %2};" : "=l"(r) : "f"(lo), "f"(hi)); return r;
}
__device__ __forceinline__ void unpack2(u64 v, float& lo, float& hi) {
    asm("mov.b64 {%0, %1}, %2;" : "=f"(lo), "=f"(hi) : "l"(v));
}
__device__ __forceinline__ void red_add_v4(float* addr, float4 v) {
    asm volatile("red.global.add.v4.f32 [%0], {%1, %2, %3, %4};"
                 :: "l"(addr), "f"(v.x), "f"(v.y), "f"(v.z), "f"(v.w) : "memory");
}
__device__ __forceinline__ void red_add_v2(float* addr, float a, float b) {
    asm volatile("red.global.add.v2.f32 [%0], {%1, %2};"
                 :: "l"(addr), "f"(a), "f"(b) : "memory");
}
__device__ __forceinline__ u32 prmt(u32 a, u32 b, u32 s) {
    u32 d; asm("prmt.b32 %0, %1, %2, %3;" : "=r"(d) : "r"(a), "r"(b), "r"(s)); return d;
}
#define MMA16816(c0, c1, c2, c3, a0, a1, a2, a3, b0, b1) \
    asm volatile("mma.sync.aligned.m16n8k16.row.col.f32.bf16.bf16.f32 " \
                 "{%0,%1,%2,%3}, {%4,%5,%6,%7}, {%8,%9}, {%0,%1,%2,%3};" \
                 : "+f"(c0), "+f"(c1), "+f"(c2), "+f"(c3) \
                 : "r"(a0), "r"(a1), "r"(a2), "r"(a3), "r"(b0), "r"(b1))

__device__ __forceinline__ u32 pack_bf2(float e0, float e1) {
    __nv_bfloat162 h = __floats2bfloat162_rn(e0, e1);
    return *(u32*)&h;
}

// ---------------- scratch ----------------
__device__ float g_xact[NN * HH];
__device__ float g_agg1[NN * HH];
__device__ float g_agg2[NN * HH];
__device__ float g_A[NN * HH];
__device__ float g_B[NN * HH];
__device__ float g_C[NN * HH];
__device__ float g_mean[BB * HH];
__device__ float g_var[BB * HH];
__device__ float g_cnt[BB];
// edge MLP first-stage outputs: per element u32 = bf16 hi | bf16 lo << 16
__device__ u32 g_m1p[EE * MID];
__device__ u32 g_m2p[EE * MID];
// preconverted node-GEMM weights: 13 matrices of 128x128, bf16 hi/lo planes
__device__ __nv_bfloat16 g_Wh[13 * 128 * 128];
__device__ __nv_bfloat16 g_Wl[13 * 128 * 128];

__global__ void zero_kernel() {
    int idx = blockIdx.x * blockDim.x + threadIdx.x;
    if (idx < NN * HH) { g_agg1[idx] = 0.f; g_agg2[idx] = 0.f; }
    if (idx < BB * HH) { g_mean[idx] = 0.f; g_var[idx] = 0.f; }
    if (idx < BB) g_cnt[idx] = 0.f;
}

// ---------------- weight prep: fp32 -> bf16 hi/lo planes ----------------
struct WSrc { const float* p; int ldw; };
struct WPack { WSrc w[13]; };

__global__ void prep_weights(WPack wp) {
    int idx = blockIdx.x * blockDim.x + threadIdx.x;
    if (idx >= 13 * 16384) return;
    int m = idx >> 14, r = idx & 16383, c = r >> 7, k = r & 127;
    float v = wp.w[m].p[(size_t)c * wp.w[m].ldw + k];
    __nv_bfloat16 h = __float2bfloat16_rn(v);
    g_Wh[idx] = h;
    g_Wl[idx] = __float2bfloat16_rn(v - __bfloat162float(h));
}

// ---------------- node GEMM via split-bf16 HMMA (RB=64, preconverted W) ----------------
constexpr int RB = 64;
constexpr int GP = 136;   // bf16 pitch
// smem bytes: Ahi/Alo 64*136*2 each, Whi/Wlo 128*136*2 each
constexpr int GEMM_SMEM = (64 + 64 + 128 + 128) * GP * 2;

template <bool DUAL, bool SWISH, bool RESID>
__global__ __launch_bounds__(256) void gemm_node(
    const float* __restrict__ A1, int w1,
    const float* __restrict__ A2, int w2,
    const float* __restrict__ bias, const float* __restrict__ resid,
    float* __restrict__ out, int nrows)
{
    extern __shared__ char smc[];
    __nv_bfloat16* Ahi = (__nv_bfloat16*)(smc);
    __nv_bfloat16* Alo = (__nv_bfloat16*)(smc + 64 * GP * 2);
    __nv_bfloat16* Whi = (__nv_bfloat16*)(smc + 128 * GP * 2);
    __nv_bfloat16* Wlo = (__nv_bfloat16*)(smc + 256 * GP * 2);

    const int tid  = threadIdx.x;
    const int warp = tid >> 5;
    const int lane = tid & 31;
    const int fg   = lane >> 2;
    const int ft   = lane & 3;
    const int rg   = warp & 3;      // rows rg*16 .. rg*16+15
    const int chf  = warp >> 2;     // cols chf*64 .. chf*64+63
    const int r0   = blockIdx.x * RB;

    float acc[8][4];
#pragma unroll
    for (int nt = 0; nt < 8; nt++)
#pragma unroll
        for (int q = 0; q < 4; q++) acc[nt][q] = 0.f;

    const int npass = DUAL ? 2 : 1;
    for (int pass = 0; pass < npass; pass++) {
        const float* A = (pass == 0) ? A1 : A2;
        const int widx = (pass == 0) ? w1 : w2;
        if (pass == 1) __syncthreads();

        // A tile: load fp32 pairs, split to hi/lo pair u32s
        for (int i = tid; i < RB * 64; i += 256) {
            int r = i >> 6, kp = i & 63;
            int gr = r0 + r;
            float2 v = (gr < nrows) ? *(const float2*)(A + (size_t)gr * 128 + 2 * kp)
                                    : make_float2(0.f, 0.f);
            __nv_bfloat16 h0 = __float2bfloat16_rn(v.x);
            __nv_bfloat16 h1 = __float2bfloat16_rn(v.y);
            float l0 = v.x - __bfloat162float(h0);
            float l1 = v.y - __bfloat162float(h1);
            ((u32*)Ahi)[r * 68 + kp] = pack_bf2(__bfloat162float(h0), __bfloat162float(h1));
            ((u32*)Alo)[r * 68 + kp] = pack_bf2(l0, l1);
        }
        // W planes: straight u32 copy from preconverted global
        {
            const u32* srcH = (const u32*)(g_Wh + (size_t)widx * 16384);
            const u32* srcL = (const u32*)(g_Wl + (size_t)widx * 16384);
            for (int i = tid; i < 128 * 64; i += 256) {
                int c = i >> 6, kp = i & 63;
                ((u32*)Whi)[c * 68 + kp] = srcH[i];
                ((u32*)Wlo)[c * 68 + kp] = srcL[i];
            }
        }
        __syncthreads();

        const int m0 = rg * 16 + fg;
#pragma unroll
        for (int kstep = 0; kstep < 8; kstep++) {
            const int k0 = kstep * 16 + 2 * ft;
            u32 ah0 = *(const u32*)(Ahi + m0 * GP + k0);
            u32 ah1 = *(const u32*)(Ahi + (m0 + 8) * GP + k0);
            u32 ah2 = *(const u32*)(Ahi + m0 * GP + k0 + 8);
            u32 ah3 = *(const u32*)(Ahi + (m0 + 8) * GP + k0 + 8);
            u32 al0 = *(const u32*)(Alo + m0 * GP + k0);
            u32 al1 = *(const u32*)(Alo + (m0 + 8) * GP + k0);
            u32 al2 = *(const u32*)(Alo + m0 * GP + k0 + 8);
            u32 al3 = *(const u32*)(Alo + (m0 + 8) * GP + k0 + 8);
#pragma unroll
            for (int nt = 0; nt < 8; nt++) {
                const int c = chf * 64 + nt * 8 + fg;
                u32 bh0 = *(const u32*)(Whi + c * GP + k0);
                u32 bh1 = *(const u32*)(Whi + c * GP + k0 + 8);
                u32 bl0 = *(const u32*)(Wlo + c * GP + k0);
                u32 bl1 = *(const u32*)(Wlo + c * GP + k0 + 8);
                MMA16816(acc[nt][0], acc[nt][1], acc[nt][2], acc[nt][3],
                         ah0, ah1, ah2, ah3, bh0, bh1);
                MMA16816(acc[nt][0], acc[nt][1], acc[nt][2], acc[nt][3],
                         al0, al1, al2, al3, bh0, bh1);
                MMA16816(acc[nt][0], acc[nt][1], acc[nt][2], acc[nt][3],
                         ah0, ah1, ah2, ah3, bl0, bl1);
            }
        }
        if (DUAL && pass == 0) __syncthreads();
    }

    const int m0 = rg * 16 + fg;
    const int rA = r0 + m0, rBr = r0 + m0 + 8;
#pragma unroll
    for (int nt = 0; nt < 8; nt++) {
        const int c = chf * 64 + nt * 8 + 2 * ft;
        float2 bv = *(const float2*)(bias + c);
        float v0 = acc[nt][0] + bv.x, v1 = acc[nt][1] + bv.y;
        float v2 = acc[nt][2] + bv.x, v3 = acc[nt][3] + bv.y;
        if (SWISH) {
            v0 = v0 / (1.f + __expf(-v0));
            v1 = v1 / (1.f + __expf(-v1));
            v2 = v2 / (1.f + __expf(-v2));
            v3 = v3 / (1.f + __expf(-v3));
        }
        if (rA < nrows) {
            if (RESID) {
                float2 rv = *(const float2*)(resid + (size_t)rA * 128 + c);
                v0 += rv.x; v1 += rv.y;
            }
            *(float2*)(out + (size_t)rA * 128 + c) = make_float2(v0, v1);
        }
        if (rBr < nrows) {
            if (RESID) {
                float2 rv = *(const float2*)(resid + (size_t)rBr * 128 + c);
                v2 += rv.x; v3 += rv.y;
            }
            *(float2*)(out + (size_t)rBr * 128 + c) = make_float2(v2, v3);
        }
    }
}

// ---------------- edge stage 1: m = feat @ W1^T, packed bf16 hi/lo to global ----------------
constexpr int EB = 16;

__global__ __launch_bounds__(256) void edge_mlp1(
    const float* __restrict__ feat1, const float* __restrict__ feat2,
    const float* __restrict__ W1a, const float* __restrict__ W1b, int nE)
{
    __shared__ __align__(16) float f1s[EB * IN1];
    __shared__ __align__(16) float f2s[EB * IN2];
    __shared__ __align__(16) float Ws1a[MID * IN1];  // [k][j]
    __shared__ __align__(16) float Ws1b[MID * IN2];

    const int tid = threadIdx.x;
    for (int i = tid; i < MID * IN1; i += 256) Ws1a[i] = W1a[i];
    for (int i = tid; i < MID * IN2; i += 256) Ws1b[i] = W1b[i];
    __syncthreads();

    const int ntiles = nE / EB;
    const int k = tid & 63, g = tid >> 6;

    for (int t = blockIdx.x; t < ntiles; t += gridDim.x) {
        const int e0 = t * EB;
        for (int i = tid; i < EB * IN1; i += 256) f1s[i] = feat1[(size_t)e0 * IN1 + i];
        for (int i = tid; i < EB * IN2; i += 256) f2s[i] = feat2[(size_t)e0 * IN2 + i];
        __syncthreads();

        {
            const u64* wrow = (const u64*)(Ws1a + k * IN1);
            const u64* fr0 = (const u64*)(f1s + (g + 0)  * IN1);
            const u64* fr1 = (const u64*)(f1s + (g + 4)  * IN1);
            const u64* fr2 = (const u64*)(f1s + (g + 8)  * IN1);
            const u64* fr3 = (const u64*)(f1s + (g + 12) * IN1);
            u64 a0 = 0ull, a1 = 0ull, a2 = 0ull, a3 = 0ull;
#pragma unroll
            for (int jp = 0; jp < IN1 / 2; jp++) {
                u64 w = wrow[jp];
                FMA2(a0, fr0[jp], w, a0);
                FMA2(a1, fr1[jp], w, a1);
                FMA2(a2, fr2[jp], w, a2);
                FMA2(a3, fr3[jp], w, a3);
            }
            float lo, hi;
#pragma unroll
            for (int q = 0; q < 4; q++) {
                u64 a = (q == 0) ? a0 : (q == 1) ? a1 : (q == 2) ? a2 : a3;
                unpack2(a, lo, hi);
                float v = lo + hi;
                __nv_bfloat16 bh = __float2bfloat16_rn(v);
                __nv_bfloat16 bl = __float2bfloat16_rn(v - __bfloat162float(bh));
                u32 pk = (u32)__bfloat16_as_ushort(bh) | ((u32)__bfloat16_as_ushort(bl) << 16);
                g_m1p[(size_t)(e0 + g + 4 * q) * MID + k] = pk;
            }
        }
        {
            const u64* wrow = (const u64*)(Ws1b + k * IN2);
            const u64* fr0 = (const u64*)(f2s + (g + 0)  * IN2);
            const u64* fr1 = (const u64*)(f2s + (g + 4)  * IN2);
            const u64* fr2 = (const u64*)(f2s + (g + 8)  * IN2);
            const u64* fr3 = (const u64*)(f2s + (g + 12) * IN2);
            u64 a0 = 0ull, a1 = 0ull, a2 = 0ull, a3 = 0ull;
#pragma unroll
            for (int jp = 0; jp < IN2 / 2; jp++) {
                u64 w = wrow[jp];
                FMA2(a0, fr0[jp], w, a0);
                FMA2(a1, fr1[jp], w, a1);
                FMA2(a2, fr2[jp], w, a2);
                FMA2(a3, fr3[jp], w, a3);
            }
            float lo, hi;
#pragma unroll
            for (int q = 0; q < 4; q++) {
                u64 a = (q == 0) ? a0 : (q == 1) ? a1 : (q == 2) ? a2 : a3;
                unpack2(a, lo, hi);
                float v = lo + hi;
                __nv_bfloat16 bh = __float2bfloat16_rn(v);
                __nv_bfloat16 bl = __float2bfloat16_rn(v - __bfloat162float(bh));
                u32 pk = (u32)__bfloat16_as_ushort(bh) | ((u32)__bfloat16_as_ushort(bl) << 16);
                g_m2p[(size_t)(e0 + g + 4 * q) * MID + k] = pk;
            }
        }
        __syncthreads();
    }
}

// ---------------- edge stage 2: gather + HMMA + scatter, 1 sync/tile ----------------
constexpr int XP = 132;

__global__ __launch_bounds__(256, 2) void edge_scatter(
    const int* __restrict__ ei,
    const float* __restrict__ W2a, const float* __restrict__ W2b,
    const float* __restrict__ xact,
    float* __restrict__ agg1, float* __restrict__ agg2, int nE)
{
    __shared__ __align__(16) float xs[2][EB * XP];

    const int tid  = threadIdx.x;
    const int warp = tid >> 5;
    const int lane = tid & 31;
    const int fg   = lane >> 2;
    const int ft   = lane & 3;

    // preload W2 B-fragments (hi/lo split) into registers
    u32 bhi[4][4][2], blo[4][4][2];
    {
        const float* W2 = (warp < 4) ? W2a : W2b;
        const int nbase = (warp & 3) * 32;
#pragma unroll
        for (int nt = 0; nt < 4; nt++) {
            const float* wrow = W2 + (size_t)(nbase + nt * 8 + fg) * MID;
#pragma unroll
            for (int kt = 0; kt < 4; kt++) {
#pragma unroll
                for (int half = 0; half < 2; half++) {
                    int k0 = kt * 16 + half * 8 + 2 * ft;
                    float w0 = wrow[k0], w1 = wrow[k0 + 1];
                    __nv_bfloat16 h0 = __float2bfloat16_rn(w0);
                    __nv_bfloat16 h1 = __float2bfloat16_rn(w1);
                    bhi[nt][kt][half] = pack_bf2(__bfloat162float(h0), __bfloat162float(h1));
                    blo[nt][kt][half] = pack_bf2(w0 - __bfloat162float(h0),
                                                 w1 - __bfloat162float(h1));
                }
            }
        }
    }

    const int ntiles = nE / EB;

    auto do_gather = [&](int buf, int tt) {
        const int e0n = tt * EB;
#pragma unroll
        for (int j = 0; j < 2; j++) {
            int idx = tid + 256 * j;
            int e = idx >> 5, h4 = (idx & 31) << 2;
            int src = __ldg(ei + e0n + e);
            float4 v = *(const float4*)(xact + (size_t)src * HH + h4);
            *(float4*)(&xs[buf][e * XP + h4]) = v;
        }
    };

    int t = blockIdx.x;
    if (t < ntiles) do_gather(0, t);

    int it = 0;
    for (; t < ntiles; t += gridDim.x, it ^= 1) {
        const int cur = it, nxt = it ^ 1;
        const int tn = t + gridDim.x;
        __syncthreads();                 // xs[cur] ready; prior compute done with xs[nxt]
        if (tn < ntiles) do_gather(nxt, tn);

        // compute tile t
        const int e0 = t * EB;
        const u32* mpl = (warp < 4) ? g_m1p : g_m2p;
        float* agg = (warp < 4) ? agg1 : agg2;
        const int nbase = (warp & 3) * 32;

        float acc[4][4];
#pragma unroll
        for (int nt = 0; nt < 4; nt++)
#pragma unroll
            for (int q = 0; q < 4; q++) acc[nt][q] = 0.f;

        const u32* rowA = mpl + (size_t)(e0 + fg) * MID;
        const u32* rowB = mpl + (size_t)(e0 + fg + 8) * MID;
#pragma unroll
        for (int kt = 0; kt < 4; kt++) {
            const int k0 = kt * 16 + 2 * ft;
            uint2 vA0 = *(const uint2*)(rowA + k0);
            uint2 vA1 = *(const uint2*)(rowB + k0);
            uint2 vA2 = *(const uint2*)(rowA + k0 + 8);
            uint2 vA3 = *(const uint2*)(rowB + k0 + 8);
            u32 ah0 = prmt(vA0.x, vA0.y, 0x5410), al0 = prmt(vA0.x, vA0.y, 0x7632);
            u32 ah1 = prmt(vA1.x, vA1.y, 0x5410), al1 = prmt(vA1.x, vA1.y, 0x7632);
            u32 ah2 = prmt(vA2.x, vA2.y, 0x5410), al2 = prmt(vA2.x, vA2.y, 0x7632);
            u32 ah3 = prmt(vA3.x, vA3.y, 0x5410), al3 = prmt(vA3.x, vA3.y, 0x7632);
#pragma unroll
            for (int nt = 0; nt < 4; nt++) {
                MMA16816(acc[nt][0], acc[nt][1], acc[nt][2], acc[nt][3],
                         ah0, ah1, ah2, ah3, bhi[nt][kt][0], bhi[nt][kt][1]);
                MMA16816(acc[nt][0], acc[nt][1], acc[nt][2], acc[nt][3],
                         al0, al1, al2, al3, bhi[nt][kt][0], bhi[nt][kt][1]);
                MMA16816(acc[nt][0], acc[nt][1], acc[nt][2], acc[nt][3],
                         ah0, ah1, ah2, ah3, blo[nt][kt][0], blo[nt][kt][1]);
            }
        }

        const int dA = __ldg(ei + nE + e0 + fg);
        const int dB = __ldg(ei + nE + e0 + fg + 8);
#pragma unroll
        for (int nt = 0; nt < 4; nt++) {
            int ch = nbase + nt * 8 + 2 * ft;
            float2 xga = *(const float2*)(&xs[cur][fg * XP + ch]);
            float2 xgb = *(const float2*)(&xs[cur][(fg + 8) * XP + ch]);
            red_add_v2(agg + (size_t)dA * HH + ch, acc[nt][0] * xga.x, acc[nt][1] * xga.y);
            red_add_v2(agg + (size_t)dB * HH + ch, acc[nt][2] * xgb.x, acc[nt][3] * xgb.y);
        }
    }
}

// ---------------- GraphNorm ----------------
__global__ void norm_sum(const float* __restrict__ hin, const int* __restrict__ batch) {
    int idx = blockIdx.x * blockDim.x + threadIdx.x;
    if (idx >= NN * 32) return;
    int n = idx >> 5, c4 = (idx & 31) << 2;
    int b = batch[n];
    float4 v = *(const float4*)(hin + (size_t)n * HH + c4);
    red_add_v4(&g_mean[b * HH + c4], v);
    if (c4 == 0) atomicAdd(&g_cnt[b], 1.f);
}

__global__ void norm_center(const float* __restrict__ hin, const int* __restrict__ batch,
                            const float* __restrict__ ms, float* __restrict__ hc_out) {
    int idx = blockIdx.x * blockDim.x + threadIdx.x;
    if (idx >= NN * 32) return;
    int n = idx >> 5, c4 = (idx & 31) << 2;
    int b = batch[n];
    float rcnt = 1.f / fmaxf(g_cnt[b], 1.f);
    float4 hv = *(const float4*)(hin + (size_t)n * HH + c4);
    float4 mv = *(const float4*)(&g_mean[b * HH + c4]);
    float4 msv = *(const float4*)(ms + c4);
    float4 hc;
    hc.x = hv.x - mv.x * rcnt * msv.x;
    hc.y = hv.y - mv.y * rcnt * msv.y;
    hc.z = hv.z - mv.z * rcnt * msv.z;
    hc.w = hv.w - mv.w * rcnt * msv.w;
    *(float4*)(hc_out + (size_t)n * HH + c4) = hc;
    float4 sq = make_float4(hc.x * hc.x, hc.y * hc.y, hc.z * hc.z, hc.w * hc.w);
    red_add_v4(&g_var[b * HH + c4], sq);
}

__global__ void norm_apply(const float* __restrict__ hc, const int* __restrict__ batch,
                           const float* __restrict__ w, const float* __restrict__ b_,
                           float* __restrict__ out) {
    int idx = blockIdx.x * blockDim.x + threadIdx.x;
    if (idx >= NN * 32) return;
    int n = idx >> 5, c4 = (idx & 31) << 2;
    int b = batch[n];
    float rcnt = 1.f / fmaxf(g_cnt[b], 1.f);
    float4 hv = *(const float4*)(hc + (size_t)n * HH + c4);
    float4 vv = *(const float4*)(&g_var[b * HH + c4]);
    float4 wv = *(const float4*)(w + c4);
    float4 bv = *(const float4*)(b_ + c4);
    float4 o;
    o.x = wv.x * hv.x * rsqrtf(vv.x * rcnt + 1e-5f) + bv.x;
    o.y = wv.y * hv.y * rsqrtf(vv.y * rcnt + 1e-5f) + bv.y;
    o.z = wv.z * hv.z * rsqrtf(vv.z * rcnt + 1e-5f) + bv.z;
    o.w = wv.w * hv.w * rsqrtf(vv.w * rcnt + 1e-5f) + bv.w;
    *(float4*)(out + (size_t)n * HH + c4) = o;
}

// ---------------- launch ----------------
extern "C" void kernel_launch(void* const* d_in, const int* in_sizes, int n_in,
                              void* d_out, int out_size)
{
    const float* x        = (const float*)d_in[0];
    const float* feature1 = (const float*)d_in[1];
    const float* feature2 = (const float*)d_in[2];
    const int*   ei       = (const int*)d_in[3];
    const int*   batch    = (const int*)d_in[4];
    const float* lin_W    = (const float*)d_in[5];
    const float* lin_b    = (const float*)d_in[6];
    const float* f1_W1    = (const float*)d_in[7];
    const float* f1_W2    = (const float*)d_in[8];
    const float* f2_W1    = (const float*)d_in[9];
    const float* f2_W2    = (const float*)d_in[10];
    const float* c1_rel_W = (const float*)d_in[11];
    const float* c1_rel_b = (const float*)d_in[12];
    const float* c1_rt_W  = (const float*)d_in[13];
    const float* c2_rel_W = (const float*)d_in[14];
    const float* c2_rel_b = (const float*)d_in[15];
    const float* c2_rt_W  = (const float*)d_in[16];
    const float* lin1_W   = (const float*)d_in[17];
    const float* lin1_b   = (const float*)d_in[18];
    const float* lin2_W   = (const float*)d_in[19];
    const float* lin2_b   = (const float*)d_in[20];
    const float* cat_W    = (const float*)d_in[21];
    const float* cat_b    = (const float*)d_in[22];
    const float* norm_w   = (const float*)d_in[23];
    const float* norm_b   = (const float*)d_in[24];
    const float* norm_ms  = (const float*)d_in[25];
    const float* lins_W   = (const float*)d_in[26];
    const float* lins_b   = (const float*)d_in[27];
    const float* final_W  = (const float*)d_in[28];
    const float* final_b  = (const float*)d_in[29];

    const int nN = in_sizes[0] / HH;
    const int nE = in_sizes[3] / 2;

    float *pxact, *pagg1, *pagg2, *pA, *pB, *pC;
    cudaGetSymbolAddress((void**)&pxact, g_xact);
    cudaGetSymbolAddress((void**)&pagg1, g_agg1);
    cudaGetSymbolAddress((void**)&pagg2, g_agg2);
    cudaGetSymbolAddress((void**)&pA, g_A);
    cudaGetSymbolAddress((void**)&pB, g_B);
    cudaGetSymbolAddress((void**)&pC, g_C);

    cudaFuncSetAttribute(gemm_node<false, true,  false>, cudaFuncAttributeMaxDynamicSharedMemorySize, GEMM_SMEM);
    cudaFuncSetAttribute(gemm_node<true,  false, false>, cudaFuncAttributeMaxDynamicSharedMemorySize, GEMM_SMEM);
    cudaFuncSetAttribute(gemm_node<true,  false, true >, cudaFuncAttributeMaxDynamicSharedMemorySize, GEMM_SMEM);
    cudaFuncSetAttribute(gemm_node<false, true,  true >, cudaFuncAttributeMaxDynamicSharedMemorySize, GEMM_SMEM);
    cudaFuncSetAttribute(gemm_node<false, false, false>, cudaFuncAttributeMaxDynamicSharedMemorySize, GEMM_SMEM);

    const int gblocks = (nN + RB - 1) / RB;

    // weight prep (one pass; deterministic each call)
    WPack wp;
    wp.w[0]  = { lin_W, HH };
    wp.w[1]  = { c1_rel_W, HH };
    wp.w[2]  = { c1_rt_W, HH };
    wp.w[3]  = { lin1_W, HH };
    wp.w[4]  = { c2_rel_W, HH };
    wp.w[5]  = { c2_rt_W, HH };
    wp.w[6]  = { lin2_W, HH };
    wp.w[7]  = { cat_W, 2 * HH };
    wp.w[8]  = { cat_W + HH, 2 * HH };
    wp.w[9]  = { lins_W + 0 * HH * HH, HH };
    wp.w[10] = { lins_W + 1 * HH * HH, HH };
    wp.w[11] = { lins_W + 2 * HH * HH, HH };
    wp.w[12] = { final_W, HH };

    zero_kernel<<<(NN * HH + 255) / 256, 256>>>();
    prep_weights<<<(13 * 16384 + 255) / 256, 256>>>(wp);

    // edge stage 1 (independent of xact)
    edge_mlp1<<<592, 256>>>(feature1, feature2, f1_W1, f2_W1, nE);

    // x_act = swish(x @ lin_W^T + lin_b)
    gemm_node<false, true, false><<<gblocks, 256, GEMM_SMEM>>>(
        x, 0, nullptr, 0, lin_b, nullptr, pxact, nN);

    // edge stage 2
    edge_scatter<<<296, 256>>>(ei, f1_W2, f2_W2, pxact, pagg1, pagg2, nE);

    gemm_node<true, false, false><<<gblocks, 256, GEMM_SMEM>>>(
        pagg1, 1, pxact, 2, c1_rel_b, nullptr, pA, nN);
    gemm_node<false, true, false><<<gblocks, 256, GEMM_SMEM>>>(
        pA, 3, nullptr, 0, lin1_b, nullptr, pB, nN);
    gemm_node<true, false, false><<<gblocks, 256, GEMM_SMEM>>>(
        pagg2, 4, pxact, 5, c2_rel_b, nullptr, pA, nN);
    gemm_node<false, true, false><<<gblocks, 256, GEMM_SMEM>>>(
        pA, 6, nullptr, 0, lin2_b, nullptr, pC, nN);
    gemm_node<true, false, true><<<gblocks, 256, GEMM_SMEM>>>(
        pB, 7, pC, 8, cat_b, pxact, pA, nN);
    gemm_node<false, true, true><<<gblocks, 256, GEMM_SMEM>>>(
        pA, 9, nullptr, 0, lins_b + 0 * HH, pA, pB, nN);
    gemm_node<false, true, true><<<gblocks, 256, GEMM_SMEM>>>(
        pB, 10, nullptr, 0, lins_b + 1 * HH, pB, pA, nN);
    gemm_node<false, true, true><<<gblocks, 256, GEMM_SMEM>>>(
        pA, 11, nullptr, 0, lins_b + 2 * HH, pA, pB, nN);

    const int n32b = (NN * 32 + 255) / 256;
    norm_sum<<<n32b, 256>>>(pB, batch);
    norm_center<<<n32b, 256>>>(pB, batch, norm_ms, pC);
    norm_apply<<<n32b, 256>>>(pC, batch, norm_w, norm_b, pA);

    gemm_node<false, false, false><<<gblocks, 256, GEMM_SMEM>>>(
        pA, 12, nullptr, 0, final_b, nullptr, (float*)d_out, nN);
}

// round 10
// speedup vs baseline: 1.6786x; 1.0076x over previous
#include <cuda_runtime.h>
#include <cuda_bf16.h>

#define NN 50000
#define EE 1000000
#define BB 512
#define HH 128
#define MID 64
#define IN1 54
#define IN2 18

typedef unsigned long long u64;
typedef unsigned int u32;

#define FMA2(d, a, b, c) asm("fma.rn.f32x2 %0, %1, %2, %3;" : "=l"(d) : "l"(a), "l"(b), "l"(c))

__device__ __forceinline__ u64 pack2(float lo, float hi) {
    u64 r; asm("mov.b64 %0, {%1, %2};" : "=l"(r) : "f"(lo), "f"(hi)); return r;
}
__device__ __forceinline__ void unpack2(u64 v, float& lo, float& hi) {
    asm("mov.b64 {%0, %1}, %2;" : "=f"(lo), "=f"(hi) : "l"(v));
}
__device__ __forceinline__ void red_add_v4(float* addr, float4 v) {
    asm volatile("red.global.add.v4.f32 [%0], {%1, %2, %3, %4};"
                 :: "l"(addr), "f"(v.x), "f"(v.y), "f"(v.z), "f"(v.w) : "memory");
}
__device__ __forceinline__ void red_add_v2(float* addr, float a, float b) {
    asm volatile("red.global.add.v2.f32 [%0], {%1, %2};"
                 :: "l"(addr), "f"(a), "f"(b) : "memory");
}
__device__ __forceinline__ u32 prmt(u32 a, u32 b, u32 s) {
    u32 d; asm("prmt.b32 %0, %1, %2, %3;" : "=r"(d) : "r"(a), "r"(b), "r"(s)); return d;
}
#define MMA16816(c0, c1, c2, c3, a0, a1, a2, a3, b0, b1) \
    asm volatile("mma.sync.aligned.m16n8k16.row.col.f32.bf16.bf16.f32 " \
                 "{%0,%1,%2,%3}, {%4,%5,%6,%7}, {%8,%9}, {%0,%1,%2,%3};" \
                 : "+f"(c0), "+f"(c1), "+f"(c2), "+f"(c3) \
                 : "r"(a0), "r"(a1), "r"(a2), "r"(a3), "r"(b0), "r"(b1))

__device__ __forceinline__ u32 pack_bf2(float e0, float e1) {
    __nv_bfloat162 h = __floats2bfloat162_rn(e0, e1);
    return *(u32*)&h;
}

// ---------------- scratch ----------------
__device__ float g_xact[NN * HH];
__device__ float g_agg1[NN * HH];
__device__ float g_agg2[NN * HH];
__device__ float g_A[NN * HH];
__device__ float g_B[NN * HH];
__device__ float g_C[NN * HH];
__device__ float g_mean[BB * HH];
__device__ float g_var[BB * HH];
__device__ float g_cnt[BB];
__device__ u32 g_m1p[EE * MID];
__device__ u32 g_m2p[EE * MID];
// preconverted node-GEMM weights: 13 matrices of 128x128, bf16 hi/lo planes (flat [c][k])
__device__ __nv_bfloat16 g_Wh[13 * 128 * 128];
__device__ __nv_bfloat16 g_Wl[13 * 128 * 128];

__global__ void zero_kernel() {
    int idx = blockIdx.x * blockDim.x + threadIdx.x;
    if (idx < NN * HH) { g_agg1[idx] = 0.f; g_agg2[idx] = 0.f; }
    if (idx < BB * HH) { g_mean[idx] = 0.f; g_var[idx] = 0.f; }
    if (idx < BB) g_cnt[idx] = 0.f;
}

// ---------------- weight prep: fp32 -> bf16 hi/lo planes ----------------
struct WSrc { const float* p; int ldw; };
struct WPack { WSrc w[13]; };

__global__ void prep_weights(WPack wp) {
    int idx = blockIdx.x * blockDim.x + threadIdx.x;
    if (idx >= 13 * 16384) return;
    int m = idx >> 14, r = idx & 16383, c = r >> 7, k = r & 127;
    float v = wp.w[m].p[(size_t)c * wp.w[m].ldw + k];
    __nv_bfloat16 h = __float2bfloat16_rn(v);
    g_Wh[idx] = h;
    g_Wl[idx] = __float2bfloat16_rn(v - __bfloat162float(h));
}

// ---------------- persistent node GEMM via split-bf16 HMMA ----------------
// out [opt +=prev] = A@W [+ bias [+ swish] [+ resid]] ; K=128, 128 cols.
// Grid 296 persistent, 256 threads; W planes loaded ONCE per CTA; 64-row tiles.
constexpr int GP = 136;   // bf16 pitch (conflict-free fragment LDS)
constexpr int GEMM_SMEM = (64 + 64 + 128 + 128) * GP * 2;   // Ahi,Alo,Whi,Wlo

template <bool ACCUM, bool EPI, bool SWISH, bool RESID>
__global__ __launch_bounds__(256) void gemm_p(
    const float* __restrict__ A, int widx,
    const float* __restrict__ bias, const float* __restrict__ resid,
    float* __restrict__ out, int nrows)
{
    extern __shared__ char smc[];
    __nv_bfloat16* Ahi = (__nv_bfloat16*)(smc);
    __nv_bfloat16* Alo = (__nv_bfloat16*)(smc + 64 * GP * 2);
    __nv_bfloat16* Whi = (__nv_bfloat16*)(smc + 128 * GP * 2);
    __nv_bfloat16* Wlo = (__nv_bfloat16*)(smc + 256 * GP * 2);

    const int tid  = threadIdx.x;
    const int warp = tid >> 5;
    const int lane = tid & 31;
    const int fg   = lane >> 2;
    const int ft   = lane & 3;
    const int rg   = warp & 3;      // rows rg*16 .. rg*16+15
    const int chf  = warp >> 2;     // cols chf*64 .. chf*64+63

    // ---- W planes: load once (u32 copies from flat preconverted global) ----
    {
        const u32* srcH = (const u32*)(g_Wh + (size_t)widx * 16384);
        const u32* srcL = (const u32*)(g_Wl + (size_t)widx * 16384);
        for (int i = tid; i < 128 * 64; i += 256) {
            int c = i >> 6, kp = i & 63;
            ((u32*)Whi)[c * 68 + kp] = srcH[i];
            ((u32*)Wlo)[c * 68 + kp] = srcL[i];
        }
    }

    const int ntiles = (nrows + 63) >> 6;
    for (int t = blockIdx.x; t < ntiles; t += gridDim.x) {
        const int r0 = t << 6;
        __syncthreads();   // protect A smem from previous iteration's readers (also covers W fill)

        // ---- A tile fill: fp32 float4 -> hi/lo bf16-pair u64 stores ----
        for (int i = tid; i < 64 * 32; i += 256) {
            int r = i >> 5, kp4 = i & 31;
            int gr = r0 + r;
            float4 v = (gr < nrows) ? *(const float4*)(A + (size_t)gr * 128 + 4 * kp4)
                                    : make_float4(0.f, 0.f, 0.f, 0.f);
            __nv_bfloat162 h01 = __floats2bfloat162_rn(v.x, v.y);
            __nv_bfloat162 h23 = __floats2bfloat162_rn(v.z, v.w);
            __nv_bfloat162 l01 = __floats2bfloat162_rn(v.x - __bfloat162float(h01.x),
                                                       v.y - __bfloat162float(h01.y));
            __nv_bfloat162 l23 = __floats2bfloat162_rn(v.z - __bfloat162float(h23.x),
                                                       v.w - __bfloat162float(h23.y));
            ((u64*)(Ahi + r * GP))[kp4] = (u64)(*(u32*)&h01) | ((u64)(*(u32*)&h23) << 32);
            ((u64*)(Alo + r * GP))[kp4] = (u64)(*(u32*)&l01) | ((u64)(*(u32*)&l23) << 32);
        }
        __syncthreads();

        float acc[8][4];
#pragma unroll
        for (int nt = 0; nt < 8; nt++)
#pragma unroll
            for (int q = 0; q < 4; q++) acc[nt][q] = 0.f;

        const int m0 = rg * 16 + fg;
#pragma unroll
        for (int kstep = 0; kstep < 8; kstep++) {
            const int k0 = kstep * 16 + 2 * ft;
            u32 ah0 = *(const u32*)(Ahi + m0 * GP + k0);
            u32 ah1 = *(const u32*)(Ahi + (m0 + 8) * GP + k0);
            u32 ah2 = *(const u32*)(Ahi + m0 * GP + k0 + 8);
            u32 ah3 = *(const u32*)(Ahi + (m0 + 8) * GP + k0 + 8);
            u32 al0 = *(const u32*)(Alo + m0 * GP + k0);
            u32 al1 = *(const u32*)(Alo + (m0 + 8) * GP + k0);
            u32 al2 = *(const u32*)(Alo + m0 * GP + k0 + 8);
            u32 al3 = *(const u32*)(Alo + (m0 + 8) * GP + k0 + 8);
#pragma unroll
            for (int nt = 0; nt < 8; nt++) {
                const int c = chf * 64 + nt * 8 + fg;
                u32 bh0 = *(const u32*)(Whi + c * GP + k0);
                u32 bh1 = *(const u32*)(Whi + c * GP + k0 + 8);
                u32 bl0 = *(const u32*)(Wlo + c * GP + k0);
                u32 bl1 = *(const u32*)(Wlo + c * GP + k0 + 8);
                MMA16816(acc[nt][0], acc[nt][1], acc[nt][2], acc[nt][3],
                         ah0, ah1, ah2, ah3, bh0, bh1);
                MMA16816(acc[nt][0], acc[nt][1], acc[nt][2], acc[nt][3],
                         al0, al1, al2, al3, bh0, bh1);
                MMA16816(acc[nt][0], acc[nt][1], acc[nt][2], acc[nt][3],
                         ah0, ah1, ah2, ah3, bl0, bl1);
            }
        }

        // ---- epilogue ----
        const int rA = r0 + m0, rBr = r0 + m0 + 8;
#pragma unroll
        for (int nt = 0; nt < 8; nt++) {
            const int c = chf * 64 + nt * 8 + 2 * ft;
            float v0 = acc[nt][0], v1 = acc[nt][1];
            float v2 = acc[nt][2], v3 = acc[nt][3];
            if (EPI) {
                float2 bv = *(const float2*)(bias + c);
                v0 += bv.x; v1 += bv.y; v2 += bv.x; v3 += bv.y;
            }
            if (rA < nrows) {
                float* orow = out + (size_t)rA * 128 + c;
                if (ACCUM) { float2 pv = *(const float2*)orow; v0 += pv.x; v1 += pv.y; }
                if (SWISH) {
                    v0 = v0 / (1.f + __expf(-v0));
                    v1 = v1 / (1.f + __expf(-v1));
                }
                if (RESID) {
                    float2 rv = *(const float2*)(resid + (size_t)rA * 128 + c);
                    v0 += rv.x; v1 += rv.y;
                }
                *(float2*)orow = make_float2(v0, v1);
            }
            if (rBr < nrows) {
                float* orow = out + (size_t)rBr * 128 + c;
                if (ACCUM) { float2 pv = *(const float2*)orow; v2 += pv.x; v3 += pv.y; }
                if (SWISH) {
                    v2 = v2 / (1.f + __expf(-v2));
                    v3 = v3 / (1.f + __expf(-v3));
                }
                if (RESID) {
                    float2 rv = *(const float2*)(resid + (size_t)rBr * 128 + c);
                    v2 += rv.x; v3 += rv.y;
                }
                *(float2*)orow = make_float2(v2, v3);
            }
        }
    }
}

// ---------------- edge stage 1 (unchanged) ----------------
constexpr int EB = 16;

__global__ __launch_bounds__(256) void edge_mlp1(
    const float* __restrict__ feat1, const float* __restrict__ feat2,
    const float* __restrict__ W1a, const float* __restrict__ W1b, int nE)
{
    __shared__ __align__(16) float f1s[EB * IN1];
    __shared__ __align__(16) float f2s[EB * IN2];
    __shared__ __align__(16) float Ws1a[MID * IN1];
    __shared__ __align__(16) float Ws1b[MID * IN2];

    const int tid = threadIdx.x;
    for (int i = tid; i < MID * IN1; i += 256) Ws1a[i] = W1a[i];
    for (int i = tid; i < MID * IN2; i += 256) Ws1b[i] = W1b[i];
    __syncthreads();

    const int ntiles = nE / EB;
    const int k = tid & 63, g = tid >> 6;

    for (int t = blockIdx.x; t < ntiles; t += gridDim.x) {
        const int e0 = t * EB;
        for (int i = tid; i < EB * IN1; i += 256) f1s[i] = feat1[(size_t)e0 * IN1 + i];
        for (int i = tid; i < EB * IN2; i += 256) f2s[i] = feat2[(size_t)e0 * IN2 + i];
        __syncthreads();

        {
            const u64* wrow = (const u64*)(Ws1a + k * IN1);
            const u64* fr0 = (const u64*)(f1s + (g + 0)  * IN1);
            const u64* fr1 = (const u64*)(f1s + (g + 4)  * IN1);
            const u64* fr2 = (const u64*)(f1s + (g + 8)  * IN1);
            const u64* fr3 = (const u64*)(f1s + (g + 12) * IN1);
            u64 a0 = 0ull, a1 = 0ull, a2 = 0ull, a3 = 0ull;
#pragma unroll
            for (int jp = 0; jp < IN1 / 2; jp++) {
                u64 w = wrow[jp];
                FMA2(a0, fr0[jp], w, a0);
                FMA2(a1, fr1[jp], w, a1);
                FMA2(a2, fr2[jp], w, a2);
                FMA2(a3, fr3[jp], w, a3);
            }
            float lo, hi;
#pragma unroll
            for (int q = 0; q < 4; q++) {
                u64 a = (q == 0) ? a0 : (q == 1) ? a1 : (q == 2) ? a2 : a3;
                unpack2(a, lo, hi);
                float v = lo + hi;
                __nv_bfloat16 bh = __float2bfloat16_rn(v);
                __nv_bfloat16 bl = __float2bfloat16_rn(v - __bfloat162float(bh));
                u32 pk = (u32)__bfloat16_as_ushort(bh) | ((u32)__bfloat16_as_ushort(bl) << 16);
                g_m1p[(size_t)(e0 + g + 4 * q) * MID + k] = pk;
            }
        }
        {
            const u64* wrow = (const u64*)(Ws1b + k * IN2);
            const u64* fr0 = (const u64*)(f2s + (g + 0)  * IN2);
            const u64* fr1 = (const u64*)(f2s + (g + 4)  * IN2);
            const u64* fr2 = (const u64*)(f2s + (g + 8)  * IN2);
            const u64* fr3 = (const u64*)(f2s + (g + 12) * IN2);
            u64 a0 = 0ull, a1 = 0ull, a2 = 0ull, a3 = 0ull;
#pragma unroll
            for (int jp = 0; jp < IN2 / 2; jp++) {
                u64 w = wrow[jp];
                FMA2(a0, fr0[jp], w, a0);
                FMA2(a1, fr1[jp], w, a1);
                FMA2(a2, fr2[jp], w, a2);
                FMA2(a3, fr3[jp], w, a3);
            }
            float lo, hi;
#pragma unroll
            for (int q = 0; q < 4; q++) {
                u64 a = (q == 0) ? a0 : (q == 1) ? a1 : (q == 2) ? a2 : a3;
                unpack2(a, lo, hi);
                float v = lo + hi;
                __nv_bfloat16 bh = __float2bfloat16_rn(v);
                __nv_bfloat16 bl = __float2bfloat16_rn(v - __bfloat162float(bh));
                u32 pk = (u32)__bfloat16_as_ushort(bh) | ((u32)__bfloat16_as_ushort(bl) << 16);
                g_m2p[(size_t)(e0 + g + 4 * q) * MID + k] = pk;
            }
        }
        __syncthreads();
    }
}

// ---------------- edge stage 2: EB=32 tiles, 3 CTAs/SM ----------------
constexpr int XP = 132;
constexpr int EB2 = 32;

__global__ __launch_bounds__(256, 3) void edge_scatter(
    const int* __restrict__ ei,
    const float* __restrict__ W2a, const float* __restrict__ W2b,
    const float* __restrict__ xact,
    float* __restrict__ agg1, float* __restrict__ agg2, int nE)
{
    __shared__ __align__(16) float xs[2][EB2 * XP];

    const int tid  = threadIdx.x;
    const int warp = tid >> 5;
    const int lane = tid & 31;
    const int fg   = lane >> 2;
    const int ft   = lane & 3;

    // preload W2 B-fragments (hi/lo split) into registers
    u32 bhi[4][4][2], blo[4][4][2];
    {
        const float* W2 = (warp < 4) ? W2a : W2b;
        const int nbase = (warp & 3) * 32;
#pragma unroll
        for (int nt = 0; nt < 4; nt++) {
            const float* wrow = W2 + (size_t)(nbase + nt * 8 + fg) * MID;
#pragma unroll
            for (int kt = 0; kt < 4; kt++) {
#pragma unroll
                for (int half = 0; half < 2; half++) {
                    int k0 = kt * 16 + half * 8 + 2 * ft;
                    float w0 = wrow[k0], w1 = wrow[k0 + 1];
                    __nv_bfloat16 h0 = __float2bfloat16_rn(w0);
                    __nv_bfloat16 h1 = __float2bfloat16_rn(w1);
                    bhi[nt][kt][half] = pack_bf2(__bfloat162float(h0), __bfloat162float(h1));
                    blo[nt][kt][half] = pack_bf2(w0 - __bfloat162float(h0),
                                                 w1 - __bfloat162float(h1));
                }
            }
        }
    }

    const int ntiles = nE / EB2;

    auto do_gather = [&](int buf, int tt) {
        const int e0n = tt * EB2;
#pragma unroll
        for (int j = 0; j < 4; j++) {
            int idx = tid + 256 * j;
            int e = idx >> 5, h4 = (idx & 31) << 2;
            int src = __ldg(ei + e0n + e);
            float4 v = *(const float4*)(xact + (size_t)src * HH + h4);
            *(float4*)(&xs[buf][e * XP + h4]) = v;
        }
    };

    int t = blockIdx.x;
    if (t < ntiles) do_gather(0, t);

    int it = 0;
    for (; t < ntiles; t += gridDim.x, it ^= 1) {
        const int cur = it, nxt = it ^ 1;
        const int tn = t + gridDim.x;
        __syncthreads();                 // xs[cur] ready; prior compute done with xs[nxt]
        if (tn < ntiles) do_gather(nxt, tn);

        const u32* mpl = (warp < 4) ? g_m1p : g_m2p;
        float* agg = (warp < 4) ? agg1 : agg2;
        const int nbase = (warp & 3) * 32;

#pragma unroll
        for (int sb = 0; sb < 2; sb++) {
            const int e0 = t * EB2 + sb * 16;
            const int exs = sb * 16;

            float acc[4][4];
#pragma unroll
            for (int nt = 0; nt < 4; nt++)
#pragma unroll
                for (int q = 0; q < 4; q++) acc[nt][q] = 0.f;

            const u32* rowA = mpl + (size_t)(e0 + fg) * MID;
            const u32* rowB = mpl + (size_t)(e0 + fg + 8) * MID;
#pragma unroll
            for (int kt = 0; kt < 4; kt++) {
                const int k0 = kt * 16 + 2 * ft;
                uint2 vA0 = *(const uint2*)(rowA + k0);
                uint2 vA1 = *(const uint2*)(rowB + k0);
                uint2 vA2 = *(const uint2*)(rowA + k0 + 8);
                uint2 vA3 = *(const uint2*)(rowB + k0 + 8);
                u32 ah0 = prmt(vA0.x, vA0.y, 0x5410), al0 = prmt(vA0.x, vA0.y, 0x7632);
                u32 ah1 = prmt(vA1.x, vA1.y, 0x5410), al1 = prmt(vA1.x, vA1.y, 0x7632);
                u32 ah2 = prmt(vA2.x, vA2.y, 0x5410), al2 = prmt(vA2.x, vA2.y, 0x7632);
                u32 ah3 = prmt(vA3.x, vA3.y, 0x5410), al3 = prmt(vA3.x, vA3.y, 0x7632);
#pragma unroll
                for (int nt = 0; nt < 4; nt++) {
                    MMA16816(acc[nt][0], acc[nt][1], acc[nt][2], acc[nt][3],
                             ah0, ah1, ah2, ah3, bhi[nt][kt][0], bhi[nt][kt][1]);
                    MMA16816(acc[nt][0], acc[nt][1], acc[nt][2], acc[nt][3],
                             al0, al1, al2, al3, bhi[nt][kt][0], bhi[nt][kt][1]);
                    MMA16816(acc[nt][0], acc[nt][1], acc[nt][2], acc[nt][3],
                             ah0, ah1, ah2, ah3, blo[nt][kt][0], blo[nt][kt][1]);
                }
            }

            const int dA = __ldg(ei + nE + e0 + fg);
            const int dB = __ldg(ei + nE + e0 + fg + 8);
#pragma unroll
            for (int nt = 0; nt < 4; nt++) {
                int ch = nbase + nt * 8 + 2 * ft;
                float2 xga = *(const float2*)(&xs[cur][(exs + fg) * XP + ch]);
                float2 xgb = *(const float2*)(&xs[cur][(exs + fg + 8) * XP + ch]);
                red_add_v2(agg + (size_t)dA * HH + ch, acc[nt][0] * xga.x, acc[nt][1] * xga.y);
                red_add_v2(agg + (size_t)dB * HH + ch, acc[nt][2] * xgb.x, acc[nt][3] * xgb.y);
            }
        }
    }
}

// ---------------- GraphNorm ----------------
__global__ void norm_sum(const float* __restrict__ hin, const int* __restrict__ batch) {
    int idx = blockIdx.x * blockDim.x + threadIdx.x;
    if (idx >= NN * 32) return;
    int n = idx >> 5, c4 = (idx & 31) << 2;
    int b = batch[n];
    float4 v = *(const float4*)(hin + (size_t)n * HH + c4);
    red_add_v4(&g_mean[b * HH + c4], v);
    if (c4 == 0) atomicAdd(&g_cnt[b], 1.f);
}

__global__ void norm_center(const float* __restrict__ hin, const int* __restrict__ batch,
                            const float* __restrict__ ms, float* __restrict__ hc_out) {
    int idx = blockIdx.x * blockDim.x + threadIdx.x;
    if (idx >= NN * 32) return;
    int n = idx >> 5, c4 = (idx & 31) << 2;
    int b = batch[n];
    float rcnt = 1.f / fmaxf(g_cnt[b], 1.f);
    float4 hv = *(const float4*)(hin + (size_t)n * HH + c4);
    float4 mv = *(const float4*)(&g_mean[b * HH + c4]);
    float4 msv = *(const float4*)(ms + c4);
    float4 hc;
    hc.x = hv.x - mv.x * rcnt * msv.x;
    hc.y = hv.y - mv.y * rcnt * msv.y;
    hc.z = hv.z - mv.z * rcnt * msv.z;
    hc.w = hv.w - mv.w * rcnt * msv.w;
    *(float4*)(hc_out + (size_t)n * HH + c4) = hc;
    float4 sq = make_float4(hc.x * hc.x, hc.y * hc.y, hc.z * hc.z, hc.w * hc.w);
    red_add_v4(&g_var[b * HH + c4], sq);
}

__global__ void norm_apply(const float* __restrict__ hc, const int* __restrict__ batch,
                           const float* __restrict__ w, const float* __restrict__ b_,
                           float* __restrict__ out) {
    int idx = blockIdx.x * blockDim.x + threadIdx.x;
    if (idx >= NN * 32) return;
    int n = idx >> 5, c4 = (idx & 31) << 2;
    int b = batch[n];
    float rcnt = 1.f / fmaxf(g_cnt[b], 1.f);
    float4 hv = *(const float4*)(hc + (size_t)n * HH + c4);
    float4 vv = *(const float4*)(&g_var[b * HH + c4]);
    float4 wv = *(const float4*)(w + c4);
    float4 bv = *(const float4*)(b_ + c4);
    float4 o;
    o.x = wv.x * hv.x * rsqrtf(vv.x * rcnt + 1e-5f) + bv.x;
    o.y = wv.y * hv.y * rsqrtf(vv.y * rcnt + 1e-5f) + bv.y;
    o.z = wv.z * hv.z * rsqrtf(vv.z * rcnt + 1e-5f) + bv.z;
    o.w = wv.w * hv.w * rsqrtf(vv.w * rcnt + 1e-5f) + bv.w;
    *(float4*)(out + (size_t)n * HH + c4) = o;
}

// ---------------- launch ----------------
extern "C" void kernel_launch(void* const* d_in, const int* in_sizes, int n_in,
                              void* d_out, int out_size)
{
    const float* x        = (const float*)d_in[0];
    const float* feature1 = (const float*)d_in[1];
    const float* feature2 = (const float*)d_in[2];
    const int*   ei       = (const int*)d_in[3];
    const int*   batch    = (const int*)d_in[4];
    const float* lin_W    = (const float*)d_in[5];
    const float* lin_b    = (const float*)d_in[6];
    const float* f1_W1    = (const float*)d_in[7];
    const float* f1_W2    = (const float*)d_in[8];
    const float* f2_W1    = (const float*)d_in[9];
    const float* f2_W2    = (const float*)d_in[10];
    const float* c1_rel_W = (const float*)d_in[11];
    const float* c1_rel_b = (const float*)d_in[12];
    const float* c1_rt_W  = (const float*)d_in[13];
    const float* c2_rel_W = (const float*)d_in[14];
    const float* c2_rel_b = (const float*)d_in[15];
    const float* c2_rt_W  = (const float*)d_in[16];
    const float* lin1_W   = (const float*)d_in[17];
    const float* lin1_b   = (const float*)d_in[18];
    const float* lin2_W   = (const float*)d_in[19];
    const float* lin2_b   = (const float*)d_in[20];
    const float* cat_W    = (const float*)d_in[21];
    const float* cat_b    = (const float*)d_in[22];
    const float* norm_w   = (const float*)d_in[23];
    const float* norm_b   = (const float*)d_in[24];
    const float* norm_ms  = (const float*)d_in[25];
    const float* lins_W   = (const float*)d_in[26];
    const float* lins_b   = (const float*)d_in[27];
    const float* final_W  = (const float*)d_in[28];
    const float* final_b  = (const float*)d_in[29];

    const int nN = in_sizes[0] / HH;
    const int nE = in_sizes[3] / 2;

    float *pxact, *pagg1, *pagg2, *pA, *pB, *pC;
    cudaGetSymbolAddress((void**)&pxact, g_xact);
    cudaGetSymbolAddress((void**)&pagg1, g_agg1);
    cudaGetSymbolAddress((void**)&pagg2, g_agg2);
    cudaGetSymbolAddress((void**)&pA, g_A);
    cudaGetSymbolAddress((void**)&pB, g_B);
    cudaGetSymbolAddress((void**)&pC, g_C);

    cudaFuncSetAttribute(gemm_p<false, true,  true,  false>, cudaFuncAttributeMaxDynamicSharedMemorySize, GEMM_SMEM);
    cudaFuncSetAttribute(gemm_p<false, false, false, false>, cudaFuncAttributeMaxDynamicSharedMemorySize, GEMM_SMEM);
    cudaFuncSetAttribute(gemm_p<true,  true,  false, false>, cudaFuncAttributeMaxDynamicSharedMemorySize, GEMM_SMEM);
    cudaFuncSetAttribute(gemm_p<true,  true,  false, true >, cudaFuncAttributeMaxDynamicSharedMemorySize, GEMM_SMEM);
    cudaFuncSetAttribute(gemm_p<false, true,  true,  true >, cudaFuncAttributeMaxDynamicSharedMemorySize, GEMM_SMEM);
    cudaFuncSetAttribute(gemm_p<false, true,  false, false>, cudaFuncAttributeMaxDynamicSharedMemorySize, GEMM_SMEM);

    const int PG = 296;   // persistent grid (2 CTAs/SM)

    WPack wp;
    wp.w[0]  = { lin_W, HH };
    wp.w[1]  = { c1_rel_W, HH };
    wp.w[2]  = { c1_rt_W, HH };
    wp.w[3]  = { lin1_W, HH };
    wp.w[4]  = { c2_rel_W, HH };
    wp.w[5]  = { c2_rt_W, HH };
    wp.w[6]  = { lin2_W, HH };
    wp.w[7]  = { cat_W, 2 * HH };
    wp.w[8]  = { cat_W + HH, 2 * HH };
    wp.w[9]  = { lins_W + 0 * HH * HH, HH };
    wp.w[10] = { lins_W + 1 * HH * HH, HH };
    wp.w[11] = { lins_W + 2 * HH * HH, HH };
    wp.w[12] = { final_W, HH };

    zero_kernel<<<(NN * HH + 255) / 256, 256>>>();
    prep_weights<<<(13 * 16384 + 255) / 256, 256>>>(wp);

    // edge stage 1 (independent of xact)
    edge_mlp1<<<592, 256>>>(feature1, feature2, f1_W1, f2_W1, nE);

    // x_act = swish(x @ lin_W^T + lin_b)
    gemm_p<false, true, true, false><<<PG, 256, GEMM_SMEM>>>(x, 0, lin_b, nullptr, pxact, nN);

    // edge stage 2
    edge_scatter<<<444, 256>>>(ei, f1_W2, f2_W2, pxact, pagg1, pagg2, nE);

    // t1 = agg1@rel1 + xact@root1 + b  -> pA
    gemm_p<false, false, false, false><<<PG, 256, GEMM_SMEM>>>(pagg1, 1, nullptr, nullptr, pA, nN);
    gemm_p<true,  true,  false, false><<<PG, 256, GEMM_SMEM>>>(pxact, 2, c1_rel_b, nullptr, pA, nN);
    // h1 = swish(t1@lin1 + b)          -> pB
    gemm_p<false, true,  true,  false><<<PG, 256, GEMM_SMEM>>>(pA, 3, lin1_b, nullptr, pB, nN);
    // t2 -> pA
    gemm_p<false, false, false, false><<<PG, 256, GEMM_SMEM>>>(pagg2, 4, nullptr, nullptr, pA, nN);
    gemm_p<true,  true,  false, false><<<PG, 256, GEMM_SMEM>>>(pxact, 5, c2_rel_b, nullptr, pA, nN);
    // h2 = swish(t2@lin2 + b)          -> pC
    gemm_p<false, true,  true,  false><<<PG, 256, GEMM_SMEM>>>(pA, 6, lin2_b, nullptr, pC, nN);
    // h = h1@cat1 + h2@cat2 + cat_b + xact -> pA
    gemm_p<false, false, false, false><<<PG, 256, GEMM_SMEM>>>(pB, 7, nullptr, nullptr, pA, nN);
    gemm_p<true,  true,  false, true ><<<PG, 256, GEMM_SMEM>>>(pC, 8, cat_b, pxact, pA, nN);
    // residual swish layers
    gemm_p<false, true,  true,  true ><<<PG, 256, GEMM_SMEM>>>(pA, 9,  lins_b + 0 * HH, pA, pB, nN);
    gemm_p<false, true,  true,  true ><<<PG, 256, GEMM_SMEM>>>(pB, 10, lins_b + 1 * HH, pB, pA, nN);
    gemm_p<false, true,  true,  true ><<<PG, 256, GEMM_SMEM>>>(pA, 11, lins_b + 2 * HH, pA, pB, nN);

    const int n32b = (NN * 32 + 255) / 256;
    norm_sum<<<n32b, 256>>>(pB, batch);
    norm_center<<<n32b, 256>>>(pB, batch, norm_ms, pC);
    norm_apply<<<n32b, 256>>>(pC, batch, norm_w, norm_b, pA);

    gemm_p<false, true, false, false><<<PG, 256, GEMM_SMEM>>>(pA, 12, final_b, nullptr, (float*)d_out, nN);
}

// round 11
// speedup vs baseline: 1.7032x; 1.0147x over previous
#include <cuda_runtime.h>
#include <cuda_bf16.h>

#define NN 50000
#define EE 1000000
#define BB 512
#define HH 128
#define MID 64
#define IN1 54
#define IN2 18

typedef unsigned long long u64;
typedef unsigned int u32;

#define FMA2(d, a, b, c) asm("fma.rn.f32x2 %0, %1, %2, %3;" : "=l"(d) : "l"(a), "l"(b), "l"(c))

__device__ __forceinline__ u64 pack2(float lo, float hi) {
    u64 r; asm("mov.b64 %0, {%1, %2};" : "=l"(r) : "f"(lo), "f"(hi)); return r;
}
__device__ __forceinline__ void unpack2(u64 v, float& lo, float& hi) {
    asm("mov.b64 {%0, %1}, %2;" : "=f"(lo), "=f"(hi) : "l"(v));
}
__device__ __forceinline__ void red_add_v4(float* addr, float4 v) {
    asm volatile("red.global.add.v4.f32 [%0], {%1, %2, %3, %4};"
                 :: "l"(addr), "f"(v.x), "f"(v.y), "f"(v.z), "f"(v.w) : "memory");
}
__device__ __forceinline__ void red_add_v2(float* addr, float a, float b) {
    asm volatile("red.global.add.v2.f32 [%0], {%1, %2};"
                 :: "l"(addr), "f"(a), "f"(b) : "memory");
}
__device__ __forceinline__ void red_add_f(float* addr, float v) {
    asm volatile("red.global.add.f32 [%0], %1;" :: "l"(addr), "f"(v) : "memory");
}
__device__ __forceinline__ u32 prmt(u32 a, u32 b, u32 s) {
    u32 d; asm("prmt.b32 %0, %1, %2, %3;" : "=r"(d) : "r"(a), "r"(b), "r"(s)); return d;
}
#define MMA16816(c0, c1, c2, c3, a0, a1, a2, a3, b0, b1) \
    asm volatile("mma.sync.aligned.m16n8k16.row.col.f32.bf16.bf16.f32 " \
                 "{%0,%1,%2,%3}, {%4,%5,%6,%7}, {%8,%9}, {%0,%1,%2,%3};" \
                 : "+f"(c0), "+f"(c1), "+f"(c2), "+f"(c3) \
                 : "r"(a0), "r"(a1), "r"(a2), "r"(a3), "r"(b0), "r"(b1))

__device__ __forceinline__ u32 pack_bf2(float e0, float e1) {
    __nv_bfloat162 h = __floats2bfloat162_rn(e0, e1);
    return *(u32*)&h;
}

// ---------------- scratch ----------------
__device__ float g_xact[NN * HH];
__device__ float g_agg1[NN * HH];
__device__ float g_agg2[NN * HH];
__device__ float g_A[NN * HH];
__device__ float g_B[NN * HH];
__device__ float g_C[NN * HH];
__device__ float g_mean[BB * HH];
__device__ float g_var[BB * HH];
__device__ float g_cnt[BB];
__device__ u32 g_m1p[EE * MID];
__device__ u32 g_m2p[EE * MID];
// preconverted node-GEMM weights: 13 matrices of 128x128, bf16 hi/lo planes (flat [c][k])
__device__ __nv_bfloat16 g_Wh[13 * 128 * 128];
__device__ __nv_bfloat16 g_Wl[13 * 128 * 128];

__global__ void zero_kernel() {
    int idx = blockIdx.x * blockDim.x + threadIdx.x;
    if (idx < NN * HH) { g_agg1[idx] = 0.f; g_agg2[idx] = 0.f; }
    if (idx < BB * HH) { g_mean[idx] = 0.f; g_var[idx] = 0.f; }
    if (idx < BB) g_cnt[idx] = 0.f;
}

// ---------------- weight prep: fp32 -> bf16 hi/lo planes ----------------
struct WSrc { const float* p; int ldw; };
struct WPack { WSrc w[13]; };

__global__ void prep_weights(WPack wp) {
    int idx = blockIdx.x * blockDim.x + threadIdx.x;
    if (idx >= 13 * 16384) return;
    int m = idx >> 14, r = idx & 16383, c = r >> 7, k = r & 127;
    float v = wp.w[m].p[(size_t)c * wp.w[m].ldw + k];
    __nv_bfloat16 h = __float2bfloat16_rn(v);
    g_Wh[idx] = h;
    g_Wl[idx] = __float2bfloat16_rn(v - __bfloat162float(h));
}

// ---------------- persistent node GEMM via split-bf16 HMMA ----------------
// out [opt +=prev] = A@W [+ bias [+ swish] [+ resid]]; K=128, 128 cols.
// FUSE: 0 = none, 1 = RED mean/cnt of stored values (GraphNorm sum),
//       2 = A is hc: apply GraphNorm (w*hc*rsqrt(var/cnt+eps)+b) during A-load.
constexpr int GP = 136;   // bf16 pitch (conflict-free fragment LDS)
constexpr int GEMM_SMEM = (64 + 64 + 128 + 128) * GP * 2;   // Ahi,Alo,Whi,Wlo

template <bool ACCUM, bool EPI, bool SWISH, bool RESID, int FUSE>
__global__ __launch_bounds__(256, 2) void gemm_p(
    const float* __restrict__ A, int widx,
    const float* __restrict__ bias, const float* __restrict__ resid,
    float* __restrict__ out, int nrows,
    const int* __restrict__ batch, const float* __restrict__ nw, const float* __restrict__ nb)
{
    extern __shared__ char smc[];
    __nv_bfloat16* Ahi = (__nv_bfloat16*)(smc);
    __nv_bfloat16* Alo = (__nv_bfloat16*)(smc + 64 * GP * 2);
    __nv_bfloat16* Whi = (__nv_bfloat16*)(smc + 128 * GP * 2);
    __nv_bfloat16* Wlo = (__nv_bfloat16*)(smc + 256 * GP * 2);

    const int tid  = threadIdx.x;
    const int warp = tid >> 5;
    const int lane = tid & 31;
    const int fg   = lane >> 2;
    const int ft   = lane & 3;
    const int rg   = warp & 3;
    const int chf  = warp >> 2;

    // ---- W planes: load once ----
    {
        const u32* srcH = (const u32*)(g_Wh + (size_t)widx * 16384);
        const u32* srcL = (const u32*)(g_Wl + (size_t)widx * 16384);
        for (int i = tid; i < 128 * 64; i += 256) {
            int c = i >> 6, kp = i & 63;
            ((u32*)Whi)[c * 68 + kp] = srcH[i];
            ((u32*)Wlo)[c * 68 + kp] = srcL[i];
        }
    }

    const int ntiles = (nrows + 63) >> 6;

    float4 pre[8];
    auto ldA = [&](int tt) {
#pragma unroll
        for (int j = 0; j < 8; j++) {
            int idx = tid + 256 * j;
            int r = idx >> 5, kp4 = idx & 31;
            int gr = (tt << 6) + r;
            float4 v = (gr < nrows) ? *(const float4*)(A + (size_t)gr * 128 + 4 * kp4)
                                    : make_float4(0.f, 0.f, 0.f, 0.f);
            if (FUSE == 2) {
                if (gr < nrows) {
                    int b = __ldg(batch + gr);
                    float rcnt = 1.f / fmaxf(g_cnt[b], 1.f);
                    float4 vv = *(const float4*)(&g_var[b * HH + 4 * kp4]);
                    float4 w4 = *(const float4*)(nw + 4 * kp4);
                    float4 b4 = *(const float4*)(nb + 4 * kp4);
                    v.x = w4.x * v.x * rsqrtf(vv.x * rcnt + 1e-5f) + b4.x;
                    v.y = w4.y * v.y * rsqrtf(vv.y * rcnt + 1e-5f) + b4.y;
                    v.z = w4.z * v.z * rsqrtf(vv.z * rcnt + 1e-5f) + b4.z;
                    v.w = w4.w * v.w * rsqrtf(vv.w * rcnt + 1e-5f) + b4.w;
                }
            }
            pre[j] = v;
        }
    };

    int t = blockIdx.x;
    if (t < ntiles) ldA(t);

    for (; t < ntiles; t += gridDim.x) {
        const int r0 = t << 6;
        __syncthreads();   // previous tile's MMA readers done (also covers W fill on iter 0)

        // ---- convert + store prefetched A tile ----
#pragma unroll
        for (int j = 0; j < 8; j++) {
            int idx = tid + 256 * j;
            int r = idx >> 5, kp4 = idx & 31;
            float4 v = pre[j];
            __nv_bfloat162 h01 = __floats2bfloat162_rn(v.x, v.y);
            __nv_bfloat162 h23 = __floats2bfloat162_rn(v.z, v.w);
            __nv_bfloat162 l01 = __floats2bfloat162_rn(v.x - __bfloat162float(h01.x),
                                                       v.y - __bfloat162float(h01.y));
            __nv_bfloat162 l23 = __floats2bfloat162_rn(v.z - __bfloat162float(h23.x),
                                                       v.w - __bfloat162float(h23.y));
            ((u64*)(Ahi + r * GP))[kp4] = (u64)(*(u32*)&h01) | ((u64)(*(u32*)&h23) << 32);
            ((u64*)(Alo + r * GP))[kp4] = (u64)(*(u32*)&l01) | ((u64)(*(u32*)&l23) << 32);
        }
        __syncthreads();

        // prefetch next tile's A (overlaps MMA loop)
        const int tn = t + gridDim.x;
        if (tn < ntiles) ldA(tn);

        float acc[8][4];
#pragma unroll
        for (int nt = 0; nt < 8; nt++)
#pragma unroll
            for (int q = 0; q < 4; q++) acc[nt][q] = 0.f;

        const int m0 = rg * 16 + fg;
#pragma unroll
        for (int kstep = 0; kstep < 8; kstep++) {
            const int k0 = kstep * 16 + 2 * ft;
            u32 ah0 = *(const u32*)(Ahi + m0 * GP + k0);
            u32 ah1 = *(const u32*)(Ahi + (m0 + 8) * GP + k0);
            u32 ah2 = *(const u32*)(Ahi + m0 * GP + k0 + 8);
            u32 ah3 = *(const u32*)(Ahi + (m0 + 8) * GP + k0 + 8);
            u32 al0 = *(const u32*)(Alo + m0 * GP + k0);
            u32 al1 = *(const u32*)(Alo + (m0 + 8) * GP + k0);
            u32 al2 = *(const u32*)(Alo + m0 * GP + k0 + 8);
            u32 al3 = *(const u32*)(Alo + (m0 + 8) * GP + k0 + 8);
#pragma unroll
            for (int nt = 0; nt < 8; nt++) {
                const int c = chf * 64 + nt * 8 + fg;
                u32 bh0 = *(const u32*)(Whi + c * GP + k0);
                u32 bh1 = *(const u32*)(Whi + c * GP + k0 + 8);
                u32 bl0 = *(const u32*)(Wlo + c * GP + k0);
                u32 bl1 = *(const u32*)(Wlo + c * GP + k0 + 8);
                MMA16816(acc[nt][0], acc[nt][1], acc[nt][2], acc[nt][3],
                         ah0, ah1, ah2, ah3, bh0, bh1);
                MMA16816(acc[nt][0], acc[nt][1], acc[nt][2], acc[nt][3],
                         al0, al1, al2, al3, bh0, bh1);
                MMA16816(acc[nt][0], acc[nt][1], acc[nt][2], acc[nt][3],
                         ah0, ah1, ah2, ah3, bl0, bl1);
            }
        }

        // ---- epilogue ----
        const int rA = r0 + m0, rBr = r0 + m0 + 8;
        int bA = 0, bB = 0;
        if (FUSE == 1) {
            if (rA < nrows)  bA = __ldg(batch + rA);
            if (rBr < nrows) bB = __ldg(batch + rBr);
        }
#pragma unroll
        for (int nt = 0; nt < 8; nt++) {
            const int c = chf * 64 + nt * 8 + 2 * ft;
            float v0 = acc[nt][0], v1 = acc[nt][1];
            float v2 = acc[nt][2], v3 = acc[nt][3];
            if (EPI) {
                float2 bv = *(const float2*)(bias + c);
                v0 += bv.x; v1 += bv.y; v2 += bv.x; v3 += bv.y;
            }
            if (rA < nrows) {
                float* orow = out + (size_t)rA * 128 + c;
                if (ACCUM) { float2 pv = *(const float2*)orow; v0 += pv.x; v1 += pv.y; }
                if (SWISH) {
                    v0 = v0 / (1.f + __expf(-v0));
                    v1 = v1 / (1.f + __expf(-v1));
                }
                if (RESID) {
                    float2 rv = *(const float2*)(resid + (size_t)rA * 128 + c);
                    v0 += rv.x; v1 += rv.y;
                }
                *(float2*)orow = make_float2(v0, v1);
                if (FUSE == 1) red_add_v2(&g_mean[bA * HH + c], v0, v1);
            }
            if (rBr < nrows) {
                float* orow = out + (size_t)rBr * 128 + c;
                if (ACCUM) { float2 pv = *(const float2*)orow; v2 += pv.x; v3 += pv.y; }
                if (SWISH) {
                    v2 = v2 / (1.f + __expf(-v2));
                    v3 = v3 / (1.f + __expf(-v3));
                }
                if (RESID) {
                    float2 rv = *(const float2*)(resid + (size_t)rBr * 128 + c);
                    v2 += rv.x; v3 += rv.y;
                }
                *(float2*)orow = make_float2(v2, v3);
                if (FUSE == 1) red_add_v2(&g_mean[bB * HH + c], v2, v3);
            }
        }
        if (FUSE == 1 && chf == 0 && ft == 0) {
            if (rA < nrows)  red_add_f(&g_cnt[bA], 1.f);
            if (rBr < nrows) red_add_f(&g_cnt[bB], 1.f);
        }
    }
}

// ---------------- edge stage 1 (unchanged) ----------------
constexpr int EB = 16;

__global__ __launch_bounds__(256) void edge_mlp1(
    const float* __restrict__ feat1, const float* __restrict__ feat2,
    const float* __restrict__ W1a, const float* __restrict__ W1b, int nE)
{
    __shared__ __align__(16) float f1s[EB * IN1];
    __shared__ __align__(16) float f2s[EB * IN2];
    __shared__ __align__(16) float Ws1a[MID * IN1];
    __shared__ __align__(16) float Ws1b[MID * IN2];

    const int tid = threadIdx.x;
    for (int i = tid; i < MID * IN1; i += 256) Ws1a[i] = W1a[i];
    for (int i = tid; i < MID * IN2; i += 256) Ws1b[i] = W1b[i];
    __syncthreads();

    const int ntiles = nE / EB;
    const int k = tid & 63, g = tid >> 6;

    for (int t = blockIdx.x; t < ntiles; t += gridDim.x) {
        const int e0 = t * EB;
        for (int i = tid; i < EB * IN1; i += 256) f1s[i] = feat1[(size_t)e0 * IN1 + i];
        for (int i = tid; i < EB * IN2; i += 256) f2s[i] = feat2[(size_t)e0 * IN2 + i];
        __syncthreads();

        {
            const u64* wrow = (const u64*)(Ws1a + k * IN1);
            const u64* fr0 = (const u64*)(f1s + (g + 0)  * IN1);
            const u64* fr1 = (const u64*)(f1s + (g + 4)  * IN1);
            const u64* fr2 = (const u64*)(f1s + (g + 8)  * IN1);
            const u64* fr3 = (const u64*)(f1s + (g + 12) * IN1);
            u64 a0 = 0ull, a1 = 0ull, a2 = 0ull, a3 = 0ull;
#pragma unroll
            for (int jp = 0; jp < IN1 / 2; jp++) {
                u64 w = wrow[jp];
                FMA2(a0, fr0[jp], w, a0);
                FMA2(a1, fr1[jp], w, a1);
                FMA2(a2, fr2[jp], w, a2);
                FMA2(a3, fr3[jp], w, a3);
            }
            float lo, hi;
#pragma unroll
            for (int q = 0; q < 4; q++) {
                u64 a = (q == 0) ? a0 : (q == 1) ? a1 : (q == 2) ? a2 : a3;
                unpack2(a, lo, hi);
                float v = lo + hi;
                __nv_bfloat16 bh = __float2bfloat16_rn(v);
                __nv_bfloat16 bl = __float2bfloat16_rn(v - __bfloat162float(bh));
                u32 pk = (u32)__bfloat16_as_ushort(bh) | ((u32)__bfloat16_as_ushort(bl) << 16);
                g_m1p[(size_t)(e0 + g + 4 * q) * MID + k] = pk;
            }
        }
        {
            const u64* wrow = (const u64*)(Ws1b + k * IN2);
            const u64* fr0 = (const u64*)(f2s + (g + 0)  * IN2);
            const u64* fr1 = (const u64*)(f2s + (g + 4)  * IN2);
            const u64* fr2 = (const u64*)(f2s + (g + 8)  * IN2);
            const u64* fr3 = (const u64*)(f2s + (g + 12) * IN2);
            u64 a0 = 0ull, a1 = 0ull, a2 = 0ull, a3 = 0ull;
#pragma unroll
            for (int jp = 0; jp < IN2 / 2; jp++) {
                u64 w = wrow[jp];
                FMA2(a0, fr0[jp], w, a0);
                FMA2(a1, fr1[jp], w, a1);
                FMA2(a2, fr2[jp], w, a2);
                FMA2(a3, fr3[jp], w, a3);
            }
            float lo, hi;
#pragma unroll
            for (int q = 0; q < 4; q++) {
                u64 a = (q == 0) ? a0 : (q == 1) ? a1 : (q == 2) ? a2 : a3;
                unpack2(a, lo, hi);
                float v = lo + hi;
                __nv_bfloat16 bh = __float2bfloat16_rn(v);
                __nv_bfloat16 bl = __float2bfloat16_rn(v - __bfloat162float(bh));
                u32 pk = (u32)__bfloat16_as_ushort(bh) | ((u32)__bfloat16_as_ushort(bl) << 16);
                g_m2p[(size_t)(e0 + g + 4 * q) * MID + k] = pk;
            }
        }
        __syncthreads();
    }
}

// ---------------- edge stage 2 (unchanged from R10) ----------------
constexpr int XP = 132;
constexpr int EB2 = 32;

__global__ __launch_bounds__(256, 3) void edge_scatter(
    const int* __restrict__ ei,
    const float* __restrict__ W2a, const float* __restrict__ W2b,
    const float* __restrict__ xact,
    float* __restrict__ agg1, float* __restrict__ agg2, int nE)
{
    __shared__ __align__(16) float xs[2][EB2 * XP];

    const int tid  = threadIdx.x;
    const int warp = tid >> 5;
    const int lane = tid & 31;
    const int fg   = lane >> 2;
    const int ft   = lane & 3;

    u32 bhi[4][4][2], blo[4][4][2];
    {
        const float* W2 = (warp < 4) ? W2a : W2b;
        const int nbase = (warp & 3) * 32;
#pragma unroll
        for (int nt = 0; nt < 4; nt++) {
            const float* wrow = W2 + (size_t)(nbase + nt * 8 + fg) * MID;
#pragma unroll
            for (int kt = 0; kt < 4; kt++) {
#pragma unroll
                for (int half = 0; half < 2; half++) {
                    int k0 = kt * 16 + half * 8 + 2 * ft;
                    float w0 = wrow[k0], w1 = wrow[k0 + 1];
                    __nv_bfloat16 h0 = __float2bfloat16_rn(w0);
                    __nv_bfloat16 h1 = __float2bfloat16_rn(w1);
                    bhi[nt][kt][half] = pack_bf2(__bfloat162float(h0), __bfloat162float(h1));
                    blo[nt][kt][half] = pack_bf2(w0 - __bfloat162float(h0),
                                                 w1 - __bfloat162float(h1));
                }
            }
        }
    }

    const int ntiles = nE / EB2;

    auto do_gather = [&](int buf, int tt) {
        const int e0n = tt * EB2;
#pragma unroll
        for (int j = 0; j < 4; j++) {
            int idx = tid + 256 * j;
            int e = idx >> 5, h4 = (idx & 31) << 2;
            int src = __ldg(ei + e0n + e);
            float4 v = *(const float4*)(xact + (size_t)src * HH + h4);
            *(float4*)(&xs[buf][e * XP + h4]) = v;
        }
    };

    int t = blockIdx.x;
    if (t < ntiles) do_gather(0, t);

    int it = 0;
    for (; t < ntiles; t += gridDim.x, it ^= 1) {
        const int cur = it, nxt = it ^ 1;
        const int tn = t + gridDim.x;
        __syncthreads();
        if (tn < ntiles) do_gather(nxt, tn);

        const u32* mpl = (warp < 4) ? g_m1p : g_m2p;
        float* agg = (warp < 4) ? agg1 : agg2;
        const int nbase = (warp & 3) * 32;

#pragma unroll
        for (int sb = 0; sb < 2; sb++) {
            const int e0 = t * EB2 + sb * 16;
            const int exs = sb * 16;

            float acc[4][4];
#pragma unroll
            for (int nt = 0; nt < 4; nt++)
#pragma unroll
                for (int q = 0; q < 4; q++) acc[nt][q] = 0.f;

            const u32* rowA = mpl + (size_t)(e0 + fg) * MID;
            const u32* rowB = mpl + (size_t)(e0 + fg + 8) * MID;
#pragma unroll
            for (int kt = 0; kt < 4; kt++) {
                const int k0 = kt * 16 + 2 * ft;
                uint2 vA0 = *(const uint2*)(rowA + k0);
                uint2 vA1 = *(const uint2*)(rowB + k0);
                uint2 vA2 = *(const uint2*)(rowA + k0 + 8);
                uint2 vA3 = *(const uint2*)(rowB + k0 + 8);
                u32 ah0 = prmt(vA0.x, vA0.y, 0x5410), al0 = prmt(vA0.x, vA0.y, 0x7632);
                u32 ah1 = prmt(vA1.x, vA1.y, 0x5410), al1 = prmt(vA1.x, vA1.y, 0x7632);
                u32 ah2 = prmt(vA2.x, vA2.y, 0x5410), al2 = prmt(vA2.x, vA2.y, 0x7632);
                u32 ah3 = prmt(vA3.x, vA3.y, 0x5410), al3 = prmt(vA3.x, vA3.y, 0x7632);
#pragma unroll
                for (int nt = 0; nt < 4; nt++) {
                    MMA16816(acc[nt][0], acc[nt][1], acc[nt][2], acc[nt][3],
                             ah0, ah1, ah2, ah3, bhi[nt][kt][0], bhi[nt][kt][1]);
                    MMA16816(acc[nt][0], acc[nt][1], acc[nt][2], acc[nt][3],
                             al0, al1, al2, al3, bhi[nt][kt][0], bhi[nt][kt][1]);
                    MMA16816(acc[nt][0], acc[nt][1], acc[nt][2], acc[nt][3],
                             ah0, ah1, ah2, ah3, blo[nt][kt][0], blo[nt][kt][1]);
                }
            }

            const int dA = __ldg(ei + nE + e0 + fg);
            const int dB = __ldg(ei + nE + e0 + fg + 8);
#pragma unroll
            for (int nt = 0; nt < 4; nt++) {
                int ch = nbase + nt * 8 + 2 * ft;
                float2 xga = *(const float2*)(&xs[cur][(exs + fg) * XP + ch]);
                float2 xgb = *(const float2*)(&xs[cur][(exs + fg + 8) * XP + ch]);
                red_add_v2(agg + (size_t)dA * HH + ch, acc[nt][0] * xga.x, acc[nt][1] * xga.y);
                red_add_v2(agg + (size_t)dB * HH + ch, acc[nt][2] * xgb.x, acc[nt][3] * xgb.y);
            }
        }
    }
}

// ---------------- GraphNorm center (sum fused into gemm; apply fused into gemm) ----------------
__global__ void norm_center(const float* __restrict__ hin, const int* __restrict__ batch,
                            const float* __restrict__ ms, float* __restrict__ hc_out) {
    int idx = blockIdx.x * blockDim.x + threadIdx.x;
    if (idx >= NN * 32) return;
    int n = idx >> 5, c4 = (idx & 31) << 2;
    int b = batch[n];
    float rcnt = 1.f / fmaxf(g_cnt[b], 1.f);
    float4 hv = *(const float4*)(hin + (size_t)n * HH + c4);
    float4 mv = *(const float4*)(&g_mean[b * HH + c4]);
    float4 msv = *(const float4*)(ms + c4);
    float4 hc;
    hc.x = hv.x - mv.x * rcnt * msv.x;
    hc.y = hv.y - mv.y * rcnt * msv.y;
    hc.z = hv.z - mv.z * rcnt * msv.z;
    hc.w = hv.w - mv.w * rcnt * msv.w;
    *(float4*)(hc_out + (size_t)n * HH + c4) = hc;
    float4 sq = make_float4(hc.x * hc.x, hc.y * hc.y, hc.z * hc.z, hc.w * hc.w);
    red_add_v4(&g_var[b * HH + c4], sq);
}

// ---------------- launch ----------------
extern "C" void kernel_launch(void* const* d_in, const int* in_sizes, int n_in,
                              void* d_out, int out_size)
{
    const float* x        = (const float*)d_in[0];
    const float* feature1 = (const float*)d_in[1];
    const float* feature2 = (const float*)d_in[2];
    const int*   ei       = (const int*)d_in[3];
    const int*   batch    = (const int*)d_in[4];
    const float* lin_W    = (const float*)d_in[5];
    const float* lin_b    = (const float*)d_in[6];
    const float* f1_W1    = (const float*)d_in[7];
    const float* f1_W2    = (const float*)d_in[8];
    const float* f2_W1    = (const float*)d_in[9];
    const float* f2_W2    = (const float*)d_in[10];
    const float* c1_rel_W = (const float*)d_in[11];
    const float* c1_rel_b = (const float*)d_in[12];
    const float* c1_rt_W  = (const float*)d_in[13];
    const float* c2_rel_W = (const float*)d_in[14];
    const float* c2_rel_b = (const float*)d_in[15];
    const float* c2_rt_W  = (const float*)d_in[16];
    const float* lin1_W   = (const float*)d_in[17];
    const float* lin1_b   = (const float*)d_in[18];
    const float* lin2_W   = (const float*)d_in[19];
    const float* lin2_b   = (const float*)d_in[20];
    const float* cat_W    = (const float*)d_in[21];
    const float* cat_b    = (const float*)d_in[22];
    const float* norm_w   = (const float*)d_in[23];
    const float* norm_b   = (const float*)d_in[24];
    const float* norm_ms  = (const float*)d_in[25];
    const float* lins_W   = (const float*)d_in[26];
    const float* lins_b   = (const float*)d_in[27];
    const float* final_W  = (const float*)d_in[28];
    const float* final_b  = (const float*)d_in[29];

    const int nN = in_sizes[0] / HH;
    const int nE = in_sizes[3] / 2;

    float *pxact, *pagg1, *pagg2, *pA, *pB, *pC;
    cudaGetSymbolAddress((void**)&pxact, g_xact);
    cudaGetSymbolAddress((void**)&pagg1, g_agg1);
    cudaGetSymbolAddress((void**)&pagg2, g_agg2);
    cudaGetSymbolAddress((void**)&pA, g_A);
    cudaGetSymbolAddress((void**)&pB, g_B);
    cudaGetSymbolAddress((void**)&pC, g_C);

    cudaFuncSetAttribute(gemm_p<false, true,  true,  false, 0>, cudaFuncAttributeMaxDynamicSharedMemorySize, GEMM_SMEM);
    cudaFuncSetAttribute(gemm_p<false, false, false, false, 0>, cudaFuncAttributeMaxDynamicSharedMemorySize, GEMM_SMEM);
    cudaFuncSetAttribute(gemm_p<true,  true,  false, false, 0>, cudaFuncAttributeMaxDynamicSharedMemorySize, GEMM_SMEM);
    cudaFuncSetAttribute(gemm_p<true,  true,  false, true,  0>, cudaFuncAttributeMaxDynamicSharedMemorySize, GEMM_SMEM);
    cudaFuncSetAttribute(gemm_p<false, true,  true,  true,  0>, cudaFuncAttributeMaxDynamicSharedMemorySize, GEMM_SMEM);
    cudaFuncSetAttribute(gemm_p<false, true,  true,  true,  1>, cudaFuncAttributeMaxDynamicSharedMemorySize, GEMM_SMEM);
    cudaFuncSetAttribute(gemm_p<false, true,  false, false, 2>, cudaFuncAttributeMaxDynamicSharedMemorySize, GEMM_SMEM);

    const int PG = 296;   // persistent grid (2 CTAs/SM)

    WPack wp;
    wp.w[0]  = { lin_W, HH };
    wp.w[1]  = { c1_rel_W, HH };
    wp.w[2]  = { c1_rt_W, HH };
    wp.w[3]  = { lin1_W, HH };
    wp.w[4]  = { c2_rel_W, HH };
    wp.w[5]  = { c2_rt_W, HH };
    wp.w[6]  = { lin2_W, HH };
    wp.w[7]  = { cat_W, 2 * HH };
    wp.w[8]  = { cat_W + HH, 2 * HH };
    wp.w[9]  = { lins_W + 0 * HH * HH, HH };
    wp.w[10] = { lins_W + 1 * HH * HH, HH };
    wp.w[11] = { lins_W + 2 * HH * HH, HH };
    wp.w[12] = { final_W, HH };

    zero_kernel<<<(NN * HH + 255) / 256, 256>>>();
    prep_weights<<<(13 * 16384 + 255) / 256, 256>>>(wp);

    // edge stage 1 (independent of xact)
    edge_mlp1<<<592, 256>>>(feature1, feature2, f1_W1, f2_W1, nE);

    // x_act = swish(x @ lin_W^T + lin_b)
    gemm_p<false, true, true, false, 0><<<PG, 256, GEMM_SMEM>>>(
        x, 0, lin_b, nullptr, pxact, nN, nullptr, nullptr, nullptr);

    // edge stage 2
    edge_scatter<<<444, 256>>>(ei, f1_W2, f2_W2, pxact, pagg1, pagg2, nE);

    // t1 = agg1@rel1 + xact@root1 + b  -> pA
    gemm_p<false, false, false, false, 0><<<PG, 256, GEMM_SMEM>>>(
        pagg1, 1, nullptr, nullptr, pA, nN, nullptr, nullptr, nullptr);
    gemm_p<true, true, false, false, 0><<<PG, 256, GEMM_SMEM>>>(
        pxact, 2, c1_rel_b, nullptr, pA, nN, nullptr, nullptr, nullptr);
    // h1 = swish(t1@lin1 + b)          -> pB
    gemm_p<false, true, true, false, 0><<<PG, 256, GEMM_SMEM>>>(
        pA, 3, lin1_b, nullptr, pB, nN, nullptr, nullptr, nullptr);
    // t2 -> pA
    gemm_p<false, false, false, false, 0><<<PG, 256, GEMM_SMEM>>>(
        pagg2, 4, nullptr, nullptr, pA, nN, nullptr, nullptr, nullptr);
    gemm_p<true, true, false, false, 0><<<PG, 256, GEMM_SMEM>>>(
        pxact, 5, c2_rel_b, nullptr, pA, nN, nullptr, nullptr, nullptr);
    // h2 = swish(t2@lin2 + b)          -> pC
    gemm_p<false, true, true, false, 0><<<PG, 256, GEMM_SMEM>>>(
        pA, 6, lin2_b, nullptr, pC, nN, nullptr, nullptr, nullptr);
    // h = h1@cat1 + h2@cat2 + cat_b + xact -> pA
    gemm_p<false, false, false, false, 0><<<PG, 256, GEMM_SMEM>>>(
        pB, 7, nullptr, nullptr, pA, nN, nullptr, nullptr, nullptr);
    gemm_p<true, true, false, true, 0><<<PG, 256, GEMM_SMEM>>>(
        pC, 8, cat_b, pxact, pA, nN, nullptr, nullptr, nullptr);
    // residual swish layers; last one fuses GraphNorm mean/cnt accumulation
    gemm_p<false, true, true, true, 0><<<PG, 256, GEMM_SMEM>>>(
        pA, 9,  lins_b + 0 * HH, pA, pB, nN, nullptr, nullptr, nullptr);
    gemm_p<false, true, true, true, 0><<<PG, 256, GEMM_SMEM>>>(
        pB, 10, lins_b + 1 * HH, pB, pA, nN, nullptr, nullptr, nullptr);
    gemm_p<false, true, true, true, 1><<<PG, 256, GEMM_SMEM>>>(
        pA, 11, lins_b + 2 * HH, pA, pB, nN, batch, nullptr, nullptr);

    // center (+var accumulation) -> pC
    const int n32b = (NN * 32 + 255) / 256;
    norm_center<<<n32b, 256>>>(pB, batch, norm_ms, pC);

    // final GEMM with fused norm-apply on A-load
    gemm_p<false, true, false, false, 2><<<PG, 256, GEMM_SMEM>>>(
        pC, 12, final_b, nullptr, (float*)d_out, nN, batch, norm_w, norm_b);
}

// round 12
// speedup vs baseline: 1.7114x; 1.0048x over previous
#include <cuda_runtime.h>
#include <cuda_bf16.h>

#define NN 50000
#define EE 1000000
#define BB 512
#define HH 128
#define MID 64
#define IN1 54
#define IN2 18

typedef unsigned long long u64;
typedef unsigned int u32;

#define FMA2(d, a, b, c) asm("fma.rn.f32x2 %0, %1, %2, %3;" : "=l"(d) : "l"(a), "l"(b), "l"(c))

__device__ __forceinline__ u64 pack2(float lo, float hi) {
    u64 r; asm("mov.b64 %0, {%1, %2};" : "=l"(r) : "f"(lo), "f"(hi)); return r;
}
__device__ __forceinline__ void unpack2(u64 v, float& lo, float& hi) {
    asm("mov.b64 {%0, %1}, %2;" : "=f"(lo), "=f"(hi) : "l"(v));
}
__device__ __forceinline__ void red_add_v4(float* addr, float4 v) {
    asm volatile("red.global.add.v4.f32 [%0], {%1, %2, %3, %4};"
                 :: "l"(addr), "f"(v.x), "f"(v.y), "f"(v.z), "f"(v.w) : "memory");
}
__device__ __forceinline__ void red_add_v2(float* addr, float a, float b) {
    asm volatile("red.global.add.v2.f32 [%0], {%1, %2};"
                 :: "l"(addr), "f"(a), "f"(b) : "memory");
}
__device__ __forceinline__ void red_add_f(float* addr, float v) {
    asm volatile("red.global.add.f32 [%0], %1;" :: "l"(addr), "f"(v) : "memory");
}
__device__ __forceinline__ u32 prmt(u32 a, u32 b, u32 s) {
    u32 d; asm("prmt.b32 %0, %1, %2, %3;" : "=r"(d) : "r"(a), "r"(b), "r"(s)); return d;
}
#define MMA16816(c0, c1, c2, c3, a0, a1, a2, a3, b0, b1) \
    asm volatile("mma.sync.aligned.m16n8k16.row.col.f32.bf16.bf16.f32 " \
                 "{%0,%1,%2,%3}, {%4,%5,%6,%7}, {%8,%9}, {%0,%1,%2,%3};" \
                 : "+f"(c0), "+f"(c1), "+f"(c2), "+f"(c3) \
                 : "r"(a0), "r"(a1), "r"(a2), "r"(a3), "r"(b0), "r"(b1))

__device__ __forceinline__ u32 pack_bf2(float e0, float e1) {
    __nv_bfloat162 h = __floats2bfloat162_rn(e0, e1);
    return *(u32*)&h;
}

// ---------------- scratch ----------------
__device__ float g_xact[NN * HH];
__device__ float g_agg1[NN * HH];
__device__ float g_agg2[NN * HH];
__device__ float g_A[NN * HH];
__device__ float g_B[NN * HH];
__device__ float g_C[NN * HH];
__device__ float g_mean[BB * HH];
__device__ float g_var[BB * HH];
__device__ float g_cnt[BB];
__device__ u32 g_m1p[EE * MID];
__device__ u32 g_m2p[EE * MID];
// preconverted node-GEMM weights: 13 matrices of 128x128, bf16 hi/lo planes (flat [c][k])
__device__ __nv_bfloat16 g_Wh[13 * 128 * 128];
__device__ __nv_bfloat16 g_Wl[13 * 128 * 128];

__global__ void zero_kernel() {
    int idx = blockIdx.x * blockDim.x + threadIdx.x;
    if (idx < NN * HH) { g_agg1[idx] = 0.f; g_agg2[idx] = 0.f; }
    if (idx < BB * HH) { g_mean[idx] = 0.f; g_var[idx] = 0.f; }
    if (idx < BB) g_cnt[idx] = 0.f;
}

// ---------------- weight prep: fp32 -> bf16 hi/lo planes ----------------
struct WSrc { const float* p; int ldw; };
struct WPack { WSrc w[13]; };

__global__ void prep_weights(WPack wp) {
    int idx = blockIdx.x * blockDim.x + threadIdx.x;
    if (idx >= 13 * 16384) return;
    int m = idx >> 14, r = idx & 16383, c = r >> 7, k = r & 127;
    float v = wp.w[m].p[(size_t)c * wp.w[m].ldw + k];
    __nv_bfloat16 h = __float2bfloat16_rn(v);
    g_Wh[idx] = h;
    g_Wl[idx] = __float2bfloat16_rn(v - __bfloat162float(h));
}

// ---------------- persistent node GEMM via split-bf16 HMMA ----------------
constexpr int GP = 136;
constexpr int GEMM_SMEM = (64 + 64 + 128 + 128) * GP * 2;

template <bool ACCUM, bool EPI, bool SWISH, bool RESID, int FUSE>
__global__ __launch_bounds__(256, 2) void gemm_p(
    const float* __restrict__ A, int widx,
    const float* __restrict__ bias, const float* __restrict__ resid,
    float* __restrict__ out, int nrows,
    const int* __restrict__ batch, const float* __restrict__ nw, const float* __restrict__ nb)
{
    extern __shared__ char smc[];
    __nv_bfloat16* Ahi = (__nv_bfloat16*)(smc);
    __nv_bfloat16* Alo = (__nv_bfloat16*)(smc + 64 * GP * 2);
    __nv_bfloat16* Whi = (__nv_bfloat16*)(smc + 128 * GP * 2);
    __nv_bfloat16* Wlo = (__nv_bfloat16*)(smc + 256 * GP * 2);

    const int tid  = threadIdx.x;
    const int warp = tid >> 5;
    const int lane = tid & 31;
    const int fg   = lane >> 2;
    const int ft   = lane & 3;
    const int rg   = warp & 3;
    const int chf  = warp >> 2;

    {
        const u32* srcH = (const u32*)(g_Wh + (size_t)widx * 16384);
        const u32* srcL = (const u32*)(g_Wl + (size_t)widx * 16384);
        for (int i = tid; i < 128 * 64; i += 256) {
            int c = i >> 6, kp = i & 63;
            ((u32*)Whi)[c * 68 + kp] = srcH[i];
            ((u32*)Wlo)[c * 68 + kp] = srcL[i];
        }
    }

    const int ntiles = (nrows + 63) >> 6;

    float4 pre[8];
    auto ldA = [&](int tt) {
#pragma unroll
        for (int j = 0; j < 8; j++) {
            int idx = tid + 256 * j;
            int r = idx >> 5, kp4 = idx & 31;
            int gr = (tt << 6) + r;
            float4 v = (gr < nrows) ? *(const float4*)(A + (size_t)gr * 128 + 4 * kp4)
                                    : make_float4(0.f, 0.f, 0.f, 0.f);
            if (FUSE == 2) {
                if (gr < nrows) {
                    int b = __ldg(batch + gr);
                    float rcnt = 1.f / fmaxf(g_cnt[b], 1.f);
                    float4 vv = *(const float4*)(&g_var[b * HH + 4 * kp4]);
                    float4 w4 = *(const float4*)(nw + 4 * kp4);
                    float4 b4 = *(const float4*)(nb + 4 * kp4);
                    v.x = w4.x * v.x * rsqrtf(vv.x * rcnt + 1e-5f) + b4.x;
                    v.y = w4.y * v.y * rsqrtf(vv.y * rcnt + 1e-5f) + b4.y;
                    v.z = w4.z * v.z * rsqrtf(vv.z * rcnt + 1e-5f) + b4.z;
                    v.w = w4.w * v.w * rsqrtf(vv.w * rcnt + 1e-5f) + b4.w;
                }
            }
            pre[j] = v;
        }
    };

    int t = blockIdx.x;
    if (t < ntiles) ldA(t);

    for (; t < ntiles; t += gridDim.x) {
        const int r0 = t << 6;
        __syncthreads();

#pragma unroll
        for (int j = 0; j < 8; j++) {
            int idx = tid + 256 * j;
            int r = idx >> 5, kp4 = idx & 31;
            float4 v = pre[j];
            __nv_bfloat162 h01 = __floats2bfloat162_rn(v.x, v.y);
            __nv_bfloat162 h23 = __floats2bfloat162_rn(v.z, v.w);
            __nv_bfloat162 l01 = __floats2bfloat162_rn(v.x - __bfloat162float(h01.x),
                                                       v.y - __bfloat162float(h01.y));
            __nv_bfloat162 l23 = __floats2bfloat162_rn(v.z - __bfloat162float(h23.x),
                                                       v.w - __bfloat162float(h23.y));
            ((u64*)(Ahi + r * GP))[kp4] = (u64)(*(u32*)&h01) | ((u64)(*(u32*)&h23) << 32);
            ((u64*)(Alo + r * GP))[kp4] = (u64)(*(u32*)&l01) | ((u64)(*(u32*)&l23) << 32);
        }
        __syncthreads();

        const int tn = t + gridDim.x;
        if (tn < ntiles) ldA(tn);

        float acc[8][4];
#pragma unroll
        for (int nt = 0; nt < 8; nt++)
#pragma unroll
            for (int q = 0; q < 4; q++) acc[nt][q] = 0.f;

        const int m0 = rg * 16 + fg;
#pragma unroll
        for (int kstep = 0; kstep < 8; kstep++) {
            const int k0 = kstep * 16 + 2 * ft;
            u32 ah0 = *(const u32*)(Ahi + m0 * GP + k0);
            u32 ah1 = *(const u32*)(Ahi + (m0 + 8) * GP + k0);
            u32 ah2 = *(const u32*)(Ahi + m0 * GP + k0 + 8);
            u32 ah3 = *(const u32*)(Ahi + (m0 + 8) * GP + k0 + 8);
            u32 al0 = *(const u32*)(Alo + m0 * GP + k0);
            u32 al1 = *(const u32*)(Alo + (m0 + 8) * GP + k0);
            u32 al2 = *(const u32*)(Alo + m0 * GP + k0 + 8);
            u32 al3 = *(const u32*)(Alo + (m0 + 8) * GP + k0 + 8);
#pragma unroll
            for (int nt = 0; nt < 8; nt++) {
                const int c = chf * 64 + nt * 8 + fg;
                u32 bh0 = *(const u32*)(Whi + c * GP + k0);
                u32 bh1 = *(const u32*)(Whi + c * GP + k0 + 8);
                u32 bl0 = *(const u32*)(Wlo + c * GP + k0);
                u32 bl1 = *(const u32*)(Wlo + c * GP + k0 + 8);
                MMA16816(acc[nt][0], acc[nt][1], acc[nt][2], acc[nt][3],
                         ah0, ah1, ah2, ah3, bh0, bh1);
                MMA16816(acc[nt][0], acc[nt][1], acc[nt][2], acc[nt][3],
                         al0, al1, al2, al3, bh0, bh1);
                MMA16816(acc[nt][0], acc[nt][1], acc[nt][2], acc[nt][3],
                         ah0, ah1, ah2, ah3, bl0, bl1);
            }
        }

        const int rA = r0 + m0, rBr = r0 + m0 + 8;
        int bA = 0, bB = 0;
        if (FUSE == 1) {
            if (rA < nrows)  bA = __ldg(batch + rA);
            if (rBr < nrows) bB = __ldg(batch + rBr);
        }
#pragma unroll
        for (int nt = 0; nt < 8; nt++) {
            const int c = chf * 64 + nt * 8 + 2 * ft;
            float v0 = acc[nt][0], v1 = acc[nt][1];
            float v2 = acc[nt][2], v3 = acc[nt][3];
            if (EPI) {
                float2 bv = *(const float2*)(bias + c);
                v0 += bv.x; v1 += bv.y; v2 += bv.x; v3 += bv.y;
            }
            if (rA < nrows) {
                float* orow = out + (size_t)rA * 128 + c;
                if (ACCUM) { float2 pv = *(const float2*)orow; v0 += pv.x; v1 += pv.y; }
                if (SWISH) {
                    v0 = v0 / (1.f + __expf(-v0));
                    v1 = v1 / (1.f + __expf(-v1));
                }
                if (RESID) {
                    float2 rv = *(const float2*)(resid + (size_t)rA * 128 + c);
                    v0 += rv.x; v1 += rv.y;
                }
                *(float2*)orow = make_float2(v0, v1);
                if (FUSE == 1) red_add_v2(&g_mean[bA * HH + c], v0, v1);
            }
            if (rBr < nrows) {
                float* orow = out + (size_t)rBr * 128 + c;
                if (ACCUM) { float2 pv = *(const float2*)orow; v2 += pv.x; v3 += pv.y; }
                if (SWISH) {
                    v2 = v2 / (1.f + __expf(-v2));
                    v3 = v3 / (1.f + __expf(-v3));
                }
                if (RESID) {
                    float2 rv = *(const float2*)(resid + (size_t)rBr * 128 + c);
                    v2 += rv.x; v3 += rv.y;
                }
                *(float2*)orow = make_float2(v2, v3);
                if (FUSE == 1) red_add_v2(&g_mean[bB * HH + c], v2, v3);
            }
        }
        if (FUSE == 1 && chf == 0 && ft == 0) {
            if (rA < nrows)  red_add_f(&g_cnt[bA], 1.f);
            if (rBr < nrows) red_add_f(&g_cnt[bB], 1.f);
        }
    }
}

// ---------------- edge stage 1 (unchanged) ----------------
constexpr int EB = 16;

__global__ __launch_bounds__(256) void edge_mlp1(
    const float* __restrict__ feat1, const float* __restrict__ feat2,
    const float* __restrict__ W1a, const float* __restrict__ W1b, int nE)
{
    __shared__ __align__(16) float f1s[EB * IN1];
    __shared__ __align__(16) float f2s[EB * IN2];
    __shared__ __align__(16) float Ws1a[MID * IN1];
    __shared__ __align__(16) float Ws1b[MID * IN2];

    const int tid = threadIdx.x;
    for (int i = tid; i < MID * IN1; i += 256) Ws1a[i] = W1a[i];
    for (int i = tid; i < MID * IN2; i += 256) Ws1b[i] = W1b[i];
    __syncthreads();

    const int ntiles = nE / EB;
    const int k = tid & 63, g = tid >> 6;

    for (int t = blockIdx.x; t < ntiles; t += gridDim.x) {
        const int e0 = t * EB;
        for (int i = tid; i < EB * IN1; i += 256) f1s[i] = feat1[(size_t)e0 * IN1 + i];
        for (int i = tid; i < EB * IN2; i += 256) f2s[i] = feat2[(size_t)e0 * IN2 + i];
        __syncthreads();

        {
            const u64* wrow = (const u64*)(Ws1a + k * IN1);
            const u64* fr0 = (const u64*)(f1s + (g + 0)  * IN1);
            const u64* fr1 = (const u64*)(f1s + (g + 4)  * IN1);
            const u64* fr2 = (const u64*)(f1s + (g + 8)  * IN1);
            const u64* fr3 = (const u64*)(f1s + (g + 12) * IN1);
            u64 a0 = 0ull, a1 = 0ull, a2 = 0ull, a3 = 0ull;
#pragma unroll
            for (int jp = 0; jp < IN1 / 2; jp++) {
                u64 w = wrow[jp];
                FMA2(a0, fr0[jp], w, a0);
                FMA2(a1, fr1[jp], w, a1);
                FMA2(a2, fr2[jp], w, a2);
                FMA2(a3, fr3[jp], w, a3);
            }
            float lo, hi;
#pragma unroll
            for (int q = 0; q < 4; q++) {
                u64 a = (q == 0) ? a0 : (q == 1) ? a1 : (q == 2) ? a2 : a3;
                unpack2(a, lo, hi);
                float v = lo + hi;
                __nv_bfloat16 bh = __float2bfloat16_rn(v);
                __nv_bfloat16 bl = __float2bfloat16_rn(v - __bfloat162float(bh));
                u32 pk = (u32)__bfloat16_as_ushort(bh) | ((u32)__bfloat16_as_ushort(bl) << 16);
                g_m1p[(size_t)(e0 + g + 4 * q) * MID + k] = pk;
            }
        }
        {
            const u64* wrow = (const u64*)(Ws1b + k * IN2);
            const u64* fr0 = (const u64*)(f2s + (g + 0)  * IN2);
            const u64* fr1 = (const u64*)(f2s + (g + 4)  * IN2);
            const u64* fr2 = (const u64*)(f2s + (g + 8)  * IN2);
            const u64* fr3 = (const u64*)(f2s + (g + 12) * IN2);
            u64 a0 = 0ull, a1 = 0ull, a2 = 0ull, a3 = 0ull;
#pragma unroll
            for (int jp = 0; jp < IN2 / 2; jp++) {
                u64 w = wrow[jp];
                FMA2(a0, fr0[jp], w, a0);
                FMA2(a1, fr1[jp], w, a1);
                FMA2(a2, fr2[jp], w, a2);
                FMA2(a3, fr3[jp], w, a3);
            }
            float lo, hi;
#pragma unroll
            for (int q = 0; q < 4; q++) {
                u64 a = (q == 0) ? a0 : (q == 1) ? a1 : (q == 2) ? a2 : a3;
                unpack2(a, lo, hi);
                float v = lo + hi;
                __nv_bfloat16 bh = __float2bfloat16_rn(v);
                __nv_bfloat16 bl = __float2bfloat16_rn(v - __bfloat162float(bh));
                u32 pk = (u32)__bfloat16_as_ushort(bh) | ((u32)__bfloat16_as_ushort(bl) << 16);
                g_m2p[(size_t)(e0 + g + 4 * q) * MID + k] = pk;
            }
        }
        __syncthreads();
    }
}

// ---------------- edge stage 2: shuffle-merged v4 REDs ----------------
constexpr int XP = 132;
constexpr int EB2 = 32;

__global__ __launch_bounds__(256, 3) void edge_scatter(
    const int* __restrict__ ei,
    const float* __restrict__ W2a, const float* __restrict__ W2b,
    const float* __restrict__ xact,
    float* __restrict__ agg1, float* __restrict__ agg2, int nE)
{
    __shared__ __align__(16) float xs[2][EB2 * XP];

    const int tid  = threadIdx.x;
    const int warp = tid >> 5;
    const int lane = tid & 31;
    const int fg   = lane >> 2;
    const int ft   = lane & 3;

    u32 bhi[4][4][2], blo[4][4][2];
    {
        const float* W2 = (warp < 4) ? W2a : W2b;
        const int nbase = (warp & 3) * 32;
#pragma unroll
        for (int nt = 0; nt < 4; nt++) {
            const float* wrow = W2 + (size_t)(nbase + nt * 8 + fg) * MID;
#pragma unroll
            for (int kt = 0; kt < 4; kt++) {
#pragma unroll
                for (int half = 0; half < 2; half++) {
                    int k0 = kt * 16 + half * 8 + 2 * ft;
                    float w0 = wrow[k0], w1 = wrow[k0 + 1];
                    __nv_bfloat16 h0 = __float2bfloat16_rn(w0);
                    __nv_bfloat16 h1 = __float2bfloat16_rn(w1);
                    bhi[nt][kt][half] = pack_bf2(__bfloat162float(h0), __bfloat162float(h1));
                    blo[nt][kt][half] = pack_bf2(w0 - __bfloat162float(h0),
                                                 w1 - __bfloat162float(h1));
                }
            }
        }
    }

    const int ntiles = nE / EB2;

    auto do_gather = [&](int buf, int tt) {
        const int e0n = tt * EB2;
#pragma unroll
        for (int j = 0; j < 4; j++) {
            int idx = tid + 256 * j;
            int e = idx >> 5, h4 = (idx & 31) << 2;
            int src = __ldg(ei + e0n + e);
            float4 v = *(const float4*)(xact + (size_t)src * HH + h4);
            *(float4*)(&xs[buf][e * XP + h4]) = v;
        }
    };

    int t = blockIdx.x;
    if (t < ntiles) do_gather(0, t);

    int it = 0;
    for (; t < ntiles; t += gridDim.x, it ^= 1) {
        const int cur = it, nxt = it ^ 1;
        const int tn = t + gridDim.x;
        __syncthreads();
        if (tn < ntiles) do_gather(nxt, tn);

        const u32* mpl = (warp < 4) ? g_m1p : g_m2p;
        float* agg = (warp < 4) ? agg1 : agg2;
        const int nbase = (warp & 3) * 32;

#pragma unroll
        for (int sb = 0; sb < 2; sb++) {
            const int e0 = t * EB2 + sb * 16;
            const int exs = sb * 16;

            float acc[4][4];
#pragma unroll
            for (int nt = 0; nt < 4; nt++)
#pragma unroll
                for (int q = 0; q < 4; q++) acc[nt][q] = 0.f;

            const u32* rowA = mpl + (size_t)(e0 + fg) * MID;
            const u32* rowB = mpl + (size_t)(e0 + fg + 8) * MID;
#pragma unroll
            for (int kt = 0; kt < 4; kt++) {
                const int k0 = kt * 16 + 2 * ft;
                uint2 vA0 = *(const uint2*)(rowA + k0);
                uint2 vA1 = *(const uint2*)(rowB + k0);
                uint2 vA2 = *(const uint2*)(rowA + k0 + 8);
                uint2 vA3 = *(const uint2*)(rowB + k0 + 8);
                u32 ah0 = prmt(vA0.x, vA0.y, 0x5410), al0 = prmt(vA0.x, vA0.y, 0x7632);
                u32 ah1 = prmt(vA1.x, vA1.y, 0x5410), al1 = prmt(vA1.x, vA1.y, 0x7632);
                u32 ah2 = prmt(vA2.x, vA2.y, 0x5410), al2 = prmt(vA2.x, vA2.y, 0x7632);
                u32 ah3 = prmt(vA3.x, vA3.y, 0x5410), al3 = prmt(vA3.x, vA3.y, 0x7632);
#pragma unroll
                for (int nt = 0; nt < 4; nt++) {
                    MMA16816(acc[nt][0], acc[nt][1], acc[nt][2], acc[nt][3],
                             ah0, ah1, ah2, ah3, bhi[nt][kt][0], bhi[nt][kt][1]);
                    MMA16816(acc[nt][0], acc[nt][1], acc[nt][2], acc[nt][3],
                             al0, al1, al2, al3, bhi[nt][kt][0], bhi[nt][kt][1]);
                    MMA16816(acc[nt][0], acc[nt][1], acc[nt][2], acc[nt][3],
                             ah0, ah1, ah2, ah3, blo[nt][kt][0], blo[nt][kt][1]);
                }
            }

            // ---- epilogue: lane-pair shuffle -> one v4 RED per 4 channels ----
            const int dA = __ldg(ei + nE + e0 + fg);
            const int dB = __ldg(ei + nE + e0 + fg + 8);
            const bool emit = ((ft & 1) == 0);   // even-ft lanes emit ch%4==0 REDs
#pragma unroll
            for (int nt = 0; nt < 4; nt++) {
                int ch = nbase + nt * 8 + 2 * ft;
                float2 xga = *(const float2*)(&xs[cur][(exs + fg) * XP + ch]);
                float2 xgb = *(const float2*)(&xs[cur][(exs + fg + 8) * XP + ch]);
                float pa0 = acc[nt][0] * xga.x, pa1 = acc[nt][1] * xga.y;
                float pb0 = acc[nt][2] * xgb.x, pb1 = acc[nt][3] * xgb.y;
                float sa0 = __shfl_xor_sync(0xffffffffu, pa0, 1);
                float sa1 = __shfl_xor_sync(0xffffffffu, pa1, 1);
                float sb0 = __shfl_xor_sync(0xffffffffu, pb0, 1);
                float sb1 = __shfl_xor_sync(0xffffffffu, pb1, 1);
                if (emit) {
                    red_add_v4(agg + (size_t)dA * HH + ch, make_float4(pa0, pa1, sa0, sa1));
                    red_add_v4(agg + (size_t)dB * HH + ch, make_float4(pb0, pb1, sb0, sb1));
                }
            }
        }
    }
}

// ---------------- GraphNorm center ----------------
__global__ void norm_center(const float* __restrict__ hin, const int* __restrict__ batch,
                            const float* __restrict__ ms, float* __restrict__ hc_out) {
    int idx = blockIdx.x * blockDim.x + threadIdx.x;
    if (idx >= NN * 32) return;
    int n = idx >> 5, c4 = (idx & 31) << 2;
    int b = batch[n];
    float rcnt = 1.f / fmaxf(g_cnt[b], 1.f);
    float4 hv = *(const float4*)(hin + (size_t)n * HH + c4);
    float4 mv = *(const float4*)(&g_mean[b * HH + c4]);
    float4 msv = *(const float4*)(ms + c4);
    float4 hc;
    hc.x = hv.x - mv.x * rcnt * msv.x;
    hc.y = hv.y - mv.y * rcnt * msv.y;
    hc.z = hv.z - mv.z * rcnt * msv.z;
    hc.w = hv.w - mv.w * rcnt * msv.w;
    *(float4*)(hc_out + (size_t)n * HH + c4) = hc;
    float4 sq = make_float4(hc.x * hc.x, hc.y * hc.y, hc.z * hc.z, hc.w * hc.w);
    red_add_v4(&g_var[b * HH + c4], sq);
}

// ---------------- launch ----------------
extern "C" void kernel_launch(void* const* d_in, const int* in_sizes, int n_in,
                              void* d_out, int out_size)
{
    const float* x        = (const float*)d_in[0];
    const float* feature1 = (const float*)d_in[1];
    const float* feature2 = (const float*)d_in[2];
    const int*   ei       = (const int*)d_in[3];
    const int*   batch    = (const int*)d_in[4];
    const float* lin_W    = (const float*)d_in[5];
    const float* lin_b    = (const float*)d_in[6];
    const float* f1_W1    = (const float*)d_in[7];
    const float* f1_W2    = (const float*)d_in[8];
    const float* f2_W1    = (const float*)d_in[9];
    const float* f2_W2    = (const float*)d_in[10];
    const float* c1_rel_W = (const float*)d_in[11];
    const float* c1_rel_b = (const float*)d_in[12];
    const float* c1_rt_W  = (const float*)d_in[13];
    const float* c2_rel_W = (const float*)d_in[14];
    const float* c2_rel_b = (const float*)d_in[15];
    const float* c2_rt_W  = (const float*)d_in[16];
    const float* lin1_W   = (const float*)d_in[17];
    const float* lin1_b   = (const float*)d_in[18];
    const float* lin2_W   = (const float*)d_in[19];
    const float* lin2_b   = (const float*)d_in[20];
    const float* cat_W    = (const float*)d_in[21];
    const float* cat_b    = (const float*)d_in[22];
    const float* norm_w   = (const float*)d_in[23];
    const float* norm_b   = (const float*)d_in[24];
    const float* norm_ms  = (const float*)d_in[25];
    const float* lins_W   = (const float*)d_in[26];
    const float* lins_b   = (const float*)d_in[27];
    const float* final_W  = (const float*)d_in[28];
    const float* final_b  = (const float*)d_in[29];

    const int nN = in_sizes[0] / HH;
    const int nE = in_sizes[3] / 2;

    float *pxact, *pagg1, *pagg2, *pA, *pB, *pC;
    cudaGetSymbolAddress((void**)&pxact, g_xact);
    cudaGetSymbolAddress((void**)&pagg1, g_agg1);
    cudaGetSymbolAddress((void**)&pagg2, g_agg2);
    cudaGetSymbolAddress((void**)&pA, g_A);
    cudaGetSymbolAddress((void**)&pB, g_B);
    cudaGetSymbolAddress((void**)&pC, g_C);

    cudaFuncSetAttribute(gemm_p<false, true,  true,  false, 0>, cudaFuncAttributeMaxDynamicSharedMemorySize, GEMM_SMEM);
    cudaFuncSetAttribute(gemm_p<false, false, false, false, 0>, cudaFuncAttributeMaxDynamicSharedMemorySize, GEMM_SMEM);
    cudaFuncSetAttribute(gemm_p<true,  true,  false, false, 0>, cudaFuncAttributeMaxDynamicSharedMemorySize, GEMM_SMEM);
    cudaFuncSetAttribute(gemm_p<true,  true,  false, true,  0>, cudaFuncAttributeMaxDynamicSharedMemorySize, GEMM_SMEM);
    cudaFuncSetAttribute(gemm_p<false, true,  true,  true,  0>, cudaFuncAttributeMaxDynamicSharedMemorySize, GEMM_SMEM);
    cudaFuncSetAttribute(gemm_p<false, true,  true,  true,  1>, cudaFuncAttributeMaxDynamicSharedMemorySize, GEMM_SMEM);
    cudaFuncSetAttribute(gemm_p<false, true,  false, false, 2>, cudaFuncAttributeMaxDynamicSharedMemorySize, GEMM_SMEM);

    const int PG = 296;

    WPack wp;
    wp.w[0]  = { lin_W, HH };
    wp.w[1]  = { c1_rel_W, HH };
    wp.w[2]  = { c1_rt_W, HH };
    wp.w[3]  = { lin1_W, HH };
    wp.w[4]  = { c2_rel_W, HH };
    wp.w[5]  = { c2_rt_W, HH };
    wp.w[6]  = { lin2_W, HH };
    wp.w[7]  = { cat_W, 2 * HH };
    wp.w[8]  = { cat_W + HH, 2 * HH };
    wp.w[9]  = { lins_W + 0 * HH * HH, HH };
    wp.w[10] = { lins_W + 1 * HH * HH, HH };
    wp.w[11] = { lins_W + 2 * HH * HH, HH };
    wp.w[12] = { final_W, HH };

    zero_kernel<<<(NN * HH + 255) / 256, 256>>>();
    prep_weights<<<(13 * 16384 + 255) / 256, 256>>>(wp);

    edge_mlp1<<<592, 256>>>(feature1, feature2, f1_W1, f2_W1, nE);

    gemm_p<false, true, true, false, 0><<<PG, 256, GEMM_SMEM>>>(
        x, 0, lin_b, nullptr, pxact, nN, nullptr, nullptr, nullptr);

    edge_scatter<<<444, 256>>>(ei, f1_W2, f2_W2, pxact, pagg1, pagg2, nE);

    gemm_p<false, false, false, false, 0><<<PG, 256, GEMM_SMEM>>>(
        pagg1, 1, nullptr, nullptr, pA, nN, nullptr, nullptr, nullptr);
    gemm_p<true, true, false, false, 0><<<PG, 256, GEMM_SMEM>>>(
        pxact, 2, c1_rel_b, nullptr, pA, nN, nullptr, nullptr, nullptr);
    gemm_p<false, true, true, false, 0><<<PG, 256, GEMM_SMEM>>>(
        pA, 3, lin1_b, nullptr, pB, nN, nullptr, nullptr, nullptr);
    gemm_p<false, false, false, false, 0><<<PG, 256, GEMM_SMEM>>>(
        pagg2, 4, nullptr, nullptr, pA, nN, nullptr, nullptr, nullptr);
    gemm_p<true, true, false, false, 0><<<PG, 256, GEMM_SMEM>>>(
        pxact, 5, c2_rel_b, nullptr, pA, nN, nullptr, nullptr, nullptr);
    gemm_p<false, true, true, false, 0><<<PG, 256, GEMM_SMEM>>>(
        pA, 6, lin2_b, nullptr, pC, nN, nullptr, nullptr, nullptr);
    gemm_p<false, false, false, false, 0><<<PG, 256, GEMM_SMEM>>>(
        pB, 7, nullptr, nullptr, pA, nN, nullptr, nullptr, nullptr);
    gemm_p<true, true, false, true, 0><<<PG, 256, GEMM_SMEM>>>(
        pC, 8, cat_b, pxact, pA, nN, nullptr, nullptr, nullptr);
    gemm_p<false, true, true, true, 0><<<PG, 256, GEMM_SMEM>>>(
        pA, 9,  lins_b + 0 * HH, pA, pB, nN, nullptr, nullptr, nullptr);
    gemm_p<false, true, true, true, 0><<<PG, 256, GEMM_SMEM>>>(
        pB, 10, lins_b + 1 * HH, pB, pA, nN, nullptr, nullptr, nullptr);
    gemm_p<false, true, true, true, 1><<<PG, 256, GEMM_SMEM>>>(
        pA, 11, lins_b + 2 * HH, pA, pB, nN, batch, nullptr, nullptr);

    const int n32b = (NN * 32 + 255) / 256;
    norm_center<<<n32b, 256>>>(pB, batch, norm_ms, pC);

    gemm_p<false, true, false, false, 2><<<PG, 256, GEMM_SMEM>>>(
        pC, 12, final_b, nullptr, (float*)d_out, nN, batch, norm_w, norm_b);
}

// round 13
// speedup vs baseline: 1.8636x; 1.0890x over previous
#include <cuda_runtime.h>
#include <cuda_bf16.h>
#include <cuda_fp16.h>

#define NN 50000
#define EE 1000000
#define BB 512
#define HH 128
#define MID 64
#define IN1 54
#define IN2 18

typedef unsigned long long u64;
typedef unsigned int u32;

#define FMA2(d, a, b, c) asm("fma.rn.f32x2 %0, %1, %2, %3;" : "=l"(d) : "l"(a), "l"(b), "l"(c))

__device__ __forceinline__ u64 pack2(float lo, float hi) {
    u64 r; asm("mov.b64 %0, {%1, %2};" : "=l"(r) : "f"(lo), "f"(hi)); return r;
}
__device__ __forceinline__ void unpack2(u64 v, float& lo, float& hi) {
    asm("mov.b64 {%0, %1}, %2;" : "=f"(lo), "=f"(hi) : "l"(v));
}
__device__ __forceinline__ void red_add_v4(float* addr, float4 v) {
    asm volatile("red.global.add.v4.f32 [%0], {%1, %2, %3, %4};"
                 :: "l"(addr), "f"(v.x), "f"(v.y), "f"(v.z), "f"(v.w) : "memory");
}
__device__ __forceinline__ void red_add_v2(float* addr, float a, float b) {
    asm volatile("red.global.add.v2.f32 [%0], {%1, %2};"
                 :: "l"(addr), "f"(a), "f"(b) : "memory");
}
__device__ __forceinline__ void red_add_f(float* addr, float v) {
    asm volatile("red.global.add.f32 [%0], %1;" :: "l"(addr), "f"(v) : "memory");
}
__device__ __forceinline__ u32 prmt(u32 a, u32 b, u32 s) {
    u32 d; asm("prmt.b32 %0, %1, %2, %3;" : "=r"(d) : "r"(a), "r"(b), "r"(s)); return d;
}
// bf16 mma (node chain)
#define MMA16816(c0, c1, c2, c3, a0, a1, a2, a3, b0, b1) \
    asm volatile("mma.sync.aligned.m16n8k16.row.col.f32.bf16.bf16.f32 " \
                 "{%0,%1,%2,%3}, {%4,%5,%6,%7}, {%8,%9}, {%0,%1,%2,%3};" \
                 : "+f"(c0), "+f"(c1), "+f"(c2), "+f"(c3) \
                 : "r"(a0), "r"(a1), "r"(a2), "r"(a3), "r"(b0), "r"(b1))
// fp16 mma (edge path)
#define MMAH16816(c0, c1, c2, c3, a0, a1, a2, a3, b0, b1) \
    asm volatile("mma.sync.aligned.m16n8k16.row.col.f32.f16.f16.f32 " \
                 "{%0,%1,%2,%3}, {%4,%5,%6,%7}, {%8,%9}, {%0,%1,%2,%3};" \
                 : "+f"(c0), "+f"(c1), "+f"(c2), "+f"(c3) \
                 : "r"(a0), "r"(a1), "r"(a2), "r"(a3), "r"(b0), "r"(b1))

__device__ __forceinline__ u32 pack_bf2(float e0, float e1) {
    __nv_bfloat162 h = __floats2bfloat162_rn(e0, e1);
    return *(u32*)&h;
}
__device__ __forceinline__ u32 pack_h2(float e0, float e1) {
    __half2 h = __floats2half2_rn(e0, e1);
    return *(u32*)&h;
}

// ---------------- scratch ----------------
__device__ float g_xact[NN * HH];
__device__ float g_agg1[NN * HH];
__device__ float g_agg2[NN * HH];
__device__ float g_A[NN * HH];
__device__ float g_B[NN * HH];
__device__ float g_C[NN * HH];
__device__ float g_mean[BB * HH];
__device__ float g_var[BB * HH];
__device__ float g_cnt[BB];
__device__ u32 g_m1p[EE * MID];   // fp16 hi | fp16 lo
__device__ u32 g_m2p[EE * MID];
// preconverted node-GEMM weights: 13 matrices of 128x128, bf16 hi/lo planes (flat [c][k])
__device__ __nv_bfloat16 g_Wh[13 * 128 * 128];
__device__ __nv_bfloat16 g_Wl[13 * 128 * 128];

__global__ void zero_kernel() {
    int idx = blockIdx.x * blockDim.x + threadIdx.x;
    if (idx < NN * HH) { g_agg1[idx] = 0.f; g_agg2[idx] = 0.f; }
    if (idx < BB * HH) { g_mean[idx] = 0.f; g_var[idx] = 0.f; }
    if (idx < BB) g_cnt[idx] = 0.f;
}

// ---------------- weight prep: fp32 -> bf16 hi/lo planes ----------------
struct WSrc { const float* p; int ldw; };
struct WPack { WSrc w[13]; };

__global__ void prep_weights(WPack wp) {
    int idx = blockIdx.x * blockDim.x + threadIdx.x;
    if (idx >= 13 * 16384) return;
    int m = idx >> 14, r = idx & 16383, c = r >> 7, k = r & 127;
    float v = wp.w[m].p[(size_t)c * wp.w[m].ldw + k];
    __nv_bfloat16 h = __float2bfloat16_rn(v);
    g_Wh[idx] = h;
    g_Wl[idx] = __float2bfloat16_rn(v - __bfloat162float(h));
}

// ---------------- persistent node GEMM via split-bf16 HMMA (unchanged) ----------------
constexpr int GP = 136;
constexpr int GEMM_SMEM = (64 + 64 + 128 + 128) * GP * 2;

template <bool ACCUM, bool EPI, bool SWISH, bool RESID, int FUSE>
__global__ __launch_bounds__(256, 2) void gemm_p(
    const float* __restrict__ A, int widx,
    const float* __restrict__ bias, const float* __restrict__ resid,
    float* __restrict__ out, int nrows,
    const int* __restrict__ batch, const float* __restrict__ nw, const float* __restrict__ nb)
{
    extern __shared__ char smc[];
    __nv_bfloat16* Ahi = (__nv_bfloat16*)(smc);
    __nv_bfloat16* Alo = (__nv_bfloat16*)(smc + 64 * GP * 2);
    __nv_bfloat16* Whi = (__nv_bfloat16*)(smc + 128 * GP * 2);
    __nv_bfloat16* Wlo = (__nv_bfloat16*)(smc + 256 * GP * 2);

    const int tid  = threadIdx.x;
    const int warp = tid >> 5;
    const int lane = tid & 31;
    const int fg   = lane >> 2;
    const int ft   = lane & 3;
    const int rg   = warp & 3;
    const int chf  = warp >> 2;

    {
        const u32* srcH = (const u32*)(g_Wh + (size_t)widx * 16384);
        const u32* srcL = (const u32*)(g_Wl + (size_t)widx * 16384);
        for (int i = tid; i < 128 * 64; i += 256) {
            int c = i >> 6, kp = i & 63;
            ((u32*)Whi)[c * 68 + kp] = srcH[i];
            ((u32*)Wlo)[c * 68 + kp] = srcL[i];
        }
    }

    const int ntiles = (nrows + 63) >> 6;

    float4 pre[8];
    auto ldA = [&](int tt) {
#pragma unroll
        for (int j = 0; j < 8; j++) {
            int idx = tid + 256 * j;
            int r = idx >> 5, kp4 = idx & 31;
            int gr = (tt << 6) + r;
            float4 v = (gr < nrows) ? *(const float4*)(A + (size_t)gr * 128 + 4 * kp4)
                                    : make_float4(0.f, 0.f, 0.f, 0.f);
            if (FUSE == 2) {
                if (gr < nrows) {
                    int b = __ldg(batch + gr);
                    float rcnt = 1.f / fmaxf(g_cnt[b], 1.f);
                    float4 vv = *(const float4*)(&g_var[b * HH + 4 * kp4]);
                    float4 w4 = *(const float4*)(nw + 4 * kp4);
                    float4 b4 = *(const float4*)(nb + 4 * kp4);
                    v.x = w4.x * v.x * rsqrtf(vv.x * rcnt + 1e-5f) + b4.x;
                    v.y = w4.y * v.y * rsqrtf(vv.y * rcnt + 1e-5f) + b4.y;
                    v.z = w4.z * v.z * rsqrtf(vv.z * rcnt + 1e-5f) + b4.z;
                    v.w = w4.w * v.w * rsqrtf(vv.w * rcnt + 1e-5f) + b4.w;
                }
            }
            pre[j] = v;
        }
    };

    int t = blockIdx.x;
    if (t < ntiles) ldA(t);

    for (; t < ntiles; t += gridDim.x) {
        const int r0 = t << 6;
        __syncthreads();

#pragma unroll
        for (int j = 0; j < 8; j++) {
            int idx = tid + 256 * j;
            int r = idx >> 5, kp4 = idx & 31;
            float4 v = pre[j];
            __nv_bfloat162 h01 = __floats2bfloat162_rn(v.x, v.y);
            __nv_bfloat162 h23 = __floats2bfloat162_rn(v.z, v.w);
            __nv_bfloat162 l01 = __floats2bfloat162_rn(v.x - __bfloat162float(h01.x),
                                                       v.y - __bfloat162float(h01.y));
            __nv_bfloat162 l23 = __floats2bfloat162_rn(v.z - __bfloat162float(h23.x),
                                                       v.w - __bfloat162float(h23.y));
            ((u64*)(Ahi + r * GP))[kp4] = (u64)(*(u32*)&h01) | ((u64)(*(u32*)&h23) << 32);
            ((u64*)(Alo + r * GP))[kp4] = (u64)(*(u32*)&l01) | ((u64)(*(u32*)&l23) << 32);
        }
        __syncthreads();

        const int tn = t + gridDim.x;
        if (tn < ntiles) ldA(tn);

        float acc[8][4];
#pragma unroll
        for (int nt = 0; nt < 8; nt++)
#pragma unroll
            for (int q = 0; q < 4; q++) acc[nt][q] = 0.f;

        const int m0 = rg * 16 + fg;
#pragma unroll
        for (int kstep = 0; kstep < 8; kstep++) {
            const int k0 = kstep * 16 + 2 * ft;
            u32 ah0 = *(const u32*)(Ahi + m0 * GP + k0);
            u32 ah1 = *(const u32*)(Ahi + (m0 + 8) * GP + k0);
            u32 ah2 = *(const u32*)(Ahi + m0 * GP + k0 + 8);
            u32 ah3 = *(const u32*)(Ahi + (m0 + 8) * GP + k0 + 8);
            u32 al0 = *(const u32*)(Alo + m0 * GP + k0);
            u32 al1 = *(const u32*)(Alo + (m0 + 8) * GP + k0);
            u32 al2 = *(const u32*)(Alo + m0 * GP + k0 + 8);
            u32 al3 = *(const u32*)(Alo + (m0 + 8) * GP + k0 + 8);
#pragma unroll
            for (int nt = 0; nt < 8; nt++) {
                const int c = chf * 64 + nt * 8 + fg;
                u32 bh0 = *(const u32*)(Whi + c * GP + k0);
                u32 bh1 = *(const u32*)(Whi + c * GP + k0 + 8);
                u32 bl0 = *(const u32*)(Wlo + c * GP + k0);
                u32 bl1 = *(const u32*)(Wlo + c * GP + k0 + 8);
                MMA16816(acc[nt][0], acc[nt][1], acc[nt][2], acc[nt][3],
                         ah0, ah1, ah2, ah3, bh0, bh1);
                MMA16816(acc[nt][0], acc[nt][1], acc[nt][2], acc[nt][3],
                         al0, al1, al2, al3, bh0, bh1);
                MMA16816(acc[nt][0], acc[nt][1], acc[nt][2], acc[nt][3],
                         ah0, ah1, ah2, ah3, bl0, bl1);
            }
        }

        const int rA = r0 + m0, rBr = r0 + m0 + 8;
        int bA = 0, bB = 0;
        if (FUSE == 1) {
            if (rA < nrows)  bA = __ldg(batch + rA);
            if (rBr < nrows) bB = __ldg(batch + rBr);
        }
#pragma unroll
        for (int nt = 0; nt < 8; nt++) {
            const int c = chf * 64 + nt * 8 + 2 * ft;
            float v0 = acc[nt][0], v1 = acc[nt][1];
            float v2 = acc[nt][2], v3 = acc[nt][3];
            if (EPI) {
                float2 bv = *(const float2*)(bias + c);
                v0 += bv.x; v1 += bv.y; v2 += bv.x; v3 += bv.y;
            }
            if (rA < nrows) {
                float* orow = out + (size_t)rA * 128 + c;
                if (ACCUM) { float2 pv = *(const float2*)orow; v0 += pv.x; v1 += pv.y; }
                if (SWISH) {
                    v0 = v0 / (1.f + __expf(-v0));
                    v1 = v1 / (1.f + __expf(-v1));
                }
                if (RESID) {
                    float2 rv = *(const float2*)(resid + (size_t)rA * 128 + c);
                    v0 += rv.x; v1 += rv.y;
                }
                *(float2*)orow = make_float2(v0, v1);
                if (FUSE == 1) red_add_v2(&g_mean[bA * HH + c], v0, v1);
            }
            if (rBr < nrows) {
                float* orow = out + (size_t)rBr * 128 + c;
                if (ACCUM) { float2 pv = *(const float2*)orow; v2 += pv.x; v3 += pv.y; }
                if (SWISH) {
                    v2 = v2 / (1.f + __expf(-v2));
                    v3 = v3 / (1.f + __expf(-v3));
                }
                if (RESID) {
                    float2 rv = *(const float2*)(resid + (size_t)rBr * 128 + c);
                    v2 += rv.x; v3 += rv.y;
                }
                *(float2*)orow = make_float2(v2, v3);
                if (FUSE == 1) red_add_v2(&g_mean[bB * HH + c], v2, v3);
            }
        }
        if (FUSE == 1 && chf == 0 && ft == 0) {
            if (rA < nrows)  red_add_f(&g_cnt[bA], 1.f);
            if (rBr < nrows) red_add_f(&g_cnt[bB], 1.f);
        }
    }
}

// ---------------- edge stage 1: m packed as fp16 hi|lo ----------------
constexpr int EB = 16;

__global__ __launch_bounds__(256) void edge_mlp1(
    const float* __restrict__ feat1, const float* __restrict__ feat2,
    const float* __restrict__ W1a, const float* __restrict__ W1b, int nE)
{
    __shared__ __align__(16) float f1s[EB * IN1];
    __shared__ __align__(16) float f2s[EB * IN2];
    __shared__ __align__(16) float Ws1a[MID * IN1];
    __shared__ __align__(16) float Ws1b[MID * IN2];

    const int tid = threadIdx.x;
    for (int i = tid; i < MID * IN1; i += 256) Ws1a[i] = W1a[i];
    for (int i = tid; i < MID * IN2; i += 256) Ws1b[i] = W1b[i];
    __syncthreads();

    const int ntiles = nE / EB;
    const int k = tid & 63, g = tid >> 6;

    for (int t = blockIdx.x; t < ntiles; t += gridDim.x) {
        const int e0 = t * EB;
        for (int i = tid; i < EB * IN1; i += 256) f1s[i] = feat1[(size_t)e0 * IN1 + i];
        for (int i = tid; i < EB * IN2; i += 256) f2s[i] = feat2[(size_t)e0 * IN2 + i];
        __syncthreads();

        {
            const u64* wrow = (const u64*)(Ws1a + k * IN1);
            const u64* fr0 = (const u64*)(f1s + (g + 0)  * IN1);
            const u64* fr1 = (const u64*)(f1s + (g + 4)  * IN1);
            const u64* fr2 = (const u64*)(f1s + (g + 8)  * IN1);
            const u64* fr3 = (const u64*)(f1s + (g + 12) * IN1);
            u64 a0 = 0ull, a1 = 0ull, a2 = 0ull, a3 = 0ull;
#pragma unroll
            for (int jp = 0; jp < IN1 / 2; jp++) {
                u64 w = wrow[jp];
                FMA2(a0, fr0[jp], w, a0);
                FMA2(a1, fr1[jp], w, a1);
                FMA2(a2, fr2[jp], w, a2);
                FMA2(a3, fr3[jp], w, a3);
            }
            float lo, hi;
#pragma unroll
            for (int q = 0; q < 4; q++) {
                u64 a = (q == 0) ? a0 : (q == 1) ? a1 : (q == 2) ? a2 : a3;
                unpack2(a, lo, hi);
                float v = lo + hi;
                __half hh = __float2half_rn(v);
                __half hl = __float2half_rn(v - __half2float(hh));
                u32 pk = (u32)__half_as_ushort(hh) | ((u32)__half_as_ushort(hl) << 16);
                g_m1p[(size_t)(e0 + g + 4 * q) * MID + k] = pk;
            }
        }
        {
            const u64* wrow = (const u64*)(Ws1b + k * IN2);
            const u64* fr0 = (const u64*)(f2s + (g + 0)  * IN2);
            const u64* fr1 = (const u64*)(f2s + (g + 4)  * IN2);
            const u64* fr2 = (const u64*)(f2s + (g + 8)  * IN2);
            const u64* fr3 = (const u64*)(f2s + (g + 12) * IN2);
            u64 a0 = 0ull, a1 = 0ull, a2 = 0ull, a3 = 0ull;
#pragma unroll
            for (int jp = 0; jp < IN2 / 2; jp++) {
                u64 w = wrow[jp];
                FMA2(a0, fr0[jp], w, a0);
                FMA2(a1, fr1[jp], w, a1);
                FMA2(a2, fr2[jp], w, a2);
                FMA2(a3, fr3[jp], w, a3);
            }
            float lo, hi;
#pragma unroll
            for (int q = 0; q < 4; q++) {
                u64 a = (q == 0) ? a0 : (q == 1) ? a1 : (q == 2) ? a2 : a3;
                unpack2(a, lo, hi);
                float v = lo + hi;
                __half hh = __float2half_rn(v);
                __half hl = __float2half_rn(v - __half2float(hh));
                u32 pk = (u32)__half_as_ushort(hh) | ((u32)__half_as_ushort(hl) << 16);
                g_m2p[(size_t)(e0 + g + 4 * q) * MID + k] = pk;
            }
        }
        __syncthreads();
    }
}

// ---------------- edge stage 2: fp16 2-term HMMA ----------------
constexpr int XP = 132;
constexpr int EB2 = 32;

__global__ __launch_bounds__(256, 3) void edge_scatter(
    const int* __restrict__ ei,
    const float* __restrict__ W2a, const float* __restrict__ W2b,
    const float* __restrict__ xact,
    float* __restrict__ agg1, float* __restrict__ agg2, int nE)
{
    __shared__ __align__(16) float xs[2][EB2 * XP];

    const int tid  = threadIdx.x;
    const int warp = tid >> 5;
    const int lane = tid & 31;
    const int fg   = lane >> 2;
    const int ft   = lane & 3;

    // preload W2 B-fragments (single fp16)
    u32 bhf[4][4][2];
    {
        const float* W2 = (warp < 4) ? W2a : W2b;
        const int nbase = (warp & 3) * 32;
#pragma unroll
        for (int nt = 0; nt < 4; nt++) {
            const float* wrow = W2 + (size_t)(nbase + nt * 8 + fg) * MID;
#pragma unroll
            for (int kt = 0; kt < 4; kt++) {
#pragma unroll
                for (int half = 0; half < 2; half++) {
                    int k0 = kt * 16 + half * 8 + 2 * ft;
                    bhf[nt][kt][half] = pack_h2(wrow[k0], wrow[k0 + 1]);
                }
            }
        }
    }

    const int ntiles = nE / EB2;

    auto do_gather = [&](int buf, int tt) {
        const int e0n = tt * EB2;
#pragma unroll
        for (int j = 0; j < 4; j++) {
            int idx = tid + 256 * j;
            int e = idx >> 5, h4 = (idx & 31) << 2;
            int src = __ldg(ei + e0n + e);
            float4 v = *(const float4*)(xact + (size_t)src * HH + h4);
            *(float4*)(&xs[buf][e * XP + h4]) = v;
        }
    };

    int t = blockIdx.x;
    if (t < ntiles) do_gather(0, t);

    int it = 0;
    for (; t < ntiles; t += gridDim.x, it ^= 1) {
        const int cur = it, nxt = it ^ 1;
        const int tn = t + gridDim.x;
        __syncthreads();
        if (tn < ntiles) do_gather(nxt, tn);

        const u32* mpl = (warp < 4) ? g_m1p : g_m2p;
        float* agg = (warp < 4) ? agg1 : agg2;
        const int nbase = (warp & 3) * 32;

#pragma unroll
        for (int sb = 0; sb < 2; sb++) {
            const int e0 = t * EB2 + sb * 16;
            const int exs = sb * 16;

            float acc[4][4];
#pragma unroll
            for (int nt = 0; nt < 4; nt++)
#pragma unroll
                for (int q = 0; q < 4; q++) acc[nt][q] = 0.f;

            const u32* rowA = mpl + (size_t)(e0 + fg) * MID;
            const u32* rowB = mpl + (size_t)(e0 + fg + 8) * MID;
#pragma unroll
            for (int kt = 0; kt < 4; kt++) {
                const int k0 = kt * 16 + 2 * ft;
                uint2 vA0 = *(const uint2*)(rowA + k0);
                uint2 vA1 = *(const uint2*)(rowB + k0);
                uint2 vA2 = *(const uint2*)(rowA + k0 + 8);
                uint2 vA3 = *(const uint2*)(rowB + k0 + 8);
                u32 ah0 = prmt(vA0.x, vA0.y, 0x5410), al0 = prmt(vA0.x, vA0.y, 0x7632);
                u32 ah1 = prmt(vA1.x, vA1.y, 0x5410), al1 = prmt(vA1.x, vA1.y, 0x7632);
                u32 ah2 = prmt(vA2.x, vA2.y, 0x5410), al2 = prmt(vA2.x, vA2.y, 0x7632);
                u32 ah3 = prmt(vA3.x, vA3.y, 0x5410), al3 = prmt(vA3.x, vA3.y, 0x7632);
#pragma unroll
                for (int nt = 0; nt < 4; nt++) {
                    MMAH16816(acc[nt][0], acc[nt][1], acc[nt][2], acc[nt][3],
                              ah0, ah1, ah2, ah3, bhf[nt][kt][0], bhf[nt][kt][1]);
                    MMAH16816(acc[nt][0], acc[nt][1], acc[nt][2], acc[nt][3],
                              al0, al1, al2, al3, bhf[nt][kt][0], bhf[nt][kt][1]);
                }
            }

            const int dA = __ldg(ei + nE + e0 + fg);
            const int dB = __ldg(ei + nE + e0 + fg + 8);
#pragma unroll
            for (int nt = 0; nt < 4; nt++) {
                int ch = nbase + nt * 8 + 2 * ft;
                float2 xga = *(const float2*)(&xs[cur][(exs + fg) * XP + ch]);
                float2 xgb = *(const float2*)(&xs[cur][(exs + fg + 8) * XP + ch]);
                red_add_v2(agg + (size_t)dA * HH + ch, acc[nt][0] * xga.x, acc[nt][1] * xga.y);
                red_add_v2(agg + (size_t)dB * HH + ch, acc[nt][2] * xgb.x, acc[nt][3] * xgb.y);
            }
        }
    }
}

// ---------------- GraphNorm center ----------------
__global__ void norm_center(const float* __restrict__ hin, const int* __restrict__ batch,
                            const float* __restrict__ ms, float* __restrict__ hc_out) {
    int idx = blockIdx.x * blockDim.x + threadIdx.x;
    if (idx >= NN * 32) return;
    int n = idx >> 5, c4 = (idx & 31) << 2;
    int b = batch[n];
    float rcnt = 1.f / fmaxf(g_cnt[b], 1.f);
    float4 hv = *(const float4*)(hin + (size_t)n * HH + c4);
    float4 mv = *(const float4*)(&g_mean[b * HH + c4]);
    float4 msv = *(const float4*)(ms + c4);
    float4 hc;
    hc.x = hv.x - mv.x * rcnt * msv.x;
    hc.y = hv.y - mv.y * rcnt * msv.y;
    hc.z = hv.z - mv.z * rcnt * msv.z;
    hc.w = hv.w - mv.w * rcnt * msv.w;
    *(float4*)(hc_out + (size_t)n * HH + c4) = hc;
    float4 sq = make_float4(hc.x * hc.x, hc.y * hc.y, hc.z * hc.z, hc.w * hc.w);
    red_add_v4(&g_var[b * HH + c4], sq);
}

// ---------------- launch ----------------
extern "C" void kernel_launch(void* const* d_in, const int* in_sizes, int n_in,
                              void* d_out, int out_size)
{
    const float* x        = (const float*)d_in[0];
    const float* feature1 = (const float*)d_in[1];
    const float* feature2 = (const float*)d_in[2];
    const int*   ei       = (const int*)d_in[3];
    const int*   batch    = (const int*)d_in[4];
    const float* lin_W    = (const float*)d_in[5];
    const float* lin_b    = (const float*)d_in[6];
    const float* f1_W1    = (const float*)d_in[7];
    const float* f1_W2    = (const float*)d_in[8];
    const float* f2_W1    = (const float*)d_in[9];
    const float* f2_W2    = (const float*)d_in[10];
    const float* c1_rel_W = (const float*)d_in[11];
    const float* c1_rel_b = (const float*)d_in[12];
    const float* c1_rt_W  = (const float*)d_in[13];
    const float* c2_rel_W = (const float*)d_in[14];
    const float* c2_rel_b = (const float*)d_in[15];
    const float* c2_rt_W  = (const float*)d_in[16];
    const float* lin1_W   = (const float*)d_in[17];
    const float* lin1_b   = (const float*)d_in[18];
    const float* lin2_W   = (const float*)d_in[19];
    const float* lin2_b   = (const float*)d_in[20];
    const float* cat_W    = (const float*)d_in[21];
    const float* cat_b    = (const float*)d_in[22];
    const float* norm_w   = (const float*)d_in[23];
    const float* norm_b   = (const float*)d_in[24];
    const float* norm_ms  = (const float*)d_in[25];
    const float* lins_W   = (const float*)d_in[26];
    const float* lins_b   = (const float*)d_in[27];
    const float* final_W  = (const float*)d_in[28];
    const float* final_b  = (const float*)d_in[29];

    const int nN = in_sizes[0] / HH;
    const int nE = in_sizes[3] / 2;

    float *pxact, *pagg1, *pagg2, *pA, *pB, *pC;
    cudaGetSymbolAddress((void**)&pxact, g_xact);
    cudaGetSymbolAddress((void**)&pagg1, g_agg1);
    cudaGetSymbolAddress((void**)&pagg2, g_agg2);
    cudaGetSymbolAddress((void**)&pA, g_A);
    cudaGetSymbolAddress((void**)&pB, g_B);
    cudaGetSymbolAddress((void**)&pC, g_C);

    cudaFuncSetAttribute(gemm_p<false, true,  true,  false, 0>, cudaFuncAttributeMaxDynamicSharedMemorySize, GEMM_SMEM);
    cudaFuncSetAttribute(gemm_p<false, false, false, false, 0>, cudaFuncAttributeMaxDynamicSharedMemorySize, GEMM_SMEM);
    cudaFuncSetAttribute(gemm_p<true,  true,  false, false, 0>, cudaFuncAttributeMaxDynamicSharedMemorySize, GEMM_SMEM);
    cudaFuncSetAttribute(gemm_p<true,  true,  false, true,  0>, cudaFuncAttributeMaxDynamicSharedMemorySize, GEMM_SMEM);
    cudaFuncSetAttribute(gemm_p<false, true,  true,  true,  0>, cudaFuncAttributeMaxDynamicSharedMemorySize, GEMM_SMEM);
    cudaFuncSetAttribute(gemm_p<false, true,  true,  true,  1>, cudaFuncAttributeMaxDynamicSharedMemorySize, GEMM_SMEM);
    cudaFuncSetAttribute(gemm_p<false, true,  false, false, 2>, cudaFuncAttributeMaxDynamicSharedMemorySize, GEMM_SMEM);

    const int PG = 296;

    WPack wp;
    wp.w[0]  = { lin_W, HH };
    wp.w[1]  = { c1_rel_W, HH };
    wp.w[2]  = { c1_rt_W, HH };
    wp.w[3]  = { lin1_W, HH };
    wp.w[4]  = { c2_rel_W, HH };
    wp.w[5]  = { c2_rt_W, HH };
    wp.w[6]  = { lin2_W, HH };
    wp.w[7]  = { cat_W, 2 * HH };
    wp.w[8]  = { cat_W + HH, 2 * HH };
    wp.w[9]  = { lins_W + 0 * HH * HH, HH };
    wp.w[10] = { lins_W + 1 * HH * HH, HH };
    wp.w[11] = { lins_W + 2 * HH * HH, HH };
    wp.w[12] = { final_W, HH };

    zero_kernel<<<(NN * HH + 255) / 256, 256>>>();
    prep_weights<<<(13 * 16384 + 255) / 256, 256>>>(wp);

    edge_mlp1<<<592, 256>>>(feature1, feature2, f1_W1, f2_W1, nE);

    gemm_p<false, true, true, false, 0><<<PG, 256, GEMM_SMEM>>>(
        x, 0, lin_b, nullptr, pxact, nN, nullptr, nullptr, nullptr);

    edge_scatter<<<444, 256>>>(ei, f1_W2, f2_W2, pxact, pagg1, pagg2, nE);

    gemm_p<false, false, false, false, 0><<<PG, 256, GEMM_SMEM>>>(
        pagg1, 1, nullptr, nullptr, pA, nN, nullptr, nullptr, nullptr);
    gemm_p<true, true, false, false, 0><<<PG, 256, GEMM_SMEM>>>(
        pxact, 2, c1_rel_b, nullptr, pA, nN, nullptr, nullptr, nullptr);
    gemm_p<false, true, true, false, 0><<<PG, 256, GEMM_SMEM>>>(
        pA, 3, lin1_b, nullptr, pB, nN, nullptr, nullptr, nullptr);
    gemm_p<false, false, false, false, 0><<<PG, 256, GEMM_SMEM>>>(
        pagg2, 4, nullptr, nullptr, pA, nN, nullptr, nullptr, nullptr);
    gemm_p<true, true, false, false, 0><<<PG, 256, GEMM_SMEM>>>(
        pxact, 5, c2_rel_b, nullptr, pA, nN, nullptr, nullptr, nullptr);
    gemm_p<false, true, true, false, 0><<<PG, 256, GEMM_SMEM>>>(
        pA, 6, lin2_b, nullptr, pC, nN, nullptr, nullptr, nullptr);
    gemm_p<false, false, false, false, 0><<<PG, 256, GEMM_SMEM>>>(
        pB, 7, nullptr, nullptr, pA, nN, nullptr, nullptr, nullptr);
    gemm_p<true, true, false, true, 0><<<PG, 256, GEMM_SMEM>>>(
        pC, 8, cat_b, pxact, pA, nN, nullptr, nullptr, nullptr);
    gemm_p<false, true, true, true, 0><<<PG, 256, GEMM_SMEM>>>(
        pA, 9,  lins_b + 0 * HH, pA, pB, nN, nullptr, nullptr, nullptr);
    gemm_p<false, true, true, true, 0><<<PG, 256, GEMM_SMEM>>>(
        pB, 10, lins_b + 1 * HH, pB, pA, nN, nullptr, nullptr, nullptr);
    gemm_p<false, true, true, true, 1><<<PG, 256, GEMM_SMEM>>>(
        pA, 11, lins_b + 2 * HH, pA, pB, nN, batch, nullptr, nullptr);

    const int n32b = (NN * 32 + 255) / 256;
    norm_center<<<n32b, 256>>>(pB, batch, norm_ms, pC);

    gemm_p<false, true, false, false, 2><<<PG, 256, GEMM_SMEM>>>(
        pC, 12, final_b, nullptr, (float*)d_out, nN, batch, norm_w, norm_b);
}

// round 14
// speedup vs baseline: 1.9176x; 1.0289x over previous
#include <cuda_runtime.h>
#include <cuda_bf16.h>
#include <cuda_fp16.h>

#define NN 50000
#define EE 1000000
#define BB 512
#define HH 128
#define MID 64
#define IN1 54
#define IN2 18

typedef unsigned long long u64;
typedef unsigned int u32;

#define FMA2(d, a, b, c) asm("fma.rn.f32x2 %0, %1, %2, %3;" : "=l"(d) : "l"(a), "l"(b), "l"(c))

__device__ __forceinline__ u64 pack2(float lo, float hi) {
    u64 r; asm("mov.b64 %0, {%1, %2};" : "=l"(r) : "f"(lo), "f"(hi)); return r;
}
__device__ __forceinline__ void unpack2(u64 v, float& lo, float& hi) {
    asm("mov.b64 {%0, %1}, %2;" : "=f"(lo), "=f"(hi) : "l"(v));
}
__device__ __forceinline__ void red_add_v4(float* addr, float4 v) {
    asm volatile("red.global.add.v4.f32 [%0], {%1, %2, %3, %4};"
                 :: "l"(addr), "f"(v.x), "f"(v.y), "f"(v.z), "f"(v.w) : "memory");
}
__device__ __forceinline__ void red_add_v2(float* addr, float a, float b) {
    asm volatile("red.global.add.v2.f32 [%0], {%1, %2};"
                 :: "l"(addr), "f"(a), "f"(b) : "memory");
}
__device__ __forceinline__ void red_add_f(float* addr, float v) {
    asm volatile("red.global.add.f32 [%0], %1;" :: "l"(addr), "f"(v) : "memory");
}
// bf16 mma (node chain)
#define MMA16816(c0, c1, c2, c3, a0, a1, a2, a3, b0, b1) \
    asm volatile("mma.sync.aligned.m16n8k16.row.col.f32.bf16.bf16.f32 " \
                 "{%0,%1,%2,%3}, {%4,%5,%6,%7}, {%8,%9}, {%0,%1,%2,%3};" \
                 : "+f"(c0), "+f"(c1), "+f"(c2), "+f"(c3) \
                 : "r"(a0), "r"(a1), "r"(a2), "r"(a3), "r"(b0), "r"(b1))
// fp16 mma (edge path)
#define MMAH16816(c0, c1, c2, c3, a0, a1, a2, a3, b0, b1) \
    asm volatile("mma.sync.aligned.m16n8k16.row.col.f32.f16.f16.f32 " \
                 "{%0,%1,%2,%3}, {%4,%5,%6,%7}, {%8,%9}, {%0,%1,%2,%3};" \
                 : "+f"(c0), "+f"(c1), "+f"(c2), "+f"(c3) \
                 : "r"(a0), "r"(a1), "r"(a2), "r"(a3), "r"(b0), "r"(b1))

__device__ __forceinline__ u32 pack_bf2(float e0, float e1) {
    __nv_bfloat162 h = __floats2bfloat162_rn(e0, e1);
    return *(u32*)&h;
}
__device__ __forceinline__ u32 pack_h2(float e0, float e1) {
    __half2 h = __floats2half2_rn(e0, e1);
    return *(u32*)&h;
}

// ---------------- scratch ----------------
__device__ float g_xact[NN * HH];
__device__ float g_agg1[NN * HH];
__device__ float g_agg2[NN * HH];
__device__ float g_A[NN * HH];
__device__ float g_B[NN * HH];
__device__ float g_C[NN * HH];
__device__ float g_mean[BB * HH];
__device__ float g_var[BB * HH];
__device__ float g_cnt[BB];
__device__ __half g_m1h[EE * MID];   // single fp16 per element
__device__ __half g_m2h[EE * MID];
// preconverted node-GEMM weights: 13 matrices of 128x128, bf16 hi/lo planes (flat [c][k])
__device__ __nv_bfloat16 g_Wh[13 * 128 * 128];
__device__ __nv_bfloat16 g_Wl[13 * 128 * 128];

__global__ void zero_kernel() {
    int idx = blockIdx.x * blockDim.x + threadIdx.x;
    if (idx < NN * HH) { g_agg1[idx] = 0.f; g_agg2[idx] = 0.f; }
    if (idx < BB * HH) { g_mean[idx] = 0.f; g_var[idx] = 0.f; }
    if (idx < BB) g_cnt[idx] = 0.f;
}

// ---------------- weight prep: fp32 -> bf16 hi/lo planes ----------------
struct WSrc { const float* p; int ldw; };
struct WPack { WSrc w[13]; };

__global__ void prep_weights(WPack wp) {
    int idx = blockIdx.x * blockDim.x + threadIdx.x;
    if (idx >= 13 * 16384) return;
    int m = idx >> 14, r = idx & 16383, c = r >> 7, k = r & 127;
    float v = wp.w[m].p[(size_t)c * wp.w[m].ldw + k];
    __nv_bfloat16 h = __float2bfloat16_rn(v);
    g_Wh[idx] = h;
    g_Wl[idx] = __float2bfloat16_rn(v - __bfloat162float(h));
}

// ---------------- persistent node GEMM via split-bf16 HMMA (unchanged) ----------------
constexpr int GP = 136;
constexpr int GEMM_SMEM = (64 + 64 + 128 + 128) * GP * 2;

template <bool ACCUM, bool EPI, bool SWISH, bool RESID, int FUSE>
__global__ __launch_bounds__(256, 2) void gemm_p(
    const float* __restrict__ A, int widx,
    const float* __restrict__ bias, const float* __restrict__ resid,
    float* __restrict__ out, int nrows,
    const int* __restrict__ batch, const float* __restrict__ nw, const float* __restrict__ nb)
{
    extern __shared__ char smc[];
    __nv_bfloat16* Ahi = (__nv_bfloat16*)(smc);
    __nv_bfloat16* Alo = (__nv_bfloat16*)(smc + 64 * GP * 2);
    __nv_bfloat16* Whi = (__nv_bfloat16*)(smc + 128 * GP * 2);
    __nv_bfloat16* Wlo = (__nv_bfloat16*)(smc + 256 * GP * 2);

    const int tid  = threadIdx.x;
    const int warp = tid >> 5;
    const int lane = tid & 31;
    const int fg   = lane >> 2;
    const int ft   = lane & 3;
    const int rg   = warp & 3;
    const int chf  = warp >> 2;

    {
        const u32* srcH = (const u32*)(g_Wh + (size_t)widx * 16384);
        const u32* srcL = (const u32*)(g_Wl + (size_t)widx * 16384);
        for (int i = tid; i < 128 * 64; i += 256) {
            int c = i >> 6, kp = i & 63;
            ((u32*)Whi)[c * 68 + kp] = srcH[i];
            ((u32*)Wlo)[c * 68 + kp] = srcL[i];
        }
    }

    const int ntiles = (nrows + 63) >> 6;

    float4 pre[8];
    auto ldA = [&](int tt) {
#pragma unroll
        for (int j = 0; j < 8; j++) {
            int idx = tid + 256 * j;
            int r = idx >> 5, kp4 = idx & 31;
            int gr = (tt << 6) + r;
            float4 v = (gr < nrows) ? *(const float4*)(A + (size_t)gr * 128 + 4 * kp4)
                                    : make_float4(0.f, 0.f, 0.f, 0.f);
            if (FUSE == 2) {
                if (gr < nrows) {
                    int b = __ldg(batch + gr);
                    float rcnt = 1.f / fmaxf(g_cnt[b], 1.f);
                    float4 vv = *(const float4*)(&g_var[b * HH + 4 * kp4]);
                    float4 w4 = *(const float4*)(nw + 4 * kp4);
                    float4 b4 = *(const float4*)(nb + 4 * kp4);
                    v.x = w4.x * v.x * rsqrtf(vv.x * rcnt + 1e-5f) + b4.x;
                    v.y = w4.y * v.y * rsqrtf(vv.y * rcnt + 1e-5f) + b4.y;
                    v.z = w4.z * v.z * rsqrtf(vv.z * rcnt + 1e-5f) + b4.z;
                    v.w = w4.w * v.w * rsqrtf(vv.w * rcnt + 1e-5f) + b4.w;
                }
            }
            pre[j] = v;
        }
    };

    int t = blockIdx.x;
    if (t < ntiles) ldA(t);

    for (; t < ntiles; t += gridDim.x) {
        const int r0 = t << 6;
        __syncthreads();

#pragma unroll
        for (int j = 0; j < 8; j++) {
            int idx = tid + 256 * j;
            int r = idx >> 5, kp4 = idx & 31;
            float4 v = pre[j];
            __nv_bfloat162 h01 = __floats2bfloat162_rn(v.x, v.y);
            __nv_bfloat162 h23 = __floats2bfloat162_rn(v.z, v.w);
            __nv_bfloat162 l01 = __floats2bfloat162_rn(v.x - __bfloat162float(h01.x),
                                                       v.y - __bfloat162float(h01.y));
            __nv_bfloat162 l23 = __floats2bfloat162_rn(v.z - __bfloat162float(h23.x),
                                                       v.w - __bfloat162float(h23.y));
            ((u64*)(Ahi + r * GP))[kp4] = (u64)(*(u32*)&h01) | ((u64)(*(u32*)&h23) << 32);
            ((u64*)(Alo + r * GP))[kp4] = (u64)(*(u32*)&l01) | ((u64)(*(u32*)&l23) << 32);
        }
        __syncthreads();

        const int tn = t + gridDim.x;
        if (tn < ntiles) ldA(tn);

        float acc[8][4];
#pragma unroll
        for (int nt = 0; nt < 8; nt++)
#pragma unroll
            for (int q = 0; q < 4; q++) acc[nt][q] = 0.f;

        const int m0 = rg * 16 + fg;
#pragma unroll
        for (int kstep = 0; kstep < 8; kstep++) {
            const int k0 = kstep * 16 + 2 * ft;
            u32 ah0 = *(const u32*)(Ahi + m0 * GP + k0);
            u32 ah1 = *(const u32*)(Ahi + (m0 + 8) * GP + k0);
            u32 ah2 = *(const u32*)(Ahi + m0 * GP + k0 + 8);
            u32 ah3 = *(const u32*)(Ahi + (m0 + 8) * GP + k0 + 8);
            u32 al0 = *(const u32*)(Alo + m0 * GP + k0);
            u32 al1 = *(const u32*)(Alo + (m0 + 8) * GP + k0);
            u32 al2 = *(const u32*)(Alo + m0 * GP + k0 + 8);
            u32 al3 = *(const u32*)(Alo + (m0 + 8) * GP + k0 + 8);
#pragma unroll
            for (int nt = 0; nt < 8; nt++) {
                const int c = chf * 64 + nt * 8 + fg;
                u32 bh0 = *(const u32*)(Whi + c * GP + k0);
                u32 bh1 = *(const u32*)(Whi + c * GP + k0 + 8);
                u32 bl0 = *(const u32*)(Wlo + c * GP + k0);
                u32 bl1 = *(const u32*)(Wlo + c * GP + k0 + 8);
                MMA16816(acc[nt][0], acc[nt][1], acc[nt][2], acc[nt][3],
                         ah0, ah1, ah2, ah3, bh0, bh1);
                MMA16816(acc[nt][0], acc[nt][1], acc[nt][2], acc[nt][3],
                         al0, al1, al2, al3, bh0, bh1);
                MMA16816(acc[nt][0], acc[nt][1], acc[nt][2], acc[nt][3],
                         ah0, ah1, ah2, ah3, bl0, bl1);
            }
        }

        const int rA = r0 + m0, rBr = r0 + m0 + 8;
        int bA = 0, bB = 0;
        if (FUSE == 1) {
            if (rA < nrows)  bA = __ldg(batch + rA);
            if (rBr < nrows) bB = __ldg(batch + rBr);
        }
#pragma unroll
        for (int nt = 0; nt < 8; nt++) {
            const int c = chf * 64 + nt * 8 + 2 * ft;
            float v0 = acc[nt][0], v1 = acc[nt][1];
            float v2 = acc[nt][2], v3 = acc[nt][3];
            if (EPI) {
                float2 bv = *(const float2*)(bias + c);
                v0 += bv.x; v1 += bv.y; v2 += bv.x; v3 += bv.y;
            }
            if (rA < nrows) {
                float* orow = out + (size_t)rA * 128 + c;
                if (ACCUM) { float2 pv = *(const float2*)orow; v0 += pv.x; v1 += pv.y; }
                if (SWISH) {
                    v0 = v0 / (1.f + __expf(-v0));
                    v1 = v1 / (1.f + __expf(-v1));
                }
                if (RESID) {
                    float2 rv = *(const float2*)(resid + (size_t)rA * 128 + c);
                    v0 += rv.x; v1 += rv.y;
                }
                *(float2*)orow = make_float2(v0, v1);
                if (FUSE == 1) red_add_v2(&g_mean[bA * HH + c], v0, v1);
            }
            if (rBr < nrows) {
                float* orow = out + (size_t)rBr * 128 + c;
                if (ACCUM) { float2 pv = *(const float2*)orow; v2 += pv.x; v3 += pv.y; }
                if (SWISH) {
                    v2 = v2 / (1.f + __expf(-v2));
                    v3 = v3 / (1.f + __expf(-v3));
                }
                if (RESID) {
                    float2 rv = *(const float2*)(resid + (size_t)rBr * 128 + c);
                    v2 += rv.x; v3 += rv.y;
                }
                *(float2*)orow = make_float2(v2, v3);
                if (FUSE == 1) red_add_v2(&g_mean[bB * HH + c], v2, v3);
            }
        }
        if (FUSE == 1 && chf == 0 && ft == 0) {
            if (rA < nrows)  red_add_f(&g_cnt[bA], 1.f);
            if (rBr < nrows) red_add_f(&g_cnt[bB], 1.f);
        }
    }
}

// ---------------- edge stage 1: m stored as single fp16 ----------------
constexpr int EB = 16;

__global__ __launch_bounds__(256) void edge_mlp1(
    const float* __restrict__ feat1, const float* __restrict__ feat2,
    const float* __restrict__ W1a, const float* __restrict__ W1b, int nE)
{
    __shared__ __align__(16) float f1s[EB * IN1];
    __shared__ __align__(16) float f2s[EB * IN2];
    __shared__ __align__(16) float Ws1a[MID * IN1];
    __shared__ __align__(16) float Ws1b[MID * IN2];

    const int tid = threadIdx.x;
    for (int i = tid; i < MID * IN1; i += 256) Ws1a[i] = W1a[i];
    for (int i = tid; i < MID * IN2; i += 256) Ws1b[i] = W1b[i];
    __syncthreads();

    const int ntiles = nE / EB;
    const int k = tid & 63, g = tid >> 6;

    for (int t = blockIdx.x; t < ntiles; t += gridDim.x) {
        const int e0 = t * EB;
        for (int i = tid; i < EB * IN1; i += 256) f1s[i] = feat1[(size_t)e0 * IN1 + i];
        for (int i = tid; i < EB * IN2; i += 256) f2s[i] = feat2[(size_t)e0 * IN2 + i];
        __syncthreads();

        {
            const u64* wrow = (const u64*)(Ws1a + k * IN1);
            const u64* fr0 = (const u64*)(f1s + (g + 0)  * IN1);
            const u64* fr1 = (const u64*)(f1s + (g + 4)  * IN1);
            const u64* fr2 = (const u64*)(f1s + (g + 8)  * IN1);
            const u64* fr3 = (const u64*)(f1s + (g + 12) * IN1);
            u64 a0 = 0ull, a1 = 0ull, a2 = 0ull, a3 = 0ull;
#pragma unroll
            for (int jp = 0; jp < IN1 / 2; jp++) {
                u64 w = wrow[jp];
                FMA2(a0, fr0[jp], w, a0);
                FMA2(a1, fr1[jp], w, a1);
                FMA2(a2, fr2[jp], w, a2);
                FMA2(a3, fr3[jp], w, a3);
            }
            float lo, hi;
#pragma unroll
            for (int q = 0; q < 4; q++) {
                u64 a = (q == 0) ? a0 : (q == 1) ? a1 : (q == 2) ? a2 : a3;
                unpack2(a, lo, hi);
                g_m1h[(size_t)(e0 + g + 4 * q) * MID + k] = __float2half_rn(lo + hi);
            }
        }
        {
            const u64* wrow = (const u64*)(Ws1b + k * IN2);
            const u64* fr0 = (const u64*)(f2s + (g + 0)  * IN2);
            const u64* fr1 = (const u64*)(f2s + (g + 4)  * IN2);
            const u64* fr2 = (const u64*)(f2s + (g + 8)  * IN2);
            const u64* fr3 = (const u64*)(f2s + (g + 12) * IN2);
            u64 a0 = 0ull, a1 = 0ull, a2 = 0ull, a3 = 0ull;
#pragma unroll
            for (int jp = 0; jp < IN2 / 2; jp++) {
                u64 w = wrow[jp];
                FMA2(a0, fr0[jp], w, a0);
                FMA2(a1, fr1[jp], w, a1);
                FMA2(a2, fr2[jp], w, a2);
                FMA2(a3, fr3[jp], w, a3);
            }
            float lo, hi;
#pragma unroll
            for (int q = 0; q < 4; q++) {
                u64 a = (q == 0) ? a0 : (q == 1) ? a1 : (q == 2) ? a2 : a3;
                unpack2(a, lo, hi);
                g_m2h[(size_t)(e0 + g + 4 * q) * MID + k] = __float2half_rn(lo + hi);
            }
        }
        __syncthreads();
    }
}

// ---------------- edge stage 2: fp16 1-term HMMA ----------------
constexpr int XP = 132;
constexpr int EB2 = 32;

__global__ __launch_bounds__(256, 3) void edge_scatter(
    const int* __restrict__ ei,
    const float* __restrict__ W2a, const float* __restrict__ W2b,
    const float* __restrict__ xact,
    float* __restrict__ agg1, float* __restrict__ agg2, int nE)
{
    __shared__ __align__(16) float xs[2][EB2 * XP];

    const int tid  = threadIdx.x;
    const int warp = tid >> 5;
    const int lane = tid & 31;
    const int fg   = lane >> 2;
    const int ft   = lane & 3;

    // preload W2 B-fragments (single fp16)
    u32 bhf[4][4][2];
    {
        const float* W2 = (warp < 4) ? W2a : W2b;
        const int nbase = (warp & 3) * 32;
#pragma unroll
        for (int nt = 0; nt < 4; nt++) {
            const float* wrow = W2 + (size_t)(nbase + nt * 8 + fg) * MID;
#pragma unroll
            for (int kt = 0; kt < 4; kt++) {
#pragma unroll
                for (int half = 0; half < 2; half++) {
                    int k0 = kt * 16 + half * 8 + 2 * ft;
                    bhf[nt][kt][half] = pack_h2(wrow[k0], wrow[k0 + 1]);
                }
            }
        }
    }

    const int ntiles = nE / EB2;

    auto do_gather = [&](int buf, int tt) {
        const int e0n = tt * EB2;
#pragma unroll
        for (int j = 0; j < 4; j++) {
            int idx = tid + 256 * j;
            int e = idx >> 5, h4 = (idx & 31) << 2;
            int src = __ldg(ei + e0n + e);
            float4 v = *(const float4*)(xact + (size_t)src * HH + h4);
            *(float4*)(&xs[buf][e * XP + h4]) = v;
        }
    };

    int t = blockIdx.x;
    if (t < ntiles) do_gather(0, t);

    int it = 0;
    for (; t < ntiles; t += gridDim.x, it ^= 1) {
        const int cur = it, nxt = it ^ 1;
        const int tn = t + gridDim.x;
        __syncthreads();
        if (tn < ntiles) do_gather(nxt, tn);

        const __half* mpl = (warp < 4) ? g_m1h : g_m2h;
        float* agg = (warp < 4) ? agg1 : agg2;
        const int nbase = (warp & 3) * 32;

#pragma unroll
        for (int sb = 0; sb < 2; sb++) {
            const int e0 = t * EB2 + sb * 16;
            const int exs = sb * 16;

            float acc[4][4];
#pragma unroll
            for (int nt = 0; nt < 4; nt++)
#pragma unroll
                for (int q = 0; q < 4; q++) acc[nt][q] = 0.f;

            const u32* rowA = (const u32*)(mpl + (size_t)(e0 + fg) * MID);
            const u32* rowB = (const u32*)(mpl + (size_t)(e0 + fg + 8) * MID);
#pragma unroll
            for (int kt = 0; kt < 4; kt++) {
                // fp16 pairs are adjacent in memory: u32 index = k0/2 = kt*8 + ft
                u32 a0 = rowA[kt * 8 + ft];
                u32 a1 = rowB[kt * 8 + ft];
                u32 a2 = rowA[kt * 8 + ft + 4];
                u32 a3 = rowB[kt * 8 + ft + 4];
#pragma unroll
                for (int nt = 0; nt < 4; nt++) {
                    MMAH16816(acc[nt][0], acc[nt][1], acc[nt][2], acc[nt][3],
                              a0, a1, a2, a3, bhf[nt][kt][0], bhf[nt][kt][1]);
                }
            }

            const int dA = __ldg(ei + nE + e0 + fg);
            const int dB = __ldg(ei + nE + e0 + fg + 8);
#pragma unroll
            for (int nt = 0; nt < 4; nt++) {
                int ch = nbase + nt * 8 + 2 * ft;
                float2 xga = *(const float2*)(&xs[cur][(exs + fg) * XP + ch]);
                float2 xgb = *(const float2*)(&xs[cur][(exs + fg + 8) * XP + ch]);
                red_add_v2(agg + (size_t)dA * HH + ch, acc[nt][0] * xga.x, acc[nt][1] * xga.y);
                red_add_v2(agg + (size_t)dB * HH + ch, acc[nt][2] * xgb.x, acc[nt][3] * xgb.y);
            }
        }
    }
}

// ---------------- GraphNorm center ----------------
__global__ void norm_center(const float* __restrict__ hin, const int* __restrict__ batch,
                            const float* __restrict__ ms, float* __restrict__ hc_out) {
    int idx = blockIdx.x * blockDim.x + threadIdx.x;
    if (idx >= NN * 32) return;
    int n = idx >> 5, c4 = (idx & 31) << 2;
    int b = batch[n];
    float rcnt = 1.f / fmaxf(g_cnt[b], 1.f);
    float4 hv = *(const float4*)(hin + (size_t)n * HH + c4);
    float4 mv = *(const float4*)(&g_mean[b * HH + c4]);
    float4 msv = *(const float4*)(ms + c4);
    float4 hc;
    hc.x = hv.x - mv.x * rcnt * msv.x;
    hc.y = hv.y - mv.y * rcnt * msv.y;
    hc.z = hv.z - mv.z * rcnt * msv.z;
    hc.w = hv.w - mv.w * rcnt * msv.w;
    *(float4*)(hc_out + (size_t)n * HH + c4) = hc;
    float4 sq = make_float4(hc.x * hc.x, hc.y * hc.y, hc.z * hc.z, hc.w * hc.w);
    red_add_v4(&g_var[b * HH + c4], sq);
}

// ---------------- launch ----------------
extern "C" void kernel_launch(void* const* d_in, const int* in_sizes, int n_in,
                              void* d_out, int out_size)
{
    const float* x        = (const float*)d_in[0];
    const float* feature1 = (const float*)d_in[1];
    const float* feature2 = (const float*)d_in[2];
    const int*   ei       = (const int*)d_in[3];
    const int*   batch    = (const int*)d_in[4];
    const float* lin_W    = (const float*)d_in[5];
    const float* lin_b    = (const float*)d_in[6];
    const float* f1_W1    = (const float*)d_in[7];
    const float* f1_W2    = (const float*)d_in[8];
    const float* f2_W1    = (const float*)d_in[9];
    const float* f2_W2    = (const float*)d_in[10];
    const float* c1_rel_W = (const float*)d_in[11];
    const float* c1_rel_b = (const float*)d_in[12];
    const float* c1_rt_W  = (const float*)d_in[13];
    const float* c2_rel_W = (const float*)d_in[14];
    const float* c2_rel_b = (const float*)d_in[15];
    const float* c2_rt_W  = (const float*)d_in[16];
    const float* lin1_W   = (const float*)d_in[17];
    const float* lin1_b   = (const float*)d_in[18];
    const float* lin2_W   = (const float*)d_in[19];
    const float* lin2_b   = (const float*)d_in[20];
    const float* cat_W    = (const float*)d_in[21];
    const float* cat_b    = (const float*)d_in[22];
    const float* norm_w   = (const float*)d_in[23];
    const float* norm_b   = (const float*)d_in[24];
    const float* norm_ms  = (const float*)d_in[25];
    const float* lins_W   = (const float*)d_in[26];
    const float* lins_b   = (const float*)d_in[27];
    const float* final_W  = (const float*)d_in[28];
    const float* final_b  = (const float*)d_in[29];

    const int nN = in_sizes[0] / HH;
    const int nE = in_sizes[3] / 2;

    float *pxact, *pagg1, *pagg2, *pA, *pB, *pC;
    cudaGetSymbolAddress((void**)&pxact, g_xact);
    cudaGetSymbolAddress((void**)&pagg1, g_agg1);
    cudaGetSymbolAddress((void**)&pagg2, g_agg2);
    cudaGetSymbolAddress((void**)&pA, g_A);
    cudaGetSymbolAddress((void**)&pB, g_B);
    cudaGetSymbolAddress((void**)&pC, g_C);

    cudaFuncSetAttribute(gemm_p<false, true,  true,  false, 0>, cudaFuncAttributeMaxDynamicSharedMemorySize, GEMM_SMEM);
    cudaFuncSetAttribute(gemm_p<false, false, false, false, 0>, cudaFuncAttributeMaxDynamicSharedMemorySize, GEMM_SMEM);
    cudaFuncSetAttribute(gemm_p<true,  true,  false, false, 0>, cudaFuncAttributeMaxDynamicSharedMemorySize, GEMM_SMEM);
    cudaFuncSetAttribute(gemm_p<true,  true,  false, true,  0>, cudaFuncAttributeMaxDynamicSharedMemorySize, GEMM_SMEM);
    cudaFuncSetAttribute(gemm_p<false, true,  true,  true,  0>, cudaFuncAttributeMaxDynamicSharedMemorySize, GEMM_SMEM);
    cudaFuncSetAttribute(gemm_p<false, true,  true,  true,  1>, cudaFuncAttributeMaxDynamicSharedMemorySize, GEMM_SMEM);
    cudaFuncSetAttribute(gemm_p<false, true,  false, false, 2>, cudaFuncAttributeMaxDynamicSharedMemorySize, GEMM_SMEM);

    const int PG = 296;

    WPack wp;
    wp.w[0]  = { lin_W, HH };
    wp.w[1]  = { c1_rel_W, HH };
    wp.w[2]  = { c1_rt_W, HH };
    wp.w[3]  = { lin1_W, HH };
    wp.w[4]  = { c2_rel_W, HH };
    wp.w[5]  = { c2_rt_W, HH };
    wp.w[6]  = { lin2_W, HH };
    wp.w[7]  = { cat_W, 2 * HH };
    wp.w[8]  = { cat_W + HH, 2 * HH };
    wp.w[9]  = { lins_W + 0 * HH * HH, HH };
    wp.w[10] = { lins_W + 1 * HH * HH, HH };
    wp.w[11] = { lins_W + 2 * HH * HH, HH };
    wp.w[12] = { final_W, HH };

    zero_kernel<<<(NN * HH + 255) / 256, 256>>>();
    prep_weights<<<(13 * 16384 + 255) / 256, 256>>>(wp);

    edge_mlp1<<<592, 256>>>(feature1, feature2, f1_W1, f2_W1, nE);

    gemm_p<false, true, true, false, 0><<<PG, 256, GEMM_SMEM>>>(
        x, 0, lin_b, nullptr, pxact, nN, nullptr, nullptr, nullptr);

    edge_scatter<<<444, 256>>>(ei, f1_W2, f2_W2, pxact, pagg1, pagg2, nE);

    gemm_p<false, false, false, false, 0><<<PG, 256, GEMM_SMEM>>>(
        pagg1, 1, nullptr, nullptr, pA, nN, nullptr, nullptr, nullptr);
    gemm_p<true, true, false, false, 0><<<PG, 256, GEMM_SMEM>>>(
        pxact, 2, c1_rel_b, nullptr, pA, nN, nullptr, nullptr, nullptr);
    gemm_p<false, true, true, false, 0><<<PG, 256, GEMM_SMEM>>>(
        pA, 3, lin1_b, nullptr, pB, nN, nullptr, nullptr, nullptr);
    gemm_p<false, false, false, false, 0><<<PG, 256, GEMM_SMEM>>>(
        pagg2, 4, nullptr, nullptr, pA, nN, nullptr, nullptr, nullptr);
    gemm_p<true, true, false, false, 0><<<PG, 256, GEMM_SMEM>>>(
        pxact, 5, c2_rel_b, nullptr, pA, nN, nullptr, nullptr, nullptr);
    gemm_p<false, true, true, false, 0><<<PG, 256, GEMM_SMEM>>>(
        pA, 6, lin2_b, nullptr, pC, nN, nullptr, nullptr, nullptr);
    gemm_p<false, false, false, false, 0><<<PG, 256, GEMM_SMEM>>>(
        pB, 7, nullptr, nullptr, pA, nN, nullptr, nullptr, nullptr);
    gemm_p<true, true, false, true, 0><<<PG, 256, GEMM_SMEM>>>(
        pC, 8, cat_b, pxact, pA, nN, nullptr, nullptr, nullptr);
    gemm_p<false, true, true, true, 0><<<PG, 256, GEMM_SMEM>>>(
        pA, 9,  lins_b + 0 * HH, pA, pB, nN, nullptr, nullptr, nullptr);
    gemm_p<false, true, true, true, 0><<<PG, 256, GEMM_SMEM>>>(
        pB, 10, lins_b + 1 * HH, pB, pA, nN, nullptr, nullptr, nullptr);
    gemm_p<false, true, true, true, 1><<<PG, 256, GEMM_SMEM>>>(
        pA, 11, lins_b + 2 * HH, pA, pB, nN, batch, nullptr, nullptr);

    const int n32b = (NN * 32 + 255) / 256;
    norm_center<<<n32b, 256>>>(pB, batch, norm_ms, pC);

    gemm_p<false, true, false, false, 2><<<PG, 256, GEMM_SMEM>>>(
        pC, 12, final_b, nullptr, (float*)d_out, nN, batch, norm_w, norm_b);
}